// round 11
// baseline (speedup 1.0000x reference)
#include <cuda_runtime.h>
#include <cuda_bf16.h>
#include <math.h>
#include <stdint.h>

#define Bb 2
#define Tt 16
#define Hh 56
#define Ww 56
#define Cc 128
#define NPTS (Bb*Tt*Hh*Ww)          /* 100352 */
#define TOT  (NPTS*Cc)              /* 12845056 */
#define HWC  (Hh*Ww*Cc)
#define KTAPS 245
#define NTILES (NPTS/128)           /* 784 */

typedef __nv_bfloat16 bf16;
typedef __nv_bfloat162 bf162;

// ---------------- device scratch (allocation-free) ----------------
__device__ __align__(16) bf16 g_gateP[TOT];
__device__ __align__(16) bf16 g_hidP[TOT];
__device__ __align__(16) bf16 g_gateS[TOT];
__device__ __align__(16) bf16 g_hidS[TOT];
__device__ __align__(16) bf16 g_E[TOT];
__device__ __align__(16) bf16 g_WgT[Cc*Cc];       // [n][k]
__device__ __align__(16) bf16 g_WhT[Cc*Cc];
__device__ __align__(16) bf16 g_WoT[Cc*Cc];
__device__ __align__(16) bf16 g_W1T[512*Cc];      // [n=512][k=128]
__device__ __align__(16) bf16 g_W2T[Cc*512];      // [n=128][k=512]
__device__ __align__(16) bf16 g_kB[2][KTAPS*Cc];  // [tap][c]

// ---------------- helpers ----------------
__device__ __forceinline__ uint32_t smem_u32(const void* p) {
    uint32_t a;
    asm("{ .reg .u64 t; cvta.to.shared.u64 t, %1; cvt.u32.u64 %0, t; }" : "=r"(a) : "l"(p));
    return a;
}
#define LDSM4(r0, r1, r2, r3, a) \
    asm volatile("ldmatrix.sync.aligned.m8n8.x4.shared.b16 {%0,%1,%2,%3}, [%4];" \
        : "=r"(r0), "=r"(r1), "=r"(r2), "=r"(r3) : "r"(a))
#define MMA16816(c, a, b) \
    asm volatile("mma.sync.aligned.m16n8k16.row.col.f32.bf16.bf16.f32 " \
        "{%0,%1,%2,%3},{%4,%5,%6,%7},{%8,%9},{%0,%1,%2,%3};" \
        : "+f"((c)[0]), "+f"((c)[1]), "+f"((c)[2]), "+f"((c)[3]) \
        : "r"((a)[0]), "r"((a)[1]), "r"((a)[2]), "r"((a)[3]), "r"((b)[0]), "r"((b)[1]))

__device__ __forceinline__ float tanh_fast(float x) {
    float y;
    asm("tanh.approx.f32 %0, %1;" : "=f"(y) : "f"(x));
    return y;
}
__device__ __forceinline__ float exp_fast(float x) {
    float y;
    asm("ex2.approx.f32 %0, %1;" : "=f"(y) : "f"(x * 1.4426950408889634f));
    return y;
}
__device__ __forceinline__ float rcp_fast(float x) {
    float y;
    asm("rcp.approx.f32 %0, %1;" : "=f"(y) : "f"(x));
    return y;
}

#define SA 136    /* smem row stride (bf16 elems) for 128-col tiles */

// ---------------------------------------------------------------------------
// K0: weight prep
// ---------------------------------------------------------------------------
__global__ void k_prep(const float* __restrict__ Wg, const float* __restrict__ Wh,
                       const float* __restrict__ Wo, const float* __restrict__ W1,
                       const float* __restrict__ W2, const float* __restrict__ gk,
                       const float* __restrict__ hk) {
    int i = blockIdx.x * 256 + threadIdx.x;
    if (i < 16384) {
        int n = i >> 7, k = i & 127;
        g_WgT[i] = __float2bfloat16(Wg[k * 128 + n]);
        g_WhT[i] = __float2bfloat16(Wh[k * 128 + n]);
        g_WoT[i] = __float2bfloat16(Wo[k * 128 + n]);
    }
    if (i < 65536) {
        int n = i >> 7, k = i & 127;
        g_W1T[i] = __float2bfloat16(W1[k * 512 + n]);
        int n2 = i >> 9, k2 = i & 511;
        g_W2T[i] = __float2bfloat16(W2[k2 * 128 + n2]);
    }
    if (i < 2 * KTAPS * 128) {
        int which = i / (KTAPS * 128);
        int j = i - which * (KTAPS * 128);
        int tap = j >> 7, c = j & 127;
        const float* s = which ? hk : gk;
        g_kB[which][j] = __float2bfloat16(s[c * KTAPS + tap]);
    }
}

// ---------------------------------------------------------------------------
// K1: dual projection, 256 threads (8 warps: which x wn(4), 32 cols each)
// ---------------------------------------------------------------------------
#define PROJ_SMEM (3*128*SA*2 + 256*4)
__global__ void __launch_bounds__(256) k_proj(const float* __restrict__ x,
                                              const float* __restrict__ bg,
                                              const float* __restrict__ bh) {
    extern __shared__ __align__(16) char sm[];
    bf16* As = (bf16*)sm;
    bf16* Bs = As + 128 * SA;
    float* sbias = (float*)(Bs + 2 * 128 * SA);
    int tid = threadIdx.x, w = tid >> 5, l = tid & 31;
    size_t m0 = (size_t)blockIdx.x * 128;
    if (tid < 128) sbias[tid] = bg[tid];
    else           sbias[tid] = bh[tid - 128];

    const float2* xs = (const float2*)(x + m0 * 128);
    for (int idx = tid; idx < 128 * 64; idx += 256) {
        int r = idx >> 6, cp = idx & 63;
        float2 v = xs[idx];
        *(bf162*)(As + r * SA + cp * 2) = __floats2bfloat162_rn(v.x, v.y);
    }
    const uint4* wgp = (const uint4*)g_WgT;
    const uint4* whp = (const uint4*)g_WhT;
    for (int idx = tid; idx < 128 * 16; idx += 256) {
        int r = idx >> 4, c = idx & 15;
        *(uint4*)(Bs + r * SA + c * 8) = wgp[idx];
        *(uint4*)(Bs + 128 * SA + r * SA + c * 8) = whp[idx];
    }
    __syncthreads();

    int which = w >> 2;
    int wn0 = (w & 3) * 32;
    uint32_t Abase = smem_u32(As) + ((l & 15) * SA + (l >> 4) * 8) * 2;
    uint32_t Bbase = smem_u32(Bs + which * 128 * SA) + ((l & 15) * SA + (l >> 4) * 8) * 2 + wn0 * SA * 2;
    bf16* outb = which ? g_hidP : g_gateP;
    float* bb = sbias + which * 128;
    int quad = l >> 2, t4 = l & 3;

    for (int mc = 0; mc < 4; mc++) {
        float acc[2][4][4];
        #pragma unroll
        for (int mf = 0; mf < 2; mf++)
            #pragma unroll
            for (int nf = 0; nf < 4; nf++)
                #pragma unroll
                for (int e = 0; e < 4; e++) acc[mf][nf][e] = 0.f;
        #pragma unroll
        for (int k = 0; k < 8; k++) {
            uint32_t a[2][4], b[4][2];
            #pragma unroll
            for (int mf = 0; mf < 2; mf++)
                LDSM4(a[mf][0], a[mf][1], a[mf][2], a[mf][3],
                      Abase + (mc * 32 + mf * 16) * SA * 2 + k * 32);
            #pragma unroll
            for (int nf2 = 0; nf2 < 2; nf2++) {
                uint32_t r0, r1, r2, r3;
                LDSM4(r0, r1, r2, r3, Bbase + nf2 * 16 * SA * 2 + k * 32);
                b[nf2 * 2][0] = r0; b[nf2 * 2][1] = r2;
                b[nf2 * 2 + 1][0] = r1; b[nf2 * 2 + 1][1] = r3;
            }
            #pragma unroll
            for (int mf = 0; mf < 2; mf++)
                #pragma unroll
                for (int nf = 0; nf < 4; nf++) MMA16816(acc[mf][nf], a[mf], b[nf]);
        }
        #pragma unroll
        for (int mf = 0; mf < 2; mf++)
            #pragma unroll
            for (int nf = 0; nf < 4; nf++) {
                int n = wn0 + nf * 8 + t4 * 2;
                int r0 = mc * 32 + mf * 16 + quad;
                *(bf162*)(outb + (m0 + r0) * 128 + n) =
                    __floats2bfloat162_rn(acc[mf][nf][0] + bb[n], acc[mf][nf][1] + bb[n + 1]);
                *(bf162*)(outb + (m0 + r0 + 8) * 128 + n) =
                    __floats2bfloat162_rn(acc[mf][nf][2] + bb[n], acc[mf][nf][3] + bb[n + 1]);
            }
    }
}

// ---------------------------------------------------------------------------
// K2: depthwise circular conv 5x7x7 with t-reuse (round-8 version)
// ---------------------------------------------------------------------------
__global__ void __launch_bounds__(256) k_conv(void) {
    int ct = threadIdx.x & 63;
    int tq = threadIdx.x >> 6;
    int which = blockIdx.z;
    const uint32_t* __restrict__ in = (const uint32_t*)(which ? g_hidP : g_gateP);
    uint32_t* __restrict__ outp = (uint32_t*)(which ? g_hidS : g_gateS);
    const uint32_t* __restrict__ kt = (const uint32_t*)g_kB[which];
    int w0 = blockIdx.x * 14;
    int by = blockIdx.y;
    int h = by % Hh;
    int b = by / Hh;
    int t0 = tq * 4;

    int offs[20];
    #pragma unroll
    for (int j = 0; j < 20; j++) {
        int wi = w0 - 3 + j;
        if (wi < 0)   wi += 56;
        if (wi >= 56) wi -= 56;
        offs[j] = wi * 64;
    }

    bf162 acc[4][14];
    bf162 z = __floats2bfloat162_rn(0.f, 0.f);
    #pragma unroll
    for (int tr = 0; tr < 4; tr++)
        #pragma unroll
        for (int i = 0; i < 14; i++) acc[tr][i] = z;

    for (int kh = 0; kh < 7; kh++) {
        int hin = h - kh + 3;
        if (hin < 0)   hin += 56;
        if (hin >= 56) hin -= 56;
        uint32_t kv[5][7];
        #pragma unroll
        for (int ktp = 0; ktp < 5; ktp++)
            #pragma unroll
            for (int kw = 0; kw < 7; kw++)
                kv[ktp][kw] = kt[(size_t)(ktp * 49 + kh * 7 + kw) * 64 + ct];

        #pragma unroll
        for (int j = 0; j < 8; j++) {
            int t_in = (t0 - 2 + j) & 15;
            const uint32_t* src = in + (size_t)((b * 16 + t_in) * Hh + hin) * (Ww * 64) + ct;
            uint32_t win[20];
            #pragma unroll
            for (int jj = 0; jj < 20; jj++) win[jj] = src[offs[jj]];
            #pragma unroll
            for (int ktp = 0; ktp < 5; ktp++) {
                int tr = j + ktp - 4;
                if (tr >= 0 && tr < 4) {
                    #pragma unroll
                    for (int i = 0; i < 14; i++) {
                        #pragma unroll
                        for (int kw = 0; kw < 7; kw++)
                            acc[tr][i] = __hfma2(*(bf162*)&kv[ktp][kw],
                                                 *(bf162*)&win[i + 6 - kw],
                                                 acc[tr][i]);
                    }
                }
            }
        }
    }
    #pragma unroll
    for (int tr = 0; tr < 4; tr++) {
        uint32_t* dst = outp + (size_t)(((b * 16 + t0 + tr) * Hh + h) * Ww + w0) * 64 + ct;
        #pragma unroll
        for (int i = 0; i < 14; i++)
            dst[(size_t)i * 64] = *(uint32_t*)&acc[tr][i];
    }
}

// ---------------------------------------------------------------------------
// K3: LINEAR-domain Heinsen scan, 4 channels/thread (uint2) for ILP
// ---------------------------------------------------------------------------
__global__ void k_scan(void) {
    int idx = blockIdx.x * 256 + threadIdx.x;   // over B*H*W*32 quad-groups
    int cq = idx & 31;
    int rest = idx >> 5;
    int w = rest % 56; rest /= 56;
    int h = rest % 56;
    int b = rest / 56;
    size_t base = (((size_t)(b * Tt) * Hh + h) * Ww + w) * 32 + cq;   // uint2 units
    const uint2* gp = (const uint2*)g_gateS;
    const uint2* hp = (const uint2*)g_hidS;
    uint2* ep = (uint2*)g_E;
    float H0 = 0.f, H1 = 0.f, H2 = 0.f, H3 = 0.f;
    #pragma unroll
    for (int t = 0; t < Tt; t++) {
        size_t off = base + (size_t)t * (HWC / 4);
        uint2 gu = gp[off], hu = hp[off];
        float2 gA = __bfloat1622float2(*(bf162*)&gu.x);
        float2 gB = __bfloat1622float2(*(bf162*)&gu.y);
        float2 hA = __bfloat1622float2(*(bf162*)&hu.x);
        float2 hB = __bfloat1622float2(*(bf162*)&hu.y);
        float e0 = exp_fast(-fabsf(gA.x));
        float e1 = exp_fast(-fabsf(gA.y));
        float e2 = exp_fast(-fabsf(gB.x));
        float e3 = exp_fast(-fabsf(gB.y));
        float r0 = rcp_fast(1.f + e0);
        float r1 = rcp_fast(1.f + e1);
        float r2 = rcp_fast(1.f + e2);
        float r3 = rcp_fast(1.f + e3);
        float s0 = (gA.x >= 0.f) ? r0 : e0 * r0;
        float f0 = (gA.x >= 0.f) ? e0 * r0 : r0;
        float s1 = (gA.y >= 0.f) ? r1 : e1 * r1;
        float f1 = (gA.y >= 0.f) ? e1 * r1 : r1;
        float s2 = (gB.x >= 0.f) ? r2 : e2 * r2;
        float f2 = (gB.x >= 0.f) ? e2 * r2 : r2;
        float s3 = (gB.y >= 0.f) ? r3 : e3 * r3;
        float f3 = (gB.y >= 0.f) ? e3 * r3 : r3;
        H0 = fmaf(f0, H0, (hA.x * hA.x + 1e-6f) * s0);
        H1 = fmaf(f1, H1, (hA.y * hA.y + 1e-6f) * s1);
        H2 = fmaf(f2, H2, (hB.x * hB.x + 1e-6f) * s2);
        H3 = fmaf(f3, H3, (hB.y * hB.y + 1e-6f) * s3);
        bf162 oA = __floats2bfloat162_rn(H0, H1);
        bf162 oB = __floats2bfloat162_rn(H2, H3);
        uint2 o;
        o.x = *(uint32_t*)&oA;
        o.y = *(uint32_t*)&oB;
        ep[off] = o;
    }
}

// ---------------------------------------------------------------------------
// K4: womlp-v3: m=64 rows/CTA, 256 threads (wm2 x wn4), 2 CTAs/SM,
// DOUBLE-BUFFERED weight slots: W1 chunks live in Bs1, W2/Wo in Bs0.
// Weight loads (LDG->STS) overlap the gemm on the other slot; one sync per
// gemm boundary.
// ---------------------------------------------------------------------------
#define WM_SMEM ((64*SA + 64*SA + 128*SA + 128*SA)*2 + 1792*4 + 512)
__global__ void __launch_bounds__(256, 2) k_womlp(const float* __restrict__ x,
                                                  const float* __restrict__ bo,
                                                  const float* __restrict__ lns,
                                                  const float* __restrict__ lnb,
                                                  const float* __restrict__ b1,
                                                  const float* __restrict__ b2,
                                                  const float* __restrict__ gamma,
                                                  float* __restrict__ out) {
    extern __shared__ __align__(16) char sm[];
    bf16* As  = (bf16*)sm;                  // 64 x SA : E tile -> xn tile
    bf16* Cs  = As + 64 * SA;               // 64 x SA : gelu hidden chunk
    bf16* Bs0 = Cs + 64 * SA;               // 128 x SA : Wo / W2 chunks
    bf16* Bs1 = Bs0 + 128 * SA;             // 128 x SA : W1 chunks
    float* sbo  = (float*)(Bs1 + 128 * SA); // 128
    float* slns = sbo + 128;                // 128
    float* slnb = slns + 128;               // 128
    float* sb1  = slnb + 128;               // 512
    float* sb2  = sb1 + 512;                // 128
    float* sgm  = sb2 + 128;                // 128
    float* rs   = sgm + 128;                // 64*4
    float* rq   = rs + 256;                 // 64*4
    float2* stat = (float2*)(rq + 256);     // 64

    int tid = threadIdx.x, w = tid >> 5, l = tid & 31;
    int wm = w >> 2, wn = w & 3;
    int quad = l >> 2, t4 = l & 3;
    size_t m0 = (size_t)blockIdx.x * 64;

    if (tid < 128) {
        sbo[tid] = bo[tid]; slns[tid] = lns[tid]; slnb[tid] = lnb[tid];
        sb2[tid] = b2[tid]; sgm[tid] = gamma[tid];
    }
    sb1[tid] = b1[tid]; sb1[256 + tid] = b1[256 + tid];

    // load E tile (64x128) + Wo -> Bs0
    const uint4* ep = (const uint4*)(g_E + m0 * 128);
    #pragma unroll
    for (int j = 0; j < 4; j++) {
        int i = tid + 256 * j;
        int r = i >> 4, c = i & 15;
        *(uint4*)(As + r * SA + c * 8) = ep[i];
    }
    {
        const uint4* wop = (const uint4*)g_WoT;
        #pragma unroll
        for (int j = 0; j < 8; j++) {
            int i = tid + 256 * j;
            int r = i >> 4, c = i & 15;
            *(uint4*)(Bs0 + r * SA + c * 8) = wop[i];
        }
    }
    __syncthreads();

    uint32_t Abase  = smem_u32(As)  + ((l & 15) * SA + (l >> 4) * 8) * 2 + (wm * 32) * SA * 2;
    uint32_t Cbase  = smem_u32(Cs)  + ((l & 15) * SA + (l >> 4) * 8) * 2 + (wm * 32) * SA * 2;
    uint32_t B0base = smem_u32(Bs0) + ((l & 15) * SA + (l >> 4) * 8) * 2 + (wn * 32) * SA * 2;
    uint32_t B1base = smem_u32(Bs1) + ((l & 15) * SA + (l >> 4) * 8) * 2 + (wn * 32) * SA * 2;

    const uint4* w1p = (const uint4*)g_W1T;
    const uint4* w2p = (const uint4*)g_W2T;

    // ---------------- stage 0: wo GEMM (Bs0), stage W1c0 -> Bs1 -------------
    #pragma unroll
    for (int j = 0; j < 8; j++) {
        int i = tid + 256 * j;
        int r = i >> 4, c = i & 15;
        *(uint4*)(Bs1 + r * SA + c * 8) = w1p[i];
    }

    float acc[2][4][4];
    #pragma unroll
    for (int mf = 0; mf < 2; mf++)
        #pragma unroll
        for (int nf = 0; nf < 4; nf++)
            #pragma unroll
            for (int e = 0; e < 4; e++) acc[mf][nf][e] = 0.f;
    #pragma unroll
    for (int k = 0; k < 8; k++) {
        uint32_t a[2][4], b[4][2];
        #pragma unroll
        for (int mf = 0; mf < 2; mf++)
            LDSM4(a[mf][0], a[mf][1], a[mf][2], a[mf][3],
                  Abase + mf * 16 * SA * 2 + k * 32);
        #pragma unroll
        for (int nf2 = 0; nf2 < 2; nf2++) {
            uint32_t r0, r1, r2, r3;
            LDSM4(r0, r1, r2, r3, B0base + nf2 * 16 * SA * 2 + k * 32);
            b[nf2 * 2][0] = r0; b[nf2 * 2][1] = r2;
            b[nf2 * 2 + 1][0] = r1; b[nf2 * 2 + 1][1] = r3;
        }
        #pragma unroll
        for (int mf = 0; mf < 2; mf++)
            #pragma unroll
            for (int nf = 0; nf < 4; nf++) MMA16816(acc[mf][nf], a[mf], b[nf]);
    }

    // bias + per-row partial sums
    #pragma unroll
    for (int mf = 0; mf < 2; mf++) {
        float s0 = 0.f, q0 = 0.f, s1 = 0.f, q1 = 0.f;
        #pragma unroll
        for (int nf = 0; nf < 4; nf++) {
            int n = wn * 32 + nf * 8 + t4 * 2;
            float v0 = acc[mf][nf][0] + sbo[n];
            float v1 = acc[mf][nf][1] + sbo[n + 1];
            float v2 = acc[mf][nf][2] + sbo[n];
            float v3 = acc[mf][nf][3] + sbo[n + 1];
            acc[mf][nf][0] = v0; acc[mf][nf][1] = v1;
            acc[mf][nf][2] = v2; acc[mf][nf][3] = v3;
            s0 += v0 + v1; q0 += v0 * v0 + v1 * v1;
            s1 += v2 + v3; q1 += v2 * v2 + v3 * v3;
        }
        #pragma unroll
        for (int o = 1; o < 4; o <<= 1) {
            s0 += __shfl_xor_sync(0xffffffffu, s0, o);
            q0 += __shfl_xor_sync(0xffffffffu, q0, o);
            s1 += __shfl_xor_sync(0xffffffffu, s1, o);
            q1 += __shfl_xor_sync(0xffffffffu, q1, o);
        }
        if (t4 == 0) {
            int rA = wm * 32 + mf * 16 + quad;
            rs[rA * 4 + wn] = s0; rq[rA * 4 + wn] = q0;
            rs[(rA + 8) * 4 + wn] = s1; rq[(rA + 8) * 4 + wn] = q1;
        }
    }
    __syncthreads();      // gemm0 As reads done + rs/rq + W1c0 visible

    if (tid < 64) {
        float mean = (rs[tid * 4] + rs[tid * 4 + 1] + rs[tid * 4 + 2] + rs[tid * 4 + 3]) * (1.f / 128.f);
        float var = (rq[tid * 4] + rq[tid * 4 + 1] + rq[tid * 4 + 2] + rq[tid * 4 + 3]) * (1.f / 128.f) - mean * mean;
        stat[tid] = make_float2(mean, rsqrtf(var + 1e-6f));
    }
    __syncthreads();

    // write xn (bf16) into As
    #pragma unroll
    for (int mf = 0; mf < 2; mf++) {
        int rA = wm * 32 + mf * 16 + quad;
        float2 stA = stat[rA], stB = stat[rA + 8];
        #pragma unroll
        for (int nf = 0; nf < 4; nf++) {
            int n = wn * 32 + nf * 8 + t4 * 2;
            float x0 = (acc[mf][nf][0] - stA.x) * stA.y * slns[n] + slnb[n];
            float x1 = (acc[mf][nf][1] - stA.x) * stA.y * slns[n + 1] + slnb[n + 1];
            float x2 = (acc[mf][nf][2] - stB.x) * stB.y * slns[n] + slnb[n];
            float x3 = (acc[mf][nf][3] - stB.x) * stB.y * slns[n + 1] + slnb[n + 1];
            *(bf162*)(As + rA * SA + n) = __floats2bfloat162_rn(x0, x1);
            *(bf162*)(As + (rA + 8) * SA + n) = __floats2bfloat162_rn(x2, x3);
        }
    }
    __syncthreads();      // xn visible

    // ---------------- fused MLP, double-buffered weights --------------------
    float acc2[2][4][4];
    #pragma unroll
    for (int mf = 0; mf < 2; mf++)
        #pragma unroll
        for (int nf = 0; nf < 4; nf++)
            #pragma unroll
            for (int e = 0; e < 4; e++) acc2[mf][nf][e] = 0.f;

    for (int nc = 0; nc < 4; nc++) {
        // gemm1: xn @ W1c (Bs1); stage W2c -> Bs0 concurrently
        #pragma unroll
        for (int j = 0; j < 8; j++) {
            int i = tid + 256 * j;
            int r = i >> 4, c = i & 15;
            *(uint4*)(Bs0 + r * SA + c * 8) = w2p[(size_t)r * 64 + nc * 16 + c];
        }
        float a1[2][4][4];
        #pragma unroll
        for (int mf = 0; mf < 2; mf++)
            #pragma unroll
            for (int nf = 0; nf < 4; nf++)
                #pragma unroll
                for (int e = 0; e < 4; e++) a1[mf][nf][e] = 0.f;
        #pragma unroll
        for (int k = 0; k < 8; k++) {
            uint32_t a[2][4], b[4][2];
            #pragma unroll
            for (int mf = 0; mf < 2; mf++)
                LDSM4(a[mf][0], a[mf][1], a[mf][2], a[mf][3],
                      Abase + mf * 16 * SA * 2 + k * 32);
            #pragma unroll
            for (int nf2 = 0; nf2 < 2; nf2++) {
                uint32_t r0, r1, r2, r3;
                LDSM4(r0, r1, r2, r3, B1base + nf2 * 16 * SA * 2 + k * 32);
                b[nf2 * 2][0] = r0; b[nf2 * 2][1] = r2;
                b[nf2 * 2 + 1][0] = r1; b[nf2 * 2 + 1][1] = r3;
            }
            #pragma unroll
            for (int mf = 0; mf < 2; mf++)
                #pragma unroll
                for (int nf = 0; nf < 4; nf++) MMA16816(a1[mf][nf], a[mf], b[nf]);
        }
        // gelu -> Cs
        #pragma unroll
        for (int mf = 0; mf < 2; mf++)
            #pragma unroll
            for (int nf = 0; nf < 4; nf++) {
                int nl = wn * 32 + nf * 8 + t4 * 2;
                int ng = nc * 128 + nl;
                int r0 = wm * 32 + mf * 16 + quad;
                #pragma unroll
                for (int hrow = 0; hrow < 2; hrow++) {
                    float v0 = a1[mf][nf][hrow * 2] + sb1[ng];
                    float v1 = a1[mf][nf][hrow * 2 + 1] + sb1[ng + 1];
                    float t0 = tanh_fast(0.7978845608028654f * (v0 + 0.044715f * v0 * v0 * v0));
                    float t1 = tanh_fast(0.7978845608028654f * (v1 + 0.044715f * v1 * v1 * v1));
                    *(bf162*)(Cs + (r0 + hrow * 8) * SA + nl) =
                        __floats2bfloat162_rn(0.5f * v0 * (1.f + t0), 0.5f * v1 * (1.f + t1));
                }
            }
        __syncthreads();      // Cs + W2c(Bs0) visible; Bs1 reads done

        // gemm2: Cs @ W2c (Bs0), accumulate; stage W1c(nc+1) -> Bs1
        if (nc < 3) {
            #pragma unroll
            for (int j = 0; j < 8; j++) {
                int i = tid + 256 * j;
                int r = i >> 4, c = i & 15;
                *(uint4*)(Bs1 + r * SA + c * 8) = w1p[(nc + 1) * 2048 + i];
            }
        }
        #pragma unroll
        for (int k = 0; k < 8; k++) {
            uint32_t a[2][4], b[4][2];
            #pragma unroll
            for (int mf = 0; mf < 2; mf++)
                LDSM4(a[mf][0], a[mf][1], a[mf][2], a[mf][3],
                      Cbase + mf * 16 * SA * 2 + k * 32);
            #pragma unroll
            for (int nf2 = 0; nf2 < 2; nf2++) {
                uint32_t r0, r1, r2, r3;
                LDSM4(r0, r1, r2, r3, B0base + nf2 * 16 * SA * 2 + k * 32);
                b[nf2 * 2][0] = r0; b[nf2 * 2][1] = r2;
                b[nf2 * 2 + 1][0] = r1; b[nf2 * 2 + 1][1] = r3;
            }
            #pragma unroll
            for (int mf = 0; mf < 2; mf++)
                #pragma unroll
                for (int nf = 0; nf < 4; nf++) MMA16816(acc2[mf][nf], a[mf], b[nf]);
        }
        __syncthreads();      // Cs reads done (next gelu may overwrite); W1c(nc+1) visible
    }

    // ---------------- epilogue: *gamma + residual -> out (f32) ----------------
    #pragma unroll
    for (int mf = 0; mf < 2; mf++)
        #pragma unroll
        for (int nf = 0; nf < 4; nf++) {
            int n = wn * 32 + nf * 8 + t4 * 2;
            size_t r0 = m0 + wm * 32 + mf * 16 + quad;
            #pragma unroll
            for (int hrow = 0; hrow < 2; hrow++) {
                size_t r = r0 + hrow * 8;
                float v0 = (acc2[mf][nf][hrow * 2] + sb2[n]) * sgm[n] + x[r * 128 + n];
                float v1 = (acc2[mf][nf][hrow * 2 + 1] + sb2[n + 1]) * sgm[n + 1] + x[r * 128 + n + 1];
                out[r * 128 + n] = v0;
                out[r * 128 + n + 1] = v1;
            }
        }
}

// ---------------------------------------------------------------------------
extern "C" void kernel_launch(void* const* d_in, const int* in_sizes, int n_in,
                              void* d_out, int out_size) {
    const float* x     = (const float*)d_in[0];
    const float* Wg    = (const float*)d_in[1];
    const float* bg    = (const float*)d_in[2];
    const float* Wh    = (const float*)d_in[3];
    const float* bh    = (const float*)d_in[4];
    const float* gk    = (const float*)d_in[5];
    const float* hk    = (const float*)d_in[6];
    const float* Wo    = (const float*)d_in[7];
    const float* bo    = (const float*)d_in[8];
    const float* lns   = (const float*)d_in[9];
    const float* lnb   = (const float*)d_in[10];
    const float* W1    = (const float*)d_in[11];
    const float* b1    = (const float*)d_in[12];
    const float* W2    = (const float*)d_in[13];
    const float* b2    = (const float*)d_in[14];
    const float* gamma = (const float*)d_in[15];
    float* out = (float*)d_out;

    cudaFuncSetAttribute(k_proj,  cudaFuncAttributeMaxDynamicSharedMemorySize, PROJ_SMEM);
    cudaFuncSetAttribute(k_womlp, cudaFuncAttributeMaxDynamicSharedMemorySize, WM_SMEM);

    k_prep<<<256, 256>>>(Wg, Wh, Wo, W1, W2, gk, hk);
    k_proj<<<NTILES, 256, PROJ_SMEM>>>(x, bg, bh);
    k_conv<<<dim3(4, Bb * Hh, 2), 256>>>();
    k_scan<<<(Bb * Hh * Ww * 32) / 256, 256>>>();
    k_womlp<<<NPTS / 64, 256, WM_SMEM>>>(x, bo, lns, lnb, b1, b2, gamma, out);
}

// round 12
// speedup vs baseline: 1.0285x; 1.0285x over previous
#include <cuda_runtime.h>
#include <cuda_bf16.h>
#include <math.h>
#include <stdint.h>

#define Bb 2
#define Tt 16
#define Hh 56
#define Ww 56
#define Cc 128
#define NPTS (Bb*Tt*Hh*Ww)          /* 100352 */
#define TOT  (NPTS*Cc)              /* 12845056 */
#define HWC  (Hh*Ww*Cc)
#define KTAPS 245
#define NTILES (NPTS/128)           /* 784 */

typedef __nv_bfloat16 bf16;
typedef __nv_bfloat162 bf162;

// ---------------- device scratch (allocation-free) ----------------
__device__ __align__(16) bf16 g_gateP[TOT];
__device__ __align__(16) bf16 g_hidP[TOT];
__device__ __align__(16) bf16 g_gateS[TOT];
__device__ __align__(16) bf16 g_hidS[TOT];
__device__ __align__(16) bf16 g_E[TOT];
__device__ __align__(16) bf16 g_WgT[Cc*Cc];       // [n][k]
__device__ __align__(16) bf16 g_WhT[Cc*Cc];
__device__ __align__(16) bf16 g_WoT[Cc*Cc];
__device__ __align__(16) bf16 g_W1T[512*Cc];      // [n=512][k=128]
__device__ __align__(16) bf16 g_W2T[Cc*512];      // [n=128][k=512]
__device__ __align__(16) bf16 g_kB[2][KTAPS*Cc];  // [tap][c]

// ---------------- helpers ----------------
__device__ __forceinline__ uint32_t smem_u32(const void* p) {
    uint32_t a;
    asm("{ .reg .u64 t; cvta.to.shared.u64 t, %1; cvt.u32.u64 %0, t; }" : "=r"(a) : "l"(p));
    return a;
}
#define LDSM4(r0, r1, r2, r3, a) \
    asm volatile("ldmatrix.sync.aligned.m8n8.x4.shared.b16 {%0,%1,%2,%3}, [%4];" \
        : "=r"(r0), "=r"(r1), "=r"(r2), "=r"(r3) : "r"(a))
#define MMA16816(c, a, b) \
    asm volatile("mma.sync.aligned.m16n8k16.row.col.f32.bf16.bf16.f32 " \
        "{%0,%1,%2,%3},{%4,%5,%6,%7},{%8,%9},{%0,%1,%2,%3};" \
        : "+f"((c)[0]), "+f"((c)[1]), "+f"((c)[2]), "+f"((c)[3]) \
        : "r"((a)[0]), "r"((a)[1]), "r"((a)[2]), "r"((a)[3]), "r"((b)[0]), "r"((b)[1]))

__device__ __forceinline__ float tanh_fast(float x) {
    float y;
    asm("tanh.approx.f32 %0, %1;" : "=f"(y) : "f"(x));
    return y;
}
__device__ __forceinline__ float exp_fast(float x) {
    float y;
    asm("ex2.approx.f32 %0, %1;" : "=f"(y) : "f"(x * 1.4426950408889634f));
    return y;
}
__device__ __forceinline__ float rcp_fast(float x) {
    float y;
    asm("rcp.approx.f32 %0, %1;" : "=f"(y) : "f"(x));
    return y;
}

#define SA 136    /* smem row stride (bf16 elems) for 128-col tiles */

// ---------------------------------------------------------------------------
// K0: weight prep
// ---------------------------------------------------------------------------
__global__ void k_prep(const float* __restrict__ Wg, const float* __restrict__ Wh,
                       const float* __restrict__ Wo, const float* __restrict__ W1,
                       const float* __restrict__ W2, const float* __restrict__ gk,
                       const float* __restrict__ hk) {
    int i = blockIdx.x * 256 + threadIdx.x;
    if (i < 16384) {
        int n = i >> 7, k = i & 127;
        g_WgT[i] = __float2bfloat16(Wg[k * 128 + n]);
        g_WhT[i] = __float2bfloat16(Wh[k * 128 + n]);
        g_WoT[i] = __float2bfloat16(Wo[k * 128 + n]);
    }
    if (i < 65536) {
        int n = i >> 7, k = i & 127;
        g_W1T[i] = __float2bfloat16(W1[k * 512 + n]);
        int n2 = i >> 9, k2 = i & 511;
        g_W2T[i] = __float2bfloat16(W2[k2 * 128 + n2]);
    }
    if (i < 2 * KTAPS * 128) {
        int which = i / (KTAPS * 128);
        int j = i - which * (KTAPS * 128);
        int tap = j >> 7, c = j & 127;
        const float* s = which ? hk : gk;
        g_kB[which][j] = __float2bfloat16(s[c * KTAPS + tap]);
    }
}

// ---------------------------------------------------------------------------
// K1: dual projection, 256 threads (8 warps: which x wn(4), 32 cols each)
// ---------------------------------------------------------------------------
#define PROJ_SMEM (3*128*SA*2 + 256*4)
__global__ void __launch_bounds__(256) k_proj(const float* __restrict__ x,
                                              const float* __restrict__ bg,
                                              const float* __restrict__ bh) {
    extern __shared__ __align__(16) char sm[];
    bf16* As = (bf16*)sm;
    bf16* Bs = As + 128 * SA;
    float* sbias = (float*)(Bs + 2 * 128 * SA);
    int tid = threadIdx.x, w = tid >> 5, l = tid & 31;
    size_t m0 = (size_t)blockIdx.x * 128;
    if (tid < 128) sbias[tid] = bg[tid];
    else           sbias[tid] = bh[tid - 128];

    const float2* xs = (const float2*)(x + m0 * 128);
    for (int idx = tid; idx < 128 * 64; idx += 256) {
        int r = idx >> 6, cp = idx & 63;
        float2 v = xs[idx];
        *(bf162*)(As + r * SA + cp * 2) = __floats2bfloat162_rn(v.x, v.y);
    }
    const uint4* wgp = (const uint4*)g_WgT;
    const uint4* whp = (const uint4*)g_WhT;
    for (int idx = tid; idx < 128 * 16; idx += 256) {
        int r = idx >> 4, c = idx & 15;
        *(uint4*)(Bs + r * SA + c * 8) = wgp[idx];
        *(uint4*)(Bs + 128 * SA + r * SA + c * 8) = whp[idx];
    }
    __syncthreads();

    int which = w >> 2;
    int wn0 = (w & 3) * 32;
    uint32_t Abase = smem_u32(As) + ((l & 15) * SA + (l >> 4) * 8) * 2;
    uint32_t Bbase = smem_u32(Bs + which * 128 * SA) + ((l & 15) * SA + (l >> 4) * 8) * 2 + wn0 * SA * 2;
    bf16* outb = which ? g_hidP : g_gateP;
    float* bb = sbias + which * 128;
    int quad = l >> 2, t4 = l & 3;

    for (int mc = 0; mc < 4; mc++) {
        float acc[2][4][4];
        #pragma unroll
        for (int mf = 0; mf < 2; mf++)
            #pragma unroll
            for (int nf = 0; nf < 4; nf++)
                #pragma unroll
                for (int e = 0; e < 4; e++) acc[mf][nf][e] = 0.f;
        #pragma unroll
        for (int k = 0; k < 8; k++) {
            uint32_t a[2][4], b[4][2];
            #pragma unroll
            for (int mf = 0; mf < 2; mf++)
                LDSM4(a[mf][0], a[mf][1], a[mf][2], a[mf][3],
                      Abase + (mc * 32 + mf * 16) * SA * 2 + k * 32);
            #pragma unroll
            for (int nf2 = 0; nf2 < 2; nf2++) {
                uint32_t r0, r1, r2, r3;
                LDSM4(r0, r1, r2, r3, Bbase + nf2 * 16 * SA * 2 + k * 32);
                b[nf2 * 2][0] = r0; b[nf2 * 2][1] = r2;
                b[nf2 * 2 + 1][0] = r1; b[nf2 * 2 + 1][1] = r3;
            }
            #pragma unroll
            for (int mf = 0; mf < 2; mf++)
                #pragma unroll
                for (int nf = 0; nf < 4; nf++) MMA16816(acc[mf][nf], a[mf], b[nf]);
        }
        #pragma unroll
        for (int mf = 0; mf < 2; mf++)
            #pragma unroll
            for (int nf = 0; nf < 4; nf++) {
                int n = wn0 + nf * 8 + t4 * 2;
                int r0 = mc * 32 + mf * 16 + quad;
                *(bf162*)(outb + (m0 + r0) * 128 + n) =
                    __floats2bfloat162_rn(acc[mf][nf][0] + bb[n], acc[mf][nf][1] + bb[n + 1]);
                *(bf162*)(outb + (m0 + r0 + 8) * 128 + n) =
                    __floats2bfloat162_rn(acc[mf][nf][2] + bb[n], acc[mf][nf][3] + bb[n + 1]);
            }
    }
}

// ---------------------------------------------------------------------------
// K2: depthwise circular conv 5x7x7 with t-reuse (round-8 version)
// ---------------------------------------------------------------------------
__global__ void __launch_bounds__(256) k_conv(void) {
    int ct = threadIdx.x & 63;
    int tq = threadIdx.x >> 6;
    int which = blockIdx.z;
    const uint32_t* __restrict__ in = (const uint32_t*)(which ? g_hidP : g_gateP);
    uint32_t* __restrict__ outp = (uint32_t*)(which ? g_hidS : g_gateS);
    const uint32_t* __restrict__ kt = (const uint32_t*)g_kB[which];
    int w0 = blockIdx.x * 14;
    int by = blockIdx.y;
    int h = by % Hh;
    int b = by / Hh;
    int t0 = tq * 4;

    int offs[20];
    #pragma unroll
    for (int j = 0; j < 20; j++) {
        int wi = w0 - 3 + j;
        if (wi < 0)   wi += 56;
        if (wi >= 56) wi -= 56;
        offs[j] = wi * 64;
    }

    bf162 acc[4][14];
    bf162 z = __floats2bfloat162_rn(0.f, 0.f);
    #pragma unroll
    for (int tr = 0; tr < 4; tr++)
        #pragma unroll
        for (int i = 0; i < 14; i++) acc[tr][i] = z;

    for (int kh = 0; kh < 7; kh++) {
        int hin = h - kh + 3;
        if (hin < 0)   hin += 56;
        if (hin >= 56) hin -= 56;
        uint32_t kv[5][7];
        #pragma unroll
        for (int ktp = 0; ktp < 5; ktp++)
            #pragma unroll
            for (int kw = 0; kw < 7; kw++)
                kv[ktp][kw] = kt[(size_t)(ktp * 49 + kh * 7 + kw) * 64 + ct];

        #pragma unroll
        for (int j = 0; j < 8; j++) {
            int t_in = (t0 - 2 + j) & 15;
            const uint32_t* src = in + (size_t)((b * 16 + t_in) * Hh + hin) * (Ww * 64) + ct;
            uint32_t win[20];
            #pragma unroll
            for (int jj = 0; jj < 20; jj++) win[jj] = src[offs[jj]];
            #pragma unroll
            for (int ktp = 0; ktp < 5; ktp++) {
                int tr = j + ktp - 4;
                if (tr >= 0 && tr < 4) {
                    #pragma unroll
                    for (int i = 0; i < 14; i++) {
                        #pragma unroll
                        for (int kw = 0; kw < 7; kw++)
                            acc[tr][i] = __hfma2(*(bf162*)&kv[ktp][kw],
                                                 *(bf162*)&win[i + 6 - kw],
                                                 acc[tr][i]);
                    }
                }
            }
        }
    }
    #pragma unroll
    for (int tr = 0; tr < 4; tr++) {
        uint32_t* dst = outp + (size_t)(((b * 16 + t0 + tr) * Hh + h) * Ww + w0) * 64 + ct;
        #pragma unroll
        for (int i = 0; i < 14; i++)
            dst[(size_t)i * 64] = *(uint32_t*)&acc[tr][i];
    }
}

// ---------------------------------------------------------------------------
// K3: LINEAR-domain Heinsen scan, 4 channels/thread (uint2) for ILP
// ---------------------------------------------------------------------------
__global__ void k_scan(void) {
    int idx = blockIdx.x * 256 + threadIdx.x;   // over B*H*W*32 quad-groups
    int cq = idx & 31;
    int rest = idx >> 5;
    int w = rest % 56; rest /= 56;
    int h = rest % 56;
    int b = rest / 56;
    size_t base = (((size_t)(b * Tt) * Hh + h) * Ww + w) * 32 + cq;   // uint2 units
    const uint2* gp = (const uint2*)g_gateS;
    const uint2* hp = (const uint2*)g_hidS;
    uint2* ep = (uint2*)g_E;
    float H0 = 0.f, H1 = 0.f, H2 = 0.f, H3 = 0.f;
    #pragma unroll
    for (int t = 0; t < Tt; t++) {
        size_t off = base + (size_t)t * (HWC / 4);
        uint2 gu = gp[off], hu = hp[off];
        float2 gA = __bfloat1622float2(*(bf162*)&gu.x);
        float2 gB = __bfloat1622float2(*(bf162*)&gu.y);
        float2 hA = __bfloat1622float2(*(bf162*)&hu.x);
        float2 hB = __bfloat1622float2(*(bf162*)&hu.y);
        float e0 = exp_fast(-fabsf(gA.x));
        float e1 = exp_fast(-fabsf(gA.y));
        float e2 = exp_fast(-fabsf(gB.x));
        float e3 = exp_fast(-fabsf(gB.y));
        float r0 = rcp_fast(1.f + e0);
        float r1 = rcp_fast(1.f + e1);
        float r2 = rcp_fast(1.f + e2);
        float r3 = rcp_fast(1.f + e3);
        float s0 = (gA.x >= 0.f) ? r0 : e0 * r0;
        float f0 = (gA.x >= 0.f) ? e0 * r0 : r0;
        float s1 = (gA.y >= 0.f) ? r1 : e1 * r1;
        float f1 = (gA.y >= 0.f) ? e1 * r1 : r1;
        float s2 = (gB.x >= 0.f) ? r2 : e2 * r2;
        float f2 = (gB.x >= 0.f) ? e2 * r2 : r2;
        float s3 = (gB.y >= 0.f) ? r3 : e3 * r3;
        float f3 = (gB.y >= 0.f) ? e3 * r3 : r3;
        H0 = fmaf(f0, H0, (hA.x * hA.x + 1e-6f) * s0);
        H1 = fmaf(f1, H1, (hA.y * hA.y + 1e-6f) * s1);
        H2 = fmaf(f2, H2, (hB.x * hB.x + 1e-6f) * s2);
        H3 = fmaf(f3, H3, (hB.y * hB.y + 1e-6f) * s3);
        bf162 oA = __floats2bfloat162_rn(H0, H1);
        bf162 oB = __floats2bfloat162_rn(H2, H3);
        uint2 o;
        o.x = *(uint32_t*)&oA;
        o.y = *(uint32_t*)&oB;
        ep[off] = o;
    }
}

// ---------------------------------------------------------------------------
// K4: womlp (round-10 v2): m=64 rows/CTA, 256 threads (wm2 x wn4), 2 CTAs/SM.
// E@Wo+bo -> LN -> per 128-chunk: gelu(xn@W1c+b1c) -> Cs -> @W2c accumulate
// -> *gamma + x -> out.  Single Bs slot with register prefetch.
// ---------------------------------------------------------------------------
#define WM_SMEM ((64*SA + 64*SA + 128*SA)*2 + 1792*4)
__global__ void __launch_bounds__(256, 2) k_womlp(const float* __restrict__ x,
                                                  const float* __restrict__ bo,
                                                  const float* __restrict__ lns,
                                                  const float* __restrict__ lnb,
                                                  const float* __restrict__ b1,
                                                  const float* __restrict__ b2,
                                                  const float* __restrict__ gamma,
                                                  float* __restrict__ out) {
    extern __shared__ __align__(16) char sm[];
    bf16* As = (bf16*)sm;                  // 64 x SA : E tile -> xn tile
    bf16* Cs = As + 64 * SA;               // 64 x SA : gelu hidden chunk
    bf16* Bs = Cs + 64 * SA;               // 128 x SA : weight chunk slot
    float* sbo  = (float*)(Bs + 128 * SA); // 128
    float* slns = sbo + 128;               // 128
    float* slnb = slns + 128;              // 128
    float* sb1  = slnb + 128;              // 512
    float* sb2  = sb1 + 512;               // 128
    float* sgm  = sb2 + 128;               // 128
    float* rs   = sgm + 128;               // 64*4
    float* rq   = rs + 256;                // 64*4
    float2* stat = (float2*)(rq + 256);    // 64

    int tid = threadIdx.x, w = tid >> 5, l = tid & 31;
    int wm = w >> 2, wn = w & 3;
    int quad = l >> 2, t4 = l & 3;
    size_t m0 = (size_t)blockIdx.x * 64;

    if (tid < 128) {
        sbo[tid] = bo[tid]; slns[tid] = lns[tid]; slnb[tid] = lnb[tid];
        sb2[tid] = b2[tid]; sgm[tid] = gamma[tid];
    }
    sb1[tid] = b1[tid]; sb1[256 + tid] = b1[256 + tid];

    // load E tile (64x128) + Wo (128x128)
    const uint4* ep = (const uint4*)(g_E + m0 * 128);
    #pragma unroll
    for (int j = 0; j < 4; j++) {
        int i = tid + 256 * j;
        int r = i >> 4, c = i & 15;
        *(uint4*)(As + r * SA + c * 8) = ep[i];
    }
    {
        const uint4* wop = (const uint4*)g_WoT;
        #pragma unroll
        for (int j = 0; j < 8; j++) {
            int i = tid + 256 * j;
            int r = i >> 4, c = i & 15;
            *(uint4*)(Bs + r * SA + c * 8) = wop[i];
        }
    }
    __syncthreads();

    uint32_t Abase = smem_u32(As) + ((l & 15) * SA + (l >> 4) * 8) * 2 + (wm * 32) * SA * 2;
    uint32_t Cbase = smem_u32(Cs) + ((l & 15) * SA + (l >> 4) * 8) * 2 + (wm * 32) * SA * 2;
    uint32_t Bbase = smem_u32(Bs) + ((l & 15) * SA + (l >> 4) * 8) * 2 + (wn * 32) * SA * 2;

    const uint4* w1p = (const uint4*)g_W1T;
    const uint4* w2p = (const uint4*)g_W2T;
    uint4 pf[8];

    // ---------------- stage 0: wo GEMM (K=128) ----------------
    #pragma unroll
    for (int j = 0; j < 8; j++) pf[j] = w1p[tid + 256 * j];   // prefetch W1 chunk 0

    float acc[2][4][4];
    #pragma unroll
    for (int mf = 0; mf < 2; mf++)
        #pragma unroll
        for (int nf = 0; nf < 4; nf++)
            #pragma unroll
            for (int e = 0; e < 4; e++) acc[mf][nf][e] = 0.f;
    #pragma unroll
    for (int k = 0; k < 8; k++) {
        uint32_t a[2][4], b[4][2];
        #pragma unroll
        for (int mf = 0; mf < 2; mf++)
            LDSM4(a[mf][0], a[mf][1], a[mf][2], a[mf][3],
                  Abase + mf * 16 * SA * 2 + k * 32);
        #pragma unroll
        for (int nf2 = 0; nf2 < 2; nf2++) {
            uint32_t r0, r1, r2, r3;
            LDSM4(r0, r1, r2, r3, Bbase + nf2 * 16 * SA * 2 + k * 32);
            b[nf2 * 2][0] = r0; b[nf2 * 2][1] = r2;
            b[nf2 * 2 + 1][0] = r1; b[nf2 * 2 + 1][1] = r3;
        }
        #pragma unroll
        for (int mf = 0; mf < 2; mf++)
            #pragma unroll
            for (int nf = 0; nf < 4; nf++) MMA16816(acc[mf][nf], a[mf], b[nf]);
    }

    // bias + per-row partial sums
    #pragma unroll
    for (int mf = 0; mf < 2; mf++) {
        float s0 = 0.f, q0 = 0.f, s1 = 0.f, q1 = 0.f;
        #pragma unroll
        for (int nf = 0; nf < 4; nf++) {
            int n = wn * 32 + nf * 8 + t4 * 2;
            float v0 = acc[mf][nf][0] + sbo[n];
            float v1 = acc[mf][nf][1] + sbo[n + 1];
            float v2 = acc[mf][nf][2] + sbo[n];
            float v3 = acc[mf][nf][3] + sbo[n + 1];
            acc[mf][nf][0] = v0; acc[mf][nf][1] = v1;
            acc[mf][nf][2] = v2; acc[mf][nf][3] = v3;
            s0 += v0 + v1; q0 += v0 * v0 + v1 * v1;
            s1 += v2 + v3; q1 += v2 * v2 + v3 * v3;
        }
        #pragma unroll
        for (int o = 1; o < 4; o <<= 1) {
            s0 += __shfl_xor_sync(0xffffffffu, s0, o);
            q0 += __shfl_xor_sync(0xffffffffu, q0, o);
            s1 += __shfl_xor_sync(0xffffffffu, s1, o);
            q1 += __shfl_xor_sync(0xffffffffu, q1, o);
        }
        if (t4 == 0) {
            int rA = wm * 32 + mf * 16 + quad;
            rs[rA * 4 + wn] = s0; rq[rA * 4 + wn] = q0;
            rs[(rA + 8) * 4 + wn] = s1; rq[(rA + 8) * 4 + wn] = q1;
        }
    }
    __syncthreads();      // gemm0 smem reads done + rs/rq visible

    // store W1 chunk 0, compute LN stats
    #pragma unroll
    for (int j = 0; j < 8; j++) {
        int i = tid + 256 * j;
        int r = i >> 4, c = i & 15;
        *(uint4*)(Bs + r * SA + c * 8) = pf[j];
    }
    if (tid < 64) {
        float mean = (rs[tid * 4] + rs[tid * 4 + 1] + rs[tid * 4 + 2] + rs[tid * 4 + 3]) * (1.f / 128.f);
        float var = (rq[tid * 4] + rq[tid * 4 + 1] + rq[tid * 4 + 2] + rq[tid * 4 + 3]) * (1.f / 128.f) - mean * mean;
        stat[tid] = make_float2(mean, rsqrtf(var + 1e-6f));
    }
    __syncthreads();

    // write xn (bf16) into As
    #pragma unroll
    for (int mf = 0; mf < 2; mf++) {
        int rA = wm * 32 + mf * 16 + quad;
        float2 stA = stat[rA], stB = stat[rA + 8];
        #pragma unroll
        for (int nf = 0; nf < 4; nf++) {
            int n = wn * 32 + nf * 8 + t4 * 2;
            float x0 = (acc[mf][nf][0] - stA.x) * stA.y * slns[n] + slnb[n];
            float x1 = (acc[mf][nf][1] - stA.x) * stA.y * slns[n + 1] + slnb[n + 1];
            float x2 = (acc[mf][nf][2] - stB.x) * stB.y * slns[n] + slnb[n];
            float x3 = (acc[mf][nf][3] - stB.x) * stB.y * slns[n + 1] + slnb[n + 1];
            *(bf162*)(As + rA * SA + n) = __floats2bfloat162_rn(x0, x1);
            *(bf162*)(As + (rA + 8) * SA + n) = __floats2bfloat162_rn(x2, x3);
        }
    }
    __syncthreads();      // xn + W1c0 visible

    // ---------------- fused MLP: per 128-chunk gelu then W2 accumulate ------
    float acc2[2][4][4];
    #pragma unroll
    for (int mf = 0; mf < 2; mf++)
        #pragma unroll
        for (int nf = 0; nf < 4; nf++)
            #pragma unroll
            for (int e = 0; e < 4; e++) acc2[mf][nf][e] = 0.f;

    for (int nc = 0; nc < 4; nc++) {
        // --- gemm1: xn @ W1 chunk nc ; prefetch W2 chunk nc ---
        #pragma unroll
        for (int j = 0; j < 8; j++) {
            int i = tid + 256 * j;
            pf[j] = w2p[(size_t)(i >> 4) * 64 + nc * 16 + (i & 15)];
        }
        float a1[2][4][4];
        #pragma unroll
        for (int mf = 0; mf < 2; mf++)
            #pragma unroll
            for (int nf = 0; nf < 4; nf++)
                #pragma unroll
                for (int e = 0; e < 4; e++) a1[mf][nf][e] = 0.f;
        #pragma unroll
        for (int k = 0; k < 8; k++) {
            uint32_t a[2][4], b[4][2];
            #pragma unroll
            for (int mf = 0; mf < 2; mf++)
                LDSM4(a[mf][0], a[mf][1], a[mf][2], a[mf][3],
                      Abase + mf * 16 * SA * 2 + k * 32);
            #pragma unroll
            for (int nf2 = 0; nf2 < 2; nf2++) {
                uint32_t r0, r1, r2, r3;
                LDSM4(r0, r1, r2, r3, Bbase + nf2 * 16 * SA * 2 + k * 32);
                b[nf2 * 2][0] = r0; b[nf2 * 2][1] = r2;
                b[nf2 * 2 + 1][0] = r1; b[nf2 * 2 + 1][1] = r3;
            }
            #pragma unroll
            for (int mf = 0; mf < 2; mf++)
                #pragma unroll
                for (int nf = 0; nf < 4; nf++) MMA16816(a1[mf][nf], a[mf], b[nf]);
        }
        // gelu -> Cs (64 x 128 chunk, m x k layout)
        #pragma unroll
        for (int mf = 0; mf < 2; mf++)
            #pragma unroll
            for (int nf = 0; nf < 4; nf++) {
                int nl = wn * 32 + nf * 8 + t4 * 2;
                int ng = nc * 128 + nl;
                int r0 = wm * 32 + mf * 16 + quad;
                #pragma unroll
                for (int hrow = 0; hrow < 2; hrow++) {
                    float v0 = a1[mf][nf][hrow * 2] + sb1[ng];
                    float v1 = a1[mf][nf][hrow * 2 + 1] + sb1[ng + 1];
                    float t0 = tanh_fast(0.7978845608028654f * (v0 + 0.044715f * v0 * v0 * v0));
                    float t1 = tanh_fast(0.7978845608028654f * (v1 + 0.044715f * v1 * v1 * v1));
                    *(bf162*)(Cs + (r0 + hrow * 8) * SA + nl) =
                        __floats2bfloat162_rn(0.5f * v0 * (1.f + t0), 0.5f * v1 * (1.f + t1));
                }
            }
        __syncthreads();      // Bs(W1c) reads done + Cs written
        #pragma unroll
        for (int j = 0; j < 8; j++) {
            int i = tid + 256 * j;
            int r = i >> 4, c = i & 15;
            *(uint4*)(Bs + r * SA + c * 8) = pf[j];
        }
        __syncthreads();      // Bs = W2c, Cs visible

        // --- gemm2: Cs @ W2 chunk nc, accumulate; prefetch W1 chunk nc+1 ---
        if (nc < 3) {
            #pragma unroll
            for (int j = 0; j < 8; j++)
                pf[j] = w1p[(nc + 1) * 2048 + tid + 256 * j];
        }
        #pragma unroll
        for (int k = 0; k < 8; k++) {
            uint32_t a[2][4], b[4][2];
            #pragma unroll
            for (int mf = 0; mf < 2; mf++)
                LDSM4(a[mf][0], a[mf][1], a[mf][2], a[mf][3],
                      Cbase + mf * 16 * SA * 2 + k * 32);
            #pragma unroll
            for (int nf2 = 0; nf2 < 2; nf2++) {
                uint32_t r0, r1, r2, r3;
                LDSM4(r0, r1, r2, r3, Bbase + nf2 * 16 * SA * 2 + k * 32);
                b[nf2 * 2][0] = r0; b[nf2 * 2][1] = r2;
                b[nf2 * 2 + 1][0] = r1; b[nf2 * 2 + 1][1] = r3;
            }
            #pragma unroll
            for (int mf = 0; mf < 2; mf++)
                #pragma unroll
                for (int nf = 0; nf < 4; nf++) MMA16816(acc2[mf][nf], a[mf], b[nf]);
        }
        __syncthreads();      // Bs(W2c) + Cs reads done
        if (nc < 3) {
            #pragma unroll
            for (int j = 0; j < 8; j++) {
                int i = tid + 256 * j;
                int r = i >> 4, c = i & 15;
                *(uint4*)(Bs + r * SA + c * 8) = pf[j];
            }
            __syncthreads();  // Bs = W1c(nc+1)
        }
    }

    // ---------------- epilogue: *gamma + residual -> out (f32) ----------------
    #pragma unroll
    for (int mf = 0; mf < 2; mf++)
        #pragma unroll
        for (int nf = 0; nf < 4; nf++) {
            int n = wn * 32 + nf * 8 + t4 * 2;
            size_t r0 = m0 + wm * 32 + mf * 16 + quad;
            #pragma unroll
            for (int hrow = 0; hrow < 2; hrow++) {
                size_t r = r0 + hrow * 8;
                float v0 = (acc2[mf][nf][hrow * 2] + sb2[n]) * sgm[n] + x[r * 128 + n];
                float v1 = (acc2[mf][nf][hrow * 2 + 1] + sb2[n + 1]) * sgm[n + 1] + x[r * 128 + n + 1];
                out[r * 128 + n] = v0;
                out[r * 128 + n + 1] = v1;
            }
        }
}

// ---------------------------------------------------------------------------
extern "C" void kernel_launch(void* const* d_in, const int* in_sizes, int n_in,
                              void* d_out, int out_size) {
    const float* x     = (const float*)d_in[0];
    const float* Wg    = (const float*)d_in[1];
    const float* bg    = (const float*)d_in[2];
    const float* Wh    = (const float*)d_in[3];
    const float* bh    = (const float*)d_in[4];
    const float* gk    = (const float*)d_in[5];
    const float* hk    = (const float*)d_in[6];
    const float* Wo    = (const float*)d_in[7];
    const float* bo    = (const float*)d_in[8];
    const float* lns   = (const float*)d_in[9];
    const float* lnb   = (const float*)d_in[10];
    const float* W1    = (const float*)d_in[11];
    const float* b1    = (const float*)d_in[12];
    const float* W2    = (const float*)d_in[13];
    const float* b2    = (const float*)d_in[14];
    const float* gamma = (const float*)d_in[15];
    float* out = (float*)d_out;

    cudaFuncSetAttribute(k_proj,  cudaFuncAttributeMaxDynamicSharedMemorySize, PROJ_SMEM);
    cudaFuncSetAttribute(k_womlp, cudaFuncAttributeMaxDynamicSharedMemorySize, WM_SMEM);

    k_prep<<<256, 256>>>(Wg, Wh, Wo, W1, W2, gk, hk);
    k_proj<<<NTILES, 256, PROJ_SMEM>>>(x, bg, bh);
    k_conv<<<dim3(4, Bb * Hh, 2), 256>>>();
    k_scan<<<(Bb * Hh * Ww * 32) / 256, 256>>>();
    k_womlp<<<NPTS / 64, 256, WM_SMEM>>>(x, bo, lns, lnb, b1, b2, gamma, out);
}

// round 13
// speedup vs baseline: 1.0526x; 1.0234x over previous
#include <cuda_runtime.h>
#include <cuda_bf16.h>
#include <math.h>
#include <stdint.h>

#define Bb 2
#define Tt 16
#define Hh 56
#define Ww 56
#define Cc 128
#define NPTS (Bb*Tt*Hh*Ww)          /* 100352 */
#define TOT  (NPTS*Cc)              /* 12845056 */
#define HWC  (Hh*Ww*Cc)
#define KTAPS 245
#define NTILES (NPTS/128)           /* 784 */

typedef __nv_bfloat16 bf16;
typedef __nv_bfloat162 bf162;

// ---------------- device scratch (allocation-free) ----------------
__device__ __align__(16) bf16 g_gateP[TOT];
__device__ __align__(16) bf16 g_hidP[TOT];
__device__ __align__(16) bf16 g_gateS[TOT];
__device__ __align__(16) bf16 g_hidS[TOT];
__device__ __align__(16) bf16 g_E[TOT];
__device__ __align__(16) bf16 g_WgT[Cc*Cc];       // [n][k]
__device__ __align__(16) bf16 g_WhT[Cc*Cc];
__device__ __align__(16) bf16 g_WoT[Cc*Cc];
__device__ __align__(16) bf16 g_W1T[512*Cc];      // [n=512][k=128]
__device__ __align__(16) bf16 g_W2T[Cc*512];      // [n=128][k=512]
__device__ __align__(16) bf16 g_kB[2][KTAPS*Cc];  // [tap][c]

// ---------------- helpers ----------------
__device__ __forceinline__ uint32_t smem_u32(const void* p) {
    uint32_t a;
    asm("{ .reg .u64 t; cvta.to.shared.u64 t, %1; cvt.u32.u64 %0, t; }" : "=r"(a) : "l"(p));
    return a;
}
#define LDSM4(r0, r1, r2, r3, a) \
    asm volatile("ldmatrix.sync.aligned.m8n8.x4.shared.b16 {%0,%1,%2,%3}, [%4];" \
        : "=r"(r0), "=r"(r1), "=r"(r2), "=r"(r3) : "r"(a))
#define MMA16816(c, a, b) \
    asm volatile("mma.sync.aligned.m16n8k16.row.col.f32.bf16.bf16.f32 " \
        "{%0,%1,%2,%3},{%4,%5,%6,%7},{%8,%9},{%0,%1,%2,%3};" \
        : "+f"((c)[0]), "+f"((c)[1]), "+f"((c)[2]), "+f"((c)[3]) \
        : "r"((a)[0]), "r"((a)[1]), "r"((a)[2]), "r"((a)[3]), "r"((b)[0]), "r"((b)[1]))

__device__ __forceinline__ float tanh_fast(float x) {
    float y;
    asm("tanh.approx.f32 %0, %1;" : "=f"(y) : "f"(x));
    return y;
}
__device__ __forceinline__ float exp_fast(float x) {
    float y;
    asm("ex2.approx.f32 %0, %1;" : "=f"(y) : "f"(x * 1.4426950408889634f));
    return y;
}
__device__ __forceinline__ float rcp_fast(float x) {
    float y;
    asm("rcp.approx.f32 %0, %1;" : "=f"(y) : "f"(x));
    return y;
}

#define SA 136    /* smem row stride (bf16 elems) for 128-col tiles */

// ---------------------------------------------------------------------------
// K0: weight prep
// ---------------------------------------------------------------------------
__global__ void k_prep(const float* __restrict__ Wg, const float* __restrict__ Wh,
                       const float* __restrict__ Wo, const float* __restrict__ W1,
                       const float* __restrict__ W2, const float* __restrict__ gk,
                       const float* __restrict__ hk) {
    int i = blockIdx.x * 256 + threadIdx.x;
    if (i < 16384) {
        int n = i >> 7, k = i & 127;
        g_WgT[i] = __float2bfloat16(Wg[k * 128 + n]);
        g_WhT[i] = __float2bfloat16(Wh[k * 128 + n]);
        g_WoT[i] = __float2bfloat16(Wo[k * 128 + n]);
    }
    if (i < 65536) {
        int n = i >> 7, k = i & 127;
        g_W1T[i] = __float2bfloat16(W1[k * 512 + n]);
        int n2 = i >> 9, k2 = i & 511;
        g_W2T[i] = __float2bfloat16(W2[k2 * 128 + n2]);
    }
    if (i < 2 * KTAPS * 128) {
        int which = i / (KTAPS * 128);
        int j = i - which * (KTAPS * 128);
        int tap = j >> 7, c = j & 127;
        const float* s = which ? hk : gk;
        g_kB[which][j] = __float2bfloat16(s[c * KTAPS + tap]);
    }
}

// ---------------------------------------------------------------------------
// K1: dual projection, 256 threads (8 warps: which x wn(4), 32 cols each)
// ---------------------------------------------------------------------------
#define PROJ_SMEM (3*128*SA*2 + 256*4)
__global__ void __launch_bounds__(256) k_proj(const float* __restrict__ x,
                                              const float* __restrict__ bg,
                                              const float* __restrict__ bh) {
    extern __shared__ __align__(16) char sm[];
    bf16* As = (bf16*)sm;
    bf16* Bs = As + 128 * SA;
    float* sbias = (float*)(Bs + 2 * 128 * SA);
    int tid = threadIdx.x, w = tid >> 5, l = tid & 31;
    size_t m0 = (size_t)blockIdx.x * 128;
    if (tid < 128) sbias[tid] = bg[tid];
    else           sbias[tid] = bh[tid - 128];

    const float2* xs = (const float2*)(x + m0 * 128);
    for (int idx = tid; idx < 128 * 64; idx += 256) {
        int r = idx >> 6, cp = idx & 63;
        float2 v = xs[idx];
        *(bf162*)(As + r * SA + cp * 2) = __floats2bfloat162_rn(v.x, v.y);
    }
    const uint4* wgp = (const uint4*)g_WgT;
    const uint4* whp = (const uint4*)g_WhT;
    for (int idx = tid; idx < 128 * 16; idx += 256) {
        int r = idx >> 4, c = idx & 15;
        *(uint4*)(Bs + r * SA + c * 8) = wgp[idx];
        *(uint4*)(Bs + 128 * SA + r * SA + c * 8) = whp[idx];
    }
    __syncthreads();

    int which = w >> 2;
    int wn0 = (w & 3) * 32;
    uint32_t Abase = smem_u32(As) + ((l & 15) * SA + (l >> 4) * 8) * 2;
    uint32_t Bbase = smem_u32(Bs + which * 128 * SA) + ((l & 15) * SA + (l >> 4) * 8) * 2 + wn0 * SA * 2;
    bf16* outb = which ? g_hidP : g_gateP;
    float* bb = sbias + which * 128;
    int quad = l >> 2, t4 = l & 3;

    for (int mc = 0; mc < 4; mc++) {
        float acc[2][4][4];
        #pragma unroll
        for (int mf = 0; mf < 2; mf++)
            #pragma unroll
            for (int nf = 0; nf < 4; nf++)
                #pragma unroll
                for (int e = 0; e < 4; e++) acc[mf][nf][e] = 0.f;
        #pragma unroll
        for (int k = 0; k < 8; k++) {
            uint32_t a[2][4], b[4][2];
            #pragma unroll
            for (int mf = 0; mf < 2; mf++)
                LDSM4(a[mf][0], a[mf][1], a[mf][2], a[mf][3],
                      Abase + (mc * 32 + mf * 16) * SA * 2 + k * 32);
            #pragma unroll
            for (int nf2 = 0; nf2 < 2; nf2++) {
                uint32_t r0, r1, r2, r3;
                LDSM4(r0, r1, r2, r3, Bbase + nf2 * 16 * SA * 2 + k * 32);
                b[nf2 * 2][0] = r0; b[nf2 * 2][1] = r2;
                b[nf2 * 2 + 1][0] = r1; b[nf2 * 2 + 1][1] = r3;
            }
            #pragma unroll
            for (int mf = 0; mf < 2; mf++)
                #pragma unroll
                for (int nf = 0; nf < 4; nf++) MMA16816(acc[mf][nf], a[mf], b[nf]);
        }
        #pragma unroll
        for (int mf = 0; mf < 2; mf++)
            #pragma unroll
            for (int nf = 0; nf < 4; nf++) {
                int n = wn0 + nf * 8 + t4 * 2;
                int r0 = mc * 32 + mf * 16 + quad;
                *(bf162*)(outb + (m0 + r0) * 128 + n) =
                    __floats2bfloat162_rn(acc[mf][nf][0] + bb[n], acc[mf][nf][1] + bb[n + 1]);
                *(bf162*)(outb + (m0 + r0 + 8) * 128 + n) =
                    __floats2bfloat162_rn(acc[mf][nf][2] + bb[n], acc[mf][nf][3] + bb[n + 1]);
            }
    }
}

// ---------------------------------------------------------------------------
// K2: depthwise circular conv 5x7x7 with t-reuse (round-8 version)
// ---------------------------------------------------------------------------
__global__ void __launch_bounds__(256) k_conv(void) {
    int ct = threadIdx.x & 63;
    int tq = threadIdx.x >> 6;
    int which = blockIdx.z;
    const uint32_t* __restrict__ in = (const uint32_t*)(which ? g_hidP : g_gateP);
    uint32_t* __restrict__ outp = (uint32_t*)(which ? g_hidS : g_gateS);
    const uint32_t* __restrict__ kt = (const uint32_t*)g_kB[which];
    int w0 = blockIdx.x * 14;
    int by = blockIdx.y;
    int h = by % Hh;
    int b = by / Hh;
    int t0 = tq * 4;

    int offs[20];
    #pragma unroll
    for (int j = 0; j < 20; j++) {
        int wi = w0 - 3 + j;
        if (wi < 0)   wi += 56;
        if (wi >= 56) wi -= 56;
        offs[j] = wi * 64;
    }

    bf162 acc[4][14];
    bf162 z = __floats2bfloat162_rn(0.f, 0.f);
    #pragma unroll
    for (int tr = 0; tr < 4; tr++)
        #pragma unroll
        for (int i = 0; i < 14; i++) acc[tr][i] = z;

    for (int kh = 0; kh < 7; kh++) {
        int hin = h - kh + 3;
        if (hin < 0)   hin += 56;
        if (hin >= 56) hin -= 56;
        uint32_t kv[5][7];
        #pragma unroll
        for (int ktp = 0; ktp < 5; ktp++)
            #pragma unroll
            for (int kw = 0; kw < 7; kw++)
                kv[ktp][kw] = kt[(size_t)(ktp * 49 + kh * 7 + kw) * 64 + ct];

        #pragma unroll
        for (int j = 0; j < 8; j++) {
            int t_in = (t0 - 2 + j) & 15;
            const uint32_t* src = in + (size_t)((b * 16 + t_in) * Hh + hin) * (Ww * 64) + ct;
            uint32_t win[20];
            #pragma unroll
            for (int jj = 0; jj < 20; jj++) win[jj] = src[offs[jj]];
            #pragma unroll
            for (int ktp = 0; ktp < 5; ktp++) {
                int tr = j + ktp - 4;
                if (tr >= 0 && tr < 4) {
                    #pragma unroll
                    for (int i = 0; i < 14; i++) {
                        #pragma unroll
                        for (int kw = 0; kw < 7; kw++)
                            acc[tr][i] = __hfma2(*(bf162*)&kv[ktp][kw],
                                                 *(bf162*)&win[i + 6 - kw],
                                                 acc[tr][i]);
                    }
                }
            }
        }
    }
    #pragma unroll
    for (int tr = 0; tr < 4; tr++) {
        uint32_t* dst = outp + (size_t)(((b * 16 + t0 + tr) * Hh + h) * Ww + w0) * 64 + ct;
        #pragma unroll
        for (int i = 0; i < 14; i++)
            dst[(size_t)i * 64] = *(uint32_t*)&acc[tr][i];
    }
}

// ---------------------------------------------------------------------------
// K3: LINEAR-domain Heinsen scan, 4 channels/thread (uint2) for ILP
// ---------------------------------------------------------------------------
__global__ void k_scan(void) {
    int idx = blockIdx.x * 256 + threadIdx.x;   // over B*H*W*32 quad-groups
    int cq = idx & 31;
    int rest = idx >> 5;
    int w = rest % 56; rest /= 56;
    int h = rest % 56;
    int b = rest / 56;
    size_t base = (((size_t)(b * Tt) * Hh + h) * Ww + w) * 32 + cq;   // uint2 units
    const uint2* gp = (const uint2*)g_gateS;
    const uint2* hp = (const uint2*)g_hidS;
    uint2* ep = (uint2*)g_E;
    float H0 = 0.f, H1 = 0.f, H2 = 0.f, H3 = 0.f;
    #pragma unroll
    for (int t = 0; t < Tt; t++) {
        size_t off = base + (size_t)t * (HWC / 4);
        uint2 gu = gp[off], hu = hp[off];
        float2 gA = __bfloat1622float2(*(bf162*)&gu.x);
        float2 gB = __bfloat1622float2(*(bf162*)&gu.y);
        float2 hA = __bfloat1622float2(*(bf162*)&hu.x);
        float2 hB = __bfloat1622float2(*(bf162*)&hu.y);
        float e0 = exp_fast(-fabsf(gA.x));
        float e1 = exp_fast(-fabsf(gA.y));
        float e2 = exp_fast(-fabsf(gB.x));
        float e3 = exp_fast(-fabsf(gB.y));
        float r0 = rcp_fast(1.f + e0);
        float r1 = rcp_fast(1.f + e1);
        float r2 = rcp_fast(1.f + e2);
        float r3 = rcp_fast(1.f + e3);
        float s0 = (gA.x >= 0.f) ? r0 : e0 * r0;
        float f0 = (gA.x >= 0.f) ? e0 * r0 : r0;
        float s1 = (gA.y >= 0.f) ? r1 : e1 * r1;
        float f1 = (gA.y >= 0.f) ? e1 * r1 : r1;
        float s2 = (gB.x >= 0.f) ? r2 : e2 * r2;
        float f2 = (gB.x >= 0.f) ? e2 * r2 : r2;
        float s3 = (gB.y >= 0.f) ? r3 : e3 * r3;
        float f3 = (gB.y >= 0.f) ? e3 * r3 : r3;
        H0 = fmaf(f0, H0, (hA.x * hA.x + 1e-6f) * s0);
        H1 = fmaf(f1, H1, (hA.y * hA.y + 1e-6f) * s1);
        H2 = fmaf(f2, H2, (hB.x * hB.x + 1e-6f) * s2);
        H3 = fmaf(f3, H3, (hB.y * hB.y + 1e-6f) * s3);
        bf162 oA = __floats2bfloat162_rn(H0, H1);
        bf162 oB = __floats2bfloat162_rn(H2, H3);
        uint2 o;
        o.x = *(uint32_t*)&oA;
        o.y = *(uint32_t*)&oB;
        ep[off] = o;
    }
}

// ---------------------------------------------------------------------------
// K4: womlp (v2 + coalesced epilogue): m=64 rows/CTA, 256 threads, 2 CTAs/SM.
// E@Wo+bo -> LN -> per 128-chunk: gelu(xn@W1c+b1c) -> Cs -> @W2c accumulate
// -> stage y*gamma in smem -> coalesced +x -> out.
// ---------------------------------------------------------------------------
#define WM_SMEM ((64*SA + 64*SA + 128*SA)*2 + 1792*4)
__global__ void __launch_bounds__(256, 2) k_womlp(const float* __restrict__ x,
                                                  const float* __restrict__ bo,
                                                  const float* __restrict__ lns,
                                                  const float* __restrict__ lnb,
                                                  const float* __restrict__ b1,
                                                  const float* __restrict__ b2,
                                                  const float* __restrict__ gamma,
                                                  float* __restrict__ out) {
    extern __shared__ __align__(16) char sm[];
    bf16* As = (bf16*)sm;                  // 64 x SA : E tile -> xn tile
    bf16* Cs = As + 64 * SA;               // 64 x SA : gelu hidden chunk
    bf16* Bs = Cs + 64 * SA;               // 128 x SA : weight chunk slot
    float* sbo  = (float*)(Bs + 128 * SA); // 128
    float* slns = sbo + 128;               // 128
    float* slnb = slns + 128;              // 128
    float* sb1  = slnb + 128;              // 512
    float* sb2  = sb1 + 512;               // 128
    float* sgm  = sb2 + 128;               // 128
    float* rs   = sgm + 128;               // 64*4
    float* rq   = rs + 256;                // 64*4
    float2* stat = (float2*)(rq + 256);    // 64

    int tid = threadIdx.x, w = tid >> 5, l = tid & 31;
    int wm = w >> 2, wn = w & 3;
    int quad = l >> 2, t4 = l & 3;
    size_t m0 = (size_t)blockIdx.x * 64;

    if (tid < 128) {
        sbo[tid] = bo[tid]; slns[tid] = lns[tid]; slnb[tid] = lnb[tid];
        sb2[tid] = b2[tid]; sgm[tid] = gamma[tid];
    }
    sb1[tid] = b1[tid]; sb1[256 + tid] = b1[256 + tid];

    // load E tile (64x128) + Wo (128x128)
    const uint4* ep = (const uint4*)(g_E + m0 * 128);
    #pragma unroll
    for (int j = 0; j < 4; j++) {
        int i = tid + 256 * j;
        int r = i >> 4, c = i & 15;
        *(uint4*)(As + r * SA + c * 8) = ep[i];
    }
    {
        const uint4* wop = (const uint4*)g_WoT;
        #pragma unroll
        for (int j = 0; j < 8; j++) {
            int i = tid + 256 * j;
            int r = i >> 4, c = i & 15;
            *(uint4*)(Bs + r * SA + c * 8) = wop[i];
        }
    }
    __syncthreads();

    uint32_t Abase = smem_u32(As) + ((l & 15) * SA + (l >> 4) * 8) * 2 + (wm * 32) * SA * 2;
    uint32_t Cbase = smem_u32(Cs) + ((l & 15) * SA + (l >> 4) * 8) * 2 + (wm * 32) * SA * 2;
    uint32_t Bbase = smem_u32(Bs) + ((l & 15) * SA + (l >> 4) * 8) * 2 + (wn * 32) * SA * 2;

    const uint4* w1p = (const uint4*)g_W1T;
    const uint4* w2p = (const uint4*)g_W2T;
    uint4 pf[8];

    // ---------------- stage 0: wo GEMM (K=128) ----------------
    #pragma unroll
    for (int j = 0; j < 8; j++) pf[j] = w1p[tid + 256 * j];   // prefetch W1 chunk 0

    float acc[2][4][4];
    #pragma unroll
    for (int mf = 0; mf < 2; mf++)
        #pragma unroll
        for (int nf = 0; nf < 4; nf++)
            #pragma unroll
            for (int e = 0; e < 4; e++) acc[mf][nf][e] = 0.f;
    #pragma unroll
    for (int k = 0; k < 8; k++) {
        uint32_t a[2][4], b[4][2];
        #pragma unroll
        for (int mf = 0; mf < 2; mf++)
            LDSM4(a[mf][0], a[mf][1], a[mf][2], a[mf][3],
                  Abase + mf * 16 * SA * 2 + k * 32);
        #pragma unroll
        for (int nf2 = 0; nf2 < 2; nf2++) {
            uint32_t r0, r1, r2, r3;
            LDSM4(r0, r1, r2, r3, Bbase + nf2 * 16 * SA * 2 + k * 32);
            b[nf2 * 2][0] = r0; b[nf2 * 2][1] = r2;
            b[nf2 * 2 + 1][0] = r1; b[nf2 * 2 + 1][1] = r3;
        }
        #pragma unroll
        for (int mf = 0; mf < 2; mf++)
            #pragma unroll
            for (int nf = 0; nf < 4; nf++) MMA16816(acc[mf][nf], a[mf], b[nf]);
    }

    // bias + per-row partial sums
    #pragma unroll
    for (int mf = 0; mf < 2; mf++) {
        float s0 = 0.f, q0 = 0.f, s1 = 0.f, q1 = 0.f;
        #pragma unroll
        for (int nf = 0; nf < 4; nf++) {
            int n = wn * 32 + nf * 8 + t4 * 2;
            float v0 = acc[mf][nf][0] + sbo[n];
            float v1 = acc[mf][nf][1] + sbo[n + 1];
            float v2 = acc[mf][nf][2] + sbo[n];
            float v3 = acc[mf][nf][3] + sbo[n + 1];
            acc[mf][nf][0] = v0; acc[mf][nf][1] = v1;
            acc[mf][nf][2] = v2; acc[mf][nf][3] = v3;
            s0 += v0 + v1; q0 += v0 * v0 + v1 * v1;
            s1 += v2 + v3; q1 += v2 * v2 + v3 * v3;
        }
        #pragma unroll
        for (int o = 1; o < 4; o <<= 1) {
            s0 += __shfl_xor_sync(0xffffffffu, s0, o);
            q0 += __shfl_xor_sync(0xffffffffu, q0, o);
            s1 += __shfl_xor_sync(0xffffffffu, s1, o);
            q1 += __shfl_xor_sync(0xffffffffu, q1, o);
        }
        if (t4 == 0) {
            int rA = wm * 32 + mf * 16 + quad;
            rs[rA * 4 + wn] = s0; rq[rA * 4 + wn] = q0;
            rs[(rA + 8) * 4 + wn] = s1; rq[(rA + 8) * 4 + wn] = q1;
        }
    }
    __syncthreads();      // gemm0 smem reads done + rs/rq visible

    // store W1 chunk 0, compute LN stats
    #pragma unroll
    for (int j = 0; j < 8; j++) {
        int i = tid + 256 * j;
        int r = i >> 4, c = i & 15;
        *(uint4*)(Bs + r * SA + c * 8) = pf[j];
    }
    if (tid < 64) {
        float mean = (rs[tid * 4] + rs[tid * 4 + 1] + rs[tid * 4 + 2] + rs[tid * 4 + 3]) * (1.f / 128.f);
        float var = (rq[tid * 4] + rq[tid * 4 + 1] + rq[tid * 4 + 2] + rq[tid * 4 + 3]) * (1.f / 128.f) - mean * mean;
        stat[tid] = make_float2(mean, rsqrtf(var + 1e-6f));
    }
    __syncthreads();

    // write xn (bf16) into As
    #pragma unroll
    for (int mf = 0; mf < 2; mf++) {
        int rA = wm * 32 + mf * 16 + quad;
        float2 stA = stat[rA], stB = stat[rA + 8];
        #pragma unroll
        for (int nf = 0; nf < 4; nf++) {
            int n = wn * 32 + nf * 8 + t4 * 2;
            float x0 = (acc[mf][nf][0] - stA.x) * stA.y * slns[n] + slnb[n];
            float x1 = (acc[mf][nf][1] - stA.x) * stA.y * slns[n + 1] + slnb[n + 1];
            float x2 = (acc[mf][nf][2] - stB.x) * stB.y * slns[n] + slnb[n];
            float x3 = (acc[mf][nf][3] - stB.x) * stB.y * slns[n + 1] + slnb[n + 1];
            *(bf162*)(As + rA * SA + n) = __floats2bfloat162_rn(x0, x1);
            *(bf162*)(As + (rA + 8) * SA + n) = __floats2bfloat162_rn(x2, x3);
        }
    }
    __syncthreads();      // xn + W1c0 visible

    // ---------------- fused MLP: per 128-chunk gelu then W2 accumulate ------
    float acc2[2][4][4];
    #pragma unroll
    for (int mf = 0; mf < 2; mf++)
        #pragma unroll
        for (int nf = 0; nf < 4; nf++)
            #pragma unroll
            for (int e = 0; e < 4; e++) acc2[mf][nf][e] = 0.f;

    for (int nc = 0; nc < 4; nc++) {
        // --- gemm1: xn @ W1 chunk nc ; prefetch W2 chunk nc ---
        #pragma unroll
        for (int j = 0; j < 8; j++) {
            int i = tid + 256 * j;
            pf[j] = w2p[(size_t)(i >> 4) * 64 + nc * 16 + (i & 15)];
        }
        float a1[2][4][4];
        #pragma unroll
        for (int mf = 0; mf < 2; mf++)
            #pragma unroll
            for (int nf = 0; nf < 4; nf++)
                #pragma unroll
                for (int e = 0; e < 4; e++) a1[mf][nf][e] = 0.f;
        #pragma unroll
        for (int k = 0; k < 8; k++) {
            uint32_t a[2][4], b[4][2];
            #pragma unroll
            for (int mf = 0; mf < 2; mf++)
                LDSM4(a[mf][0], a[mf][1], a[mf][2], a[mf][3],
                      Abase + mf * 16 * SA * 2 + k * 32);
            #pragma unroll
            for (int nf2 = 0; nf2 < 2; nf2++) {
                uint32_t r0, r1, r2, r3;
                LDSM4(r0, r1, r2, r3, Bbase + nf2 * 16 * SA * 2 + k * 32);
                b[nf2 * 2][0] = r0; b[nf2 * 2][1] = r2;
                b[nf2 * 2 + 1][0] = r1; b[nf2 * 2 + 1][1] = r3;
            }
            #pragma unroll
            for (int mf = 0; mf < 2; mf++)
                #pragma unroll
                for (int nf = 0; nf < 4; nf++) MMA16816(a1[mf][nf], a[mf], b[nf]);
        }
        // gelu -> Cs (64 x 128 chunk, m x k layout)
        #pragma unroll
        for (int mf = 0; mf < 2; mf++)
            #pragma unroll
            for (int nf = 0; nf < 4; nf++) {
                int nl = wn * 32 + nf * 8 + t4 * 2;
                int ng = nc * 128 + nl;
                int r0 = wm * 32 + mf * 16 + quad;
                #pragma unroll
                for (int hrow = 0; hrow < 2; hrow++) {
                    float v0 = a1[mf][nf][hrow * 2] + sb1[ng];
                    float v1 = a1[mf][nf][hrow * 2 + 1] + sb1[ng + 1];
                    float t0 = tanh_fast(0.7978845608028654f * (v0 + 0.044715f * v0 * v0 * v0));
                    float t1 = tanh_fast(0.7978845608028654f * (v1 + 0.044715f * v1 * v1 * v1));
                    *(bf162*)(Cs + (r0 + hrow * 8) * SA + nl) =
                        __floats2bfloat162_rn(0.5f * v0 * (1.f + t0), 0.5f * v1 * (1.f + t1));
                }
            }
        __syncthreads();      // Bs(W1c) reads done + Cs written
        #pragma unroll
        for (int j = 0; j < 8; j++) {
            int i = tid + 256 * j;
            int r = i >> 4, c = i & 15;
            *(uint4*)(Bs + r * SA + c * 8) = pf[j];
        }
        __syncthreads();      // Bs = W2c, Cs visible

        // --- gemm2: Cs @ W2 chunk nc, accumulate; prefetch W1 chunk nc+1 ---
        if (nc < 3) {
            #pragma unroll
            for (int j = 0; j < 8; j++)
                pf[j] = w1p[(nc + 1) * 2048 + tid + 256 * j];
        }
        #pragma unroll
        for (int k = 0; k < 8; k++) {
            uint32_t a[2][4], b[4][2];
            #pragma unroll
            for (int mf = 0; mf < 2; mf++)
                LDSM4(a[mf][0], a[mf][1], a[mf][2], a[mf][3],
                      Cbase + mf * 16 * SA * 2 + k * 32);
            #pragma unroll
            for (int nf2 = 0; nf2 < 2; nf2++) {
                uint32_t r0, r1, r2, r3;
                LDSM4(r0, r1, r2, r3, Bbase + nf2 * 16 * SA * 2 + k * 32);
                b[nf2 * 2][0] = r0; b[nf2 * 2][1] = r2;
                b[nf2 * 2 + 1][0] = r1; b[nf2 * 2 + 1][1] = r3;
            }
            #pragma unroll
            for (int mf = 0; mf < 2; mf++)
                #pragma unroll
                for (int nf = 0; nf < 4; nf++) MMA16816(acc2[mf][nf], a[mf], b[nf]);
        }
        __syncthreads();      // Bs(W2c) + Cs reads done
        if (nc < 3) {
            #pragma unroll
            for (int j = 0; j < 8; j++) {
                int i = tid + 256 * j;
                int r = i >> 4, c = i & 15;
                *(uint4*)(Bs + r * SA + c * 8) = pf[j];
            }
            __syncthreads();  // Bs = W1c(nc+1)
        }
    }

    // ---------------- epilogue: stage y*gamma in smem, coalesced +x -> out ----
    // Reuse As+Cs region (34816 B) as 64 x 132 fp32 staging (33792 B).
    float* stg = (float*)sm;
    #pragma unroll
    for (int mf = 0; mf < 2; mf++)
        #pragma unroll
        for (int nf = 0; nf < 4; nf++) {
            int n = wn * 32 + nf * 8 + t4 * 2;
            int r0 = wm * 32 + mf * 16 + quad;
            #pragma unroll
            for (int hrow = 0; hrow < 2; hrow++) {
                int r = r0 + hrow * 8;
                stg[r * 132 + n]     = (acc2[mf][nf][hrow * 2]     + sb2[n])     * sgm[n];
                stg[r * 132 + n + 1] = (acc2[mf][nf][hrow * 2 + 1] + sb2[n + 1]) * sgm[n + 1];
            }
        }
    __syncthreads();
    const float4* x4 = (const float4*)(x + m0 * 128);
    float4* o4 = (float4*)(out + m0 * 128);
    #pragma unroll
    for (int j = 0; j < 8; j++) {
        int i = tid + 256 * j;          // 2048 float4s total
        int r = i >> 5, c = i & 31;
        float4 xv = x4[i];
        float4 ov;
        ov.x = stg[r * 132 + c * 4 + 0] + xv.x;
        ov.y = stg[r * 132 + c * 4 + 1] + xv.y;
        ov.z = stg[r * 132 + c * 4 + 2] + xv.z;
        ov.w = stg[r * 132 + c * 4 + 3] + xv.w;
        o4[i] = ov;
    }
}

// ---------------------------------------------------------------------------
extern "C" void kernel_launch(void* const* d_in, const int* in_sizes, int n_in,
                              void* d_out, int out_size) {
    const float* x     = (const float*)d_in[0];
    const float* Wg    = (const float*)d_in[1];
    const float* bg    = (const float*)d_in[2];
    const float* Wh    = (const float*)d_in[3];
    const float* bh    = (const float*)d_in[4];
    const float* gk    = (const float*)d_in[5];
    const float* hk    = (const float*)d_in[6];
    const float* Wo    = (const float*)d_in[7];
    const float* bo    = (const float*)d_in[8];
    const float* lns   = (const float*)d_in[9];
    const float* lnb   = (const float*)d_in[10];
    const float* W1    = (const float*)d_in[11];
    const float* b1    = (const float*)d_in[12];
    const float* W2    = (const float*)d_in[13];
    const float* b2    = (const float*)d_in[14];
    const float* gamma = (const float*)d_in[15];
    float* out = (float*)d_out;

    cudaFuncSetAttribute(k_proj,  cudaFuncAttributeMaxDynamicSharedMemorySize, PROJ_SMEM);
    cudaFuncSetAttribute(k_womlp, cudaFuncAttributeMaxDynamicSharedMemorySize, WM_SMEM);

    k_prep<<<256, 256>>>(Wg, Wh, Wo, W1, W2, gk, hk);
    k_proj<<<NTILES, 256, PROJ_SMEM>>>(x, bg, bh);
    k_conv<<<dim3(4, Bb * Hh, 2), 256>>>();
    k_scan<<<(Bb * Hh * Ww * 32) / 256, 256>>>();
    k_womlp<<<NPTS / 64, 256, WM_SMEM>>>(x, bo, lns, lnb, b1, b2, gamma, out);
}

// round 14
// speedup vs baseline: 1.0651x; 1.0119x over previous
#include <cuda_runtime.h>
#include <cuda_bf16.h>
#include <math.h>
#include <stdint.h>

#define Bb 2
#define Tt 16
#define Hh 56
#define Ww 56
#define Cc 128
#define NPTS (Bb*Tt*Hh*Ww)          /* 100352 */
#define TOT  (NPTS*Cc)              /* 12845056 */
#define HWC  (Hh*Ww*Cc)
#define KTAPS 245
#define NTILES (NPTS/128)           /* 784 */

typedef __nv_bfloat16 bf16;
typedef __nv_bfloat162 bf162;

// ---------------- device scratch (allocation-free) ----------------
__device__ __align__(16) bf16 g_gateP[TOT];
__device__ __align__(16) bf16 g_hidP[TOT];
__device__ __align__(16) bf16 g_gateS[TOT];
__device__ __align__(16) bf16 g_hidS[TOT];
__device__ __align__(16) bf16 g_E[TOT];
__device__ __align__(16) bf16 g_WgT[Cc*Cc];       // [n][k]
__device__ __align__(16) bf16 g_WhT[Cc*Cc];
__device__ __align__(16) bf16 g_WoT[Cc*Cc];
__device__ __align__(16) bf16 g_W1T[512*Cc];      // [n=512][k=128]
__device__ __align__(16) bf16 g_W2T[Cc*512];      // [n=128][k=512]
__device__ __align__(16) bf16 g_kB[2][KTAPS*Cc];  // [tap][c]

// ---------------- helpers ----------------
__device__ __forceinline__ uint32_t smem_u32(const void* p) {
    uint32_t a;
    asm("{ .reg .u64 t; cvta.to.shared.u64 t, %1; cvt.u32.u64 %0, t; }" : "=r"(a) : "l"(p));
    return a;
}
#define LDSM4(r0, r1, r2, r3, a) \
    asm volatile("ldmatrix.sync.aligned.m8n8.x4.shared.b16 {%0,%1,%2,%3}, [%4];" \
        : "=r"(r0), "=r"(r1), "=r"(r2), "=r"(r3) : "r"(a))
#define MMA16816(c, a, b) \
    asm volatile("mma.sync.aligned.m16n8k16.row.col.f32.bf16.bf16.f32 " \
        "{%0,%1,%2,%3},{%4,%5,%6,%7},{%8,%9},{%0,%1,%2,%3};" \
        : "+f"((c)[0]), "+f"((c)[1]), "+f"((c)[2]), "+f"((c)[3]) \
        : "r"((a)[0]), "r"((a)[1]), "r"((a)[2]), "r"((a)[3]), "r"((b)[0]), "r"((b)[1]))
#define CPASYNC16(sma, gp) \
    asm volatile("cp.async.cg.shared.global [%0], [%1], 16;" :: "r"(sma), "l"(gp) : "memory")
#define CPASYNC_COMMIT() asm volatile("cp.async.commit_group;" ::: "memory")
#define CPASYNC_WAIT(n)  asm volatile("cp.async.wait_group %0;" :: "n"(n) : "memory")

__device__ __forceinline__ float tanh_fast(float x) {
    float y;
    asm("tanh.approx.f32 %0, %1;" : "=f"(y) : "f"(x));
    return y;
}
__device__ __forceinline__ float exp_fast(float x) {
    float y;
    asm("ex2.approx.f32 %0, %1;" : "=f"(y) : "f"(x * 1.4426950408889634f));
    return y;
}
__device__ __forceinline__ float rcp_fast(float x) {
    float y;
    asm("rcp.approx.f32 %0, %1;" : "=f"(y) : "f"(x));
    return y;
}

#define SA 136    /* smem row stride (bf16 elems) for 128-col tiles */

// ---------------------------------------------------------------------------
// K0: weight prep
// ---------------------------------------------------------------------------
__global__ void k_prep(const float* __restrict__ Wg, const float* __restrict__ Wh,
                       const float* __restrict__ Wo, const float* __restrict__ W1,
                       const float* __restrict__ W2, const float* __restrict__ gk,
                       const float* __restrict__ hk) {
    int i = blockIdx.x * 256 + threadIdx.x;
    if (i < 16384) {
        int n = i >> 7, k = i & 127;
        g_WgT[i] = __float2bfloat16(Wg[k * 128 + n]);
        g_WhT[i] = __float2bfloat16(Wh[k * 128 + n]);
        g_WoT[i] = __float2bfloat16(Wo[k * 128 + n]);
    }
    if (i < 65536) {
        int n = i >> 7, k = i & 127;
        g_W1T[i] = __float2bfloat16(W1[k * 512 + n]);
        int n2 = i >> 9, k2 = i & 511;
        g_W2T[i] = __float2bfloat16(W2[k2 * 128 + n2]);
    }
    if (i < 2 * KTAPS * 128) {
        int which = i / (KTAPS * 128);
        int j = i - which * (KTAPS * 128);
        int tap = j >> 7, c = j & 127;
        const float* s = which ? hk : gk;
        g_kB[which][j] = __float2bfloat16(s[c * KTAPS + tap]);
    }
}

// ---------------------------------------------------------------------------
// K1: dual projection, 256 threads (8 warps: which x wn(4), 32 cols each)
// ---------------------------------------------------------------------------
#define PROJ_SMEM (3*128*SA*2 + 256*4)
__global__ void __launch_bounds__(256) k_proj(const float* __restrict__ x,
                                              const float* __restrict__ bg,
                                              const float* __restrict__ bh) {
    extern __shared__ __align__(16) char sm[];
    bf16* As = (bf16*)sm;
    bf16* Bs = As + 128 * SA;
    float* sbias = (float*)(Bs + 2 * 128 * SA);
    int tid = threadIdx.x, w = tid >> 5, l = tid & 31;
    size_t m0 = (size_t)blockIdx.x * 128;
    if (tid < 128) sbias[tid] = bg[tid];
    else           sbias[tid] = bh[tid - 128];

    const float2* xs = (const float2*)(x + m0 * 128);
    for (int idx = tid; idx < 128 * 64; idx += 256) {
        int r = idx >> 6, cp = idx & 63;
        float2 v = xs[idx];
        *(bf162*)(As + r * SA + cp * 2) = __floats2bfloat162_rn(v.x, v.y);
    }
    const uint4* wgp = (const uint4*)g_WgT;
    const uint4* whp = (const uint4*)g_WhT;
    for (int idx = tid; idx < 128 * 16; idx += 256) {
        int r = idx >> 4, c = idx & 15;
        *(uint4*)(Bs + r * SA + c * 8) = wgp[idx];
        *(uint4*)(Bs + 128 * SA + r * SA + c * 8) = whp[idx];
    }
    __syncthreads();

    int which = w >> 2;
    int wn0 = (w & 3) * 32;
    uint32_t Abase = smem_u32(As) + ((l & 15) * SA + (l >> 4) * 8) * 2;
    uint32_t Bbase = smem_u32(Bs + which * 128 * SA) + ((l & 15) * SA + (l >> 4) * 8) * 2 + wn0 * SA * 2;
    bf16* outb = which ? g_hidP : g_gateP;
    float* bb = sbias + which * 128;
    int quad = l >> 2, t4 = l & 3;

    for (int mc = 0; mc < 4; mc++) {
        float acc[2][4][4];
        #pragma unroll
        for (int mf = 0; mf < 2; mf++)
            #pragma unroll
            for (int nf = 0; nf < 4; nf++)
                #pragma unroll
                for (int e = 0; e < 4; e++) acc[mf][nf][e] = 0.f;
        #pragma unroll
        for (int k = 0; k < 8; k++) {
            uint32_t a[2][4], b[4][2];
            #pragma unroll
            for (int mf = 0; mf < 2; mf++)
                LDSM4(a[mf][0], a[mf][1], a[mf][2], a[mf][3],
                      Abase + (mc * 32 + mf * 16) * SA * 2 + k * 32);
            #pragma unroll
            for (int nf2 = 0; nf2 < 2; nf2++) {
                uint32_t r0, r1, r2, r3;
                LDSM4(r0, r1, r2, r3, Bbase + nf2 * 16 * SA * 2 + k * 32);
                b[nf2 * 2][0] = r0; b[nf2 * 2][1] = r2;
                b[nf2 * 2 + 1][0] = r1; b[nf2 * 2 + 1][1] = r3;
            }
            #pragma unroll
            for (int mf = 0; mf < 2; mf++)
                #pragma unroll
                for (int nf = 0; nf < 4; nf++) MMA16816(acc[mf][nf], a[mf], b[nf]);
        }
        #pragma unroll
        for (int mf = 0; mf < 2; mf++)
            #pragma unroll
            for (int nf = 0; nf < 4; nf++) {
                int n = wn0 + nf * 8 + t4 * 2;
                int r0 = mc * 32 + mf * 16 + quad;
                *(bf162*)(outb + (m0 + r0) * 128 + n) =
                    __floats2bfloat162_rn(acc[mf][nf][0] + bb[n], acc[mf][nf][1] + bb[n + 1]);
                *(bf162*)(outb + (m0 + r0 + 8) * 128 + n) =
                    __floats2bfloat162_rn(acc[mf][nf][2] + bb[n], acc[mf][nf][3] + bb[n + 1]);
            }
    }
}

// ---------------------------------------------------------------------------
// K2: depthwise circular conv 5x7x7 with t-reuse (round-8 version)
// ---------------------------------------------------------------------------
__global__ void __launch_bounds__(256) k_conv(void) {
    int ct = threadIdx.x & 63;
    int tq = threadIdx.x >> 6;
    int which = blockIdx.z;
    const uint32_t* __restrict__ in = (const uint32_t*)(which ? g_hidP : g_gateP);
    uint32_t* __restrict__ outp = (uint32_t*)(which ? g_hidS : g_gateS);
    const uint32_t* __restrict__ kt = (const uint32_t*)g_kB[which];
    int w0 = blockIdx.x * 14;
    int by = blockIdx.y;
    int h = by % Hh;
    int b = by / Hh;
    int t0 = tq * 4;

    int offs[20];
    #pragma unroll
    for (int j = 0; j < 20; j++) {
        int wi = w0 - 3 + j;
        if (wi < 0)   wi += 56;
        if (wi >= 56) wi -= 56;
        offs[j] = wi * 64;
    }

    bf162 acc[4][14];
    bf162 z = __floats2bfloat162_rn(0.f, 0.f);
    #pragma unroll
    for (int tr = 0; tr < 4; tr++)
        #pragma unroll
        for (int i = 0; i < 14; i++) acc[tr][i] = z;

    for (int kh = 0; kh < 7; kh++) {
        int hin = h - kh + 3;
        if (hin < 0)   hin += 56;
        if (hin >= 56) hin -= 56;
        uint32_t kv[5][7];
        #pragma unroll
        for (int ktp = 0; ktp < 5; ktp++)
            #pragma unroll
            for (int kw = 0; kw < 7; kw++)
                kv[ktp][kw] = kt[(size_t)(ktp * 49 + kh * 7 + kw) * 64 + ct];

        #pragma unroll
        for (int j = 0; j < 8; j++) {
            int t_in = (t0 - 2 + j) & 15;
            const uint32_t* src = in + (size_t)((b * 16 + t_in) * Hh + hin) * (Ww * 64) + ct;
            uint32_t win[20];
            #pragma unroll
            for (int jj = 0; jj < 20; jj++) win[jj] = src[offs[jj]];
            #pragma unroll
            for (int ktp = 0; ktp < 5; ktp++) {
                int tr = j + ktp - 4;
                if (tr >= 0 && tr < 4) {
                    #pragma unroll
                    for (int i = 0; i < 14; i++) {
                        #pragma unroll
                        for (int kw = 0; kw < 7; kw++)
                            acc[tr][i] = __hfma2(*(bf162*)&kv[ktp][kw],
                                                 *(bf162*)&win[i + 6 - kw],
                                                 acc[tr][i]);
                    }
                }
            }
        }
    }
    #pragma unroll
    for (int tr = 0; tr < 4; tr++) {
        uint32_t* dst = outp + (size_t)(((b * 16 + t0 + tr) * Hh + h) * Ww + w0) * 64 + ct;
        #pragma unroll
        for (int i = 0; i < 14; i++)
            dst[(size_t)i * 64] = *(uint32_t*)&acc[tr][i];
    }
}

// ---------------------------------------------------------------------------
// K3: LINEAR-domain Heinsen scan, 4 channels/thread (uint2) for ILP
// ---------------------------------------------------------------------------
__global__ void k_scan(void) {
    int idx = blockIdx.x * 256 + threadIdx.x;
    int cq = idx & 31;
    int rest = idx >> 5;
    int w = rest % 56; rest /= 56;
    int h = rest % 56;
    int b = rest / 56;
    size_t base = (((size_t)(b * Tt) * Hh + h) * Ww + w) * 32 + cq;
    const uint2* gp = (const uint2*)g_gateS;
    const uint2* hp = (const uint2*)g_hidS;
    uint2* ep = (uint2*)g_E;
    float H0 = 0.f, H1 = 0.f, H2 = 0.f, H3 = 0.f;
    #pragma unroll
    for (int t = 0; t < Tt; t++) {
        size_t off = base + (size_t)t * (HWC / 4);
        uint2 gu = gp[off], hu = hp[off];
        float2 gA = __bfloat1622float2(*(bf162*)&gu.x);
        float2 gB = __bfloat1622float2(*(bf162*)&gu.y);
        float2 hA = __bfloat1622float2(*(bf162*)&hu.x);
        float2 hB = __bfloat1622float2(*(bf162*)&hu.y);
        float e0 = exp_fast(-fabsf(gA.x));
        float e1 = exp_fast(-fabsf(gA.y));
        float e2 = exp_fast(-fabsf(gB.x));
        float e3 = exp_fast(-fabsf(gB.y));
        float r0 = rcp_fast(1.f + e0);
        float r1 = rcp_fast(1.f + e1);
        float r2 = rcp_fast(1.f + e2);
        float r3 = rcp_fast(1.f + e3);
        float s0 = (gA.x >= 0.f) ? r0 : e0 * r0;
        float f0 = (gA.x >= 0.f) ? e0 * r0 : r0;
        float s1 = (gA.y >= 0.f) ? r1 : e1 * r1;
        float f1 = (gA.y >= 0.f) ? e1 * r1 : r1;
        float s2 = (gB.x >= 0.f) ? r2 : e2 * r2;
        float f2 = (gB.x >= 0.f) ? e2 * r2 : r2;
        float s3 = (gB.y >= 0.f) ? r3 : e3 * r3;
        float f3 = (gB.y >= 0.f) ? e3 * r3 : r3;
        H0 = fmaf(f0, H0, (hA.x * hA.x + 1e-6f) * s0);
        H1 = fmaf(f1, H1, (hA.y * hA.y + 1e-6f) * s1);
        H2 = fmaf(f2, H2, (hB.x * hB.x + 1e-6f) * s2);
        H3 = fmaf(f3, H3, (hB.y * hB.y + 1e-6f) * s3);
        bf162 oA = __floats2bfloat162_rn(H0, H1);
        bf162 oB = __floats2bfloat162_rn(H2, H3);
        uint2 o;
        o.x = *(uint32_t*)&oA;
        o.y = *(uint32_t*)&oB;
        ep[off] = o;
    }
}

// ---------------------------------------------------------------------------
// K4: womlp-v4: m=64 rows/CTA, 256 threads, 2 CTAs/SM, cp.async double-buffered
// weights (Bs0: Wo/W2 chunks, Bs1: W1 chunks). Group discipline:
// issue order == consume order, <=2 outstanding, wait_group 1 before each
// gemm (0 for the last). Coalesced epilogue retained.
// ---------------------------------------------------------------------------
#define WM_SMEM ((64*SA + 64*SA + 128*SA + 128*SA)*2 + 1792*4)
__global__ void __launch_bounds__(256, 2) k_womlp(const float* __restrict__ x,
                                                  const float* __restrict__ bo,
                                                  const float* __restrict__ lns,
                                                  const float* __restrict__ lnb,
                                                  const float* __restrict__ b1,
                                                  const float* __restrict__ b2,
                                                  const float* __restrict__ gamma,
                                                  float* __restrict__ out) {
    extern __shared__ __align__(16) char sm[];
    bf16* As  = (bf16*)sm;                   // 64 x SA : E tile -> xn tile
    bf16* Cs  = As + 64 * SA;                // 64 x SA : gelu hidden chunk
    bf16* Bs0 = Cs + 64 * SA;                // 128 x SA : Wo / W2 chunks
    bf16* Bs1 = Bs0 + 128 * SA;              // 128 x SA : W1 chunks
    float* sbo  = (float*)(Bs1 + 128 * SA);  // 128
    float* slns = sbo + 128;                 // 128
    float* slnb = slns + 128;                // 128
    float* sb1  = slnb + 128;                // 512
    float* sb2  = sb1 + 512;                 // 128
    float* sgm  = sb2 + 128;                 // 128
    float* rs   = sgm + 128;                 // 64*4
    float* rq   = rs + 256;                  // 64*4
    float2* stat = (float2*)(rq + 256);      // 64

    int tid = threadIdx.x, w = tid >> 5, l = tid & 31;
    int wm = w >> 2, wn = w & 3;
    int quad = l >> 2, t4 = l & 3;
    size_t m0 = (size_t)blockIdx.x * 64;

    const uint4* w1p = (const uint4*)g_W1T;
    const uint4* w2p = (const uint4*)g_W2T;
    uint32_t b0s = smem_u32(Bs0), b1s = smem_u32(Bs1);

    // issue Wo -> Bs0 (group A), W1c0 -> Bs1 (group B)
    #pragma unroll
    for (int j = 0; j < 8; j++) {
        int i = tid + 256 * j;
        int r = i >> 4, c = i & 15;
        CPASYNC16(b0s + (r * SA + c * 8) * 2, (const uint4*)g_WoT + i);
    }
    CPASYNC_COMMIT();
    #pragma unroll
    for (int j = 0; j < 8; j++) {
        int i = tid + 256 * j;
        int r = i >> 4, c = i & 15;
        CPASYNC16(b1s + (r * SA + c * 8) * 2, w1p + i);
    }
    CPASYNC_COMMIT();

    if (tid < 128) {
        sbo[tid] = bo[tid]; slns[tid] = lns[tid]; slnb[tid] = lnb[tid];
        sb2[tid] = b2[tid]; sgm[tid] = gamma[tid];
    }
    sb1[tid] = b1[tid]; sb1[256 + tid] = b1[256 + tid];

    // load E tile (64x128)
    const uint4* ep = (const uint4*)(g_E + m0 * 128);
    #pragma unroll
    for (int j = 0; j < 4; j++) {
        int i = tid + 256 * j;
        int r = i >> 4, c = i & 15;
        *(uint4*)(As + r * SA + c * 8) = ep[i];
    }
    CPASYNC_WAIT(1);      // Wo arrived (W1c0 may be in flight)
    __syncthreads();

    uint32_t Abase  = smem_u32(As)  + ((l & 15) * SA + (l >> 4) * 8) * 2 + (wm * 32) * SA * 2;
    uint32_t Cbase  = smem_u32(Cs)  + ((l & 15) * SA + (l >> 4) * 8) * 2 + (wm * 32) * SA * 2;
    uint32_t B0base = b0s + ((l & 15) * SA + (l >> 4) * 8) * 2 + (wn * 32) * SA * 2;
    uint32_t B1base = b1s + ((l & 15) * SA + (l >> 4) * 8) * 2 + (wn * 32) * SA * 2;

    // ---------------- stage 0: wo GEMM (Bs0) ----------------
    float acc[2][4][4];
    #pragma unroll
    for (int mf = 0; mf < 2; mf++)
        #pragma unroll
        for (int nf = 0; nf < 4; nf++)
            #pragma unroll
            for (int e = 0; e < 4; e++) acc[mf][nf][e] = 0.f;
    #pragma unroll
    for (int k = 0; k < 8; k++) {
        uint32_t a[2][4], b[4][2];
        #pragma unroll
        for (int mf = 0; mf < 2; mf++)
            LDSM4(a[mf][0], a[mf][1], a[mf][2], a[mf][3],
                  Abase + mf * 16 * SA * 2 + k * 32);
        #pragma unroll
        for (int nf2 = 0; nf2 < 2; nf2++) {
            uint32_t r0, r1, r2, r3;
            LDSM4(r0, r1, r2, r3, B0base + nf2 * 16 * SA * 2 + k * 32);
            b[nf2 * 2][0] = r0; b[nf2 * 2][1] = r2;
            b[nf2 * 2 + 1][0] = r1; b[nf2 * 2 + 1][1] = r3;
        }
        #pragma unroll
        for (int mf = 0; mf < 2; mf++)
            #pragma unroll
            for (int nf = 0; nf < 4; nf++) MMA16816(acc[mf][nf], a[mf], b[nf]);
    }

    // bias + per-row partial sums
    #pragma unroll
    for (int mf = 0; mf < 2; mf++) {
        float s0 = 0.f, q0 = 0.f, s1 = 0.f, q1 = 0.f;
        #pragma unroll
        for (int nf = 0; nf < 4; nf++) {
            int n = wn * 32 + nf * 8 + t4 * 2;
            float v0 = acc[mf][nf][0] + sbo[n];
            float v1 = acc[mf][nf][1] + sbo[n + 1];
            float v2 = acc[mf][nf][2] + sbo[n];
            float v3 = acc[mf][nf][3] + sbo[n + 1];
            acc[mf][nf][0] = v0; acc[mf][nf][1] = v1;
            acc[mf][nf][2] = v2; acc[mf][nf][3] = v3;
            s0 += v0 + v1; q0 += v0 * v0 + v1 * v1;
            s1 += v2 + v3; q1 += v2 * v2 + v3 * v3;
        }
        #pragma unroll
        for (int o = 1; o < 4; o <<= 1) {
            s0 += __shfl_xor_sync(0xffffffffu, s0, o);
            q0 += __shfl_xor_sync(0xffffffffu, q0, o);
            s1 += __shfl_xor_sync(0xffffffffu, s1, o);
            q1 += __shfl_xor_sync(0xffffffffu, q1, o);
        }
        if (t4 == 0) {
            int rA = wm * 32 + mf * 16 + quad;
            rs[rA * 4 + wn] = s0; rq[rA * 4 + wn] = q0;
            rs[(rA + 8) * 4 + wn] = s1; rq[(rA + 8) * 4 + wn] = q1;
        }
    }
    __syncthreads();      // gemm0 Bs0 reads done + rs/rq visible

    // issue W2c0 -> Bs0 (group C) — Bs0 now free
    #pragma unroll
    for (int j = 0; j < 8; j++) {
        int i = tid + 256 * j;
        int r = i >> 4, c = i & 15;
        CPASYNC16(b0s + (r * SA + c * 8) * 2, w2p + (size_t)r * 64 + c);
    }
    CPASYNC_COMMIT();

    if (tid < 64) {
        float mean = (rs[tid * 4] + rs[tid * 4 + 1] + rs[tid * 4 + 2] + rs[tid * 4 + 3]) * (1.f / 128.f);
        float var = (rq[tid * 4] + rq[tid * 4 + 1] + rq[tid * 4 + 2] + rq[tid * 4 + 3]) * (1.f / 128.f) - mean * mean;
        stat[tid] = make_float2(mean, rsqrtf(var + 1e-6f));
    }
    __syncthreads();

    // write xn (bf16) into As
    #pragma unroll
    for (int mf = 0; mf < 2; mf++) {
        int rA = wm * 32 + mf * 16 + quad;
        float2 stA = stat[rA], stB = stat[rA + 8];
        #pragma unroll
        for (int nf = 0; nf < 4; nf++) {
            int n = wn * 32 + nf * 8 + t4 * 2;
            float x0 = (acc[mf][nf][0] - stA.x) * stA.y * slns[n] + slnb[n];
            float x1 = (acc[mf][nf][1] - stA.x) * stA.y * slns[n + 1] + slnb[n + 1];
            float x2 = (acc[mf][nf][2] - stB.x) * stB.y * slns[n] + slnb[n];
            float x3 = (acc[mf][nf][3] - stB.x) * stB.y * slns[n + 1] + slnb[n + 1];
            *(bf162*)(As + rA * SA + n) = __floats2bfloat162_rn(x0, x1);
            *(bf162*)(As + (rA + 8) * SA + n) = __floats2bfloat162_rn(x2, x3);
        }
    }
    __syncthreads();      // xn visible

    // ---------------- fused MLP: cp.async pipelined chunks ------------------
    float acc2[2][4][4];
    #pragma unroll
    for (int mf = 0; mf < 2; mf++)
        #pragma unroll
        for (int nf = 0; nf < 4; nf++)
            #pragma unroll
            for (int e = 0; e < 4; e++) acc2[mf][nf][e] = 0.f;

    for (int nc = 0; nc < 4; nc++) {
        // --- gemm1: xn @ W1c_nc (Bs1). Its group is 2nd-newest -> wait 1. ---
        CPASYNC_WAIT(1);
        __syncthreads();
        float a1[2][4][4];
        #pragma unroll
        for (int mf = 0; mf < 2; mf++)
            #pragma unroll
            for (int nf = 0; nf < 4; nf++)
                #pragma unroll
                for (int e = 0; e < 4; e++) a1[mf][nf][e] = 0.f;
        #pragma unroll
        for (int k = 0; k < 8; k++) {
            uint32_t a[2][4], b[4][2];
            #pragma unroll
            for (int mf = 0; mf < 2; mf++)
                LDSM4(a[mf][0], a[mf][1], a[mf][2], a[mf][3],
                      Abase + mf * 16 * SA * 2 + k * 32);
            #pragma unroll
            for (int nf2 = 0; nf2 < 2; nf2++) {
                uint32_t r0, r1, r2, r3;
                LDSM4(r0, r1, r2, r3, B1base + nf2 * 16 * SA * 2 + k * 32);
                b[nf2 * 2][0] = r0; b[nf2 * 2][1] = r2;
                b[nf2 * 2 + 1][0] = r1; b[nf2 * 2 + 1][1] = r3;
            }
            #pragma unroll
            for (int mf = 0; mf < 2; mf++)
                #pragma unroll
                for (int nf = 0; nf < 4; nf++) MMA16816(a1[mf][nf], a[mf], b[nf]);
        }
        // gelu -> Cs
        #pragma unroll
        for (int mf = 0; mf < 2; mf++)
            #pragma unroll
            for (int nf = 0; nf < 4; nf++) {
                int nl = wn * 32 + nf * 8 + t4 * 2;
                int ng = nc * 128 + nl;
                int r0 = wm * 32 + mf * 16 + quad;
                #pragma unroll
                for (int hrow = 0; hrow < 2; hrow++) {
                    float v0 = a1[mf][nf][hrow * 2] + sb1[ng];
                    float v1 = a1[mf][nf][hrow * 2 + 1] + sb1[ng + 1];
                    float t0 = tanh_fast(0.7978845608028654f * (v0 + 0.044715f * v0 * v0 * v0));
                    float t1 = tanh_fast(0.7978845608028654f * (v1 + 0.044715f * v1 * v1 * v1));
                    *(bf162*)(Cs + (r0 + hrow * 8) * SA + nl) =
                        __floats2bfloat162_rn(0.5f * v0 * (1.f + t0), 0.5f * v1 * (1.f + t1));
                }
            }
        __syncthreads();      // Bs1 reads done + Cs written
        if (nc < 3) {
            // issue W1c(nc+1) -> Bs1
            #pragma unroll
            for (int j = 0; j < 8; j++) {
                int i = tid + 256 * j;
                int r = i >> 4, c = i & 15;
                CPASYNC16(b1s + (r * SA + c * 8) * 2, w1p + (nc + 1) * 2048 + i);
            }
            CPASYNC_COMMIT();
        }

        // --- gemm2: Cs @ W2c_nc (Bs0), accumulate ---
        if (nc < 3) CPASYNC_WAIT(1);
        else        CPASYNC_WAIT(0);
        __syncthreads();
        #pragma unroll
        for (int k = 0; k < 8; k++) {
            uint32_t a[2][4], b[4][2];
            #pragma unroll
            for (int mf = 0; mf < 2; mf++)
                LDSM4(a[mf][0], a[mf][1], a[mf][2], a[mf][3],
                      Cbase + mf * 16 * SA * 2 + k * 32);
            #pragma unroll
            for (int nf2 = 0; nf2 < 2; nf2++) {
                uint32_t r0, r1, r2, r3;
                LDSM4(r0, r1, r2, r3, B0base + nf2 * 16 * SA * 2 + k * 32);
                b[nf2 * 2][0] = r0; b[nf2 * 2][1] = r2;
                b[nf2 * 2 + 1][0] = r1; b[nf2 * 2 + 1][1] = r3;
            }
            #pragma unroll
            for (int mf = 0; mf < 2; mf++)
                #pragma unroll
                for (int nf = 0; nf < 4; nf++) MMA16816(acc2[mf][nf], a[mf], b[nf]);
        }
        __syncthreads();      // Bs0 + Cs reads done
        if (nc < 3) {
            // issue W2c(nc+1) -> Bs0
            #pragma unroll
            for (int j = 0; j < 8; j++) {
                int i = tid + 256 * j;
                int r = i >> 4, c = i & 15;
                CPASYNC16(b0s + (r * SA + c * 8) * 2, w2p + (size_t)r * 64 + (nc + 1) * 16 + c);
            }
            CPASYNC_COMMIT();
        }
    }

    // ---------------- epilogue: stage y*gamma in smem, coalesced +x -> out ----
    float* stg = (float*)sm;     // reuse As+Cs region (64 x 132 fp32)
    #pragma unroll
    for (int mf = 0; mf < 2; mf++)
        #pragma unroll
        for (int nf = 0; nf < 4; nf++) {
            int n = wn * 32 + nf * 8 + t4 * 2;
            int r0 = wm * 32 + mf * 16 + quad;
            #pragma unroll
            for (int hrow = 0; hrow < 2; hrow++) {
                int r = r0 + hrow * 8;
                stg[r * 132 + n]     = (acc2[mf][nf][hrow * 2]     + sb2[n])     * sgm[n];
                stg[r * 132 + n + 1] = (acc2[mf][nf][hrow * 2 + 1] + sb2[n + 1]) * sgm[n + 1];
            }
        }
    __syncthreads();
    const float4* x4 = (const float4*)(x + m0 * 128);
    float4* o4 = (float4*)(out + m0 * 128);
    #pragma unroll
    for (int j = 0; j < 8; j++) {
        int i = tid + 256 * j;
        int r = i >> 5, c = i & 31;
        float4 xv = x4[i];
        float4 ov;
        ov.x = stg[r * 132 + c * 4 + 0] + xv.x;
        ov.y = stg[r * 132 + c * 4 + 1] + xv.y;
        ov.z = stg[r * 132 + c * 4 + 2] + xv.z;
        ov.w = stg[r * 132 + c * 4 + 3] + xv.w;
        o4[i] = ov;
    }
}

// ---------------------------------------------------------------------------
extern "C" void kernel_launch(void* const* d_in, const int* in_sizes, int n_in,
                              void* d_out, int out_size) {
    const float* x     = (const float*)d_in[0];
    const float* Wg    = (const float*)d_in[1];
    const float* bg    = (const float*)d_in[2];
    const float* Wh    = (const float*)d_in[3];
    const float* bh    = (const float*)d_in[4];
    const float* gk    = (const float*)d_in[5];
    const float* hk    = (const float*)d_in[6];
    const float* Wo    = (const float*)d_in[7];
    const float* bo    = (const float*)d_in[8];
    const float* lns   = (const float*)d_in[9];
    const float* lnb   = (const float*)d_in[10];
    const float* W1    = (const float*)d_in[11];
    const float* b1    = (const float*)d_in[12];
    const float* W2    = (const float*)d_in[13];
    const float* b2    = (const float*)d_in[14];
    const float* gamma = (const float*)d_in[15];
    float* out = (float*)d_out;

    cudaFuncSetAttribute(k_proj,  cudaFuncAttributeMaxDynamicSharedMemorySize, PROJ_SMEM);
    cudaFuncSetAttribute(k_womlp, cudaFuncAttributeMaxDynamicSharedMemorySize, WM_SMEM);

    k_prep<<<256, 256>>>(Wg, Wh, Wo, W1, W2, gk, hk);
    k_proj<<<NTILES, 256, PROJ_SMEM>>>(x, bg, bh);
    k_conv<<<dim3(4, Bb * Hh, 2), 256>>>();
    k_scan<<<(Bb * Hh * Ww * 32) / 256, 256>>>();
    k_womlp<<<NPTS / 64, 256, WM_SMEM>>>(x, bo, lns, lnb, b1, b2, gamma, out);
}

// round 15
// speedup vs baseline: 1.0681x; 1.0028x over previous
#include <cuda_runtime.h>
#include <cuda_bf16.h>
#include <math.h>
#include <stdint.h>

#define Bb 2
#define Tt 16
#define Hh 56
#define Ww 56
#define Cc 128
#define NPTS (Bb*Tt*Hh*Ww)          /* 100352 */
#define TOT  (NPTS*Cc)              /* 12845056 */
#define HWC  (Hh*Ww*Cc)
#define KTAPS 245
#define NTILES (NPTS/128)           /* 784 */

typedef __nv_bfloat16 bf16;
typedef __nv_bfloat162 bf162;

// ---------------- device scratch (allocation-free) ----------------
__device__ __align__(16) bf16 g_gateP[TOT];
__device__ __align__(16) bf16 g_hidP[TOT];
__device__ __align__(16) bf16 g_gateS[TOT];
__device__ __align__(16) bf16 g_hidS[TOT];
__device__ __align__(16) bf16 g_E[TOT];
__device__ __align__(16) bf16 g_WgT[Cc*Cc];       // [n][k]
__device__ __align__(16) bf16 g_WhT[Cc*Cc];
__device__ __align__(16) bf16 g_WoT[Cc*Cc];
__device__ __align__(16) bf16 g_W1T[512*Cc];      // [n=512][k=128]
__device__ __align__(16) bf16 g_W2T[Cc*512];      // [n=128][k=512]
__device__ __align__(16) bf16 g_kB[2][KTAPS*Cc];  // [tap][c]

// ---------------- helpers ----------------
__device__ __forceinline__ uint32_t smem_u32(const void* p) {
    uint32_t a;
    asm("{ .reg .u64 t; cvta.to.shared.u64 t, %1; cvt.u32.u64 %0, t; }" : "=r"(a) : "l"(p));
    return a;
}
#define LDSM4(r0, r1, r2, r3, a) \
    asm volatile("ldmatrix.sync.aligned.m8n8.x4.shared.b16 {%0,%1,%2,%3}, [%4];" \
        : "=r"(r0), "=r"(r1), "=r"(r2), "=r"(r3) : "r"(a))
#define MMA16816(c, a, b) \
    asm volatile("mma.sync.aligned.m16n8k16.row.col.f32.bf16.bf16.f32 " \
        "{%0,%1,%2,%3},{%4,%5,%6,%7},{%8,%9},{%0,%1,%2,%3};" \
        : "+f"((c)[0]), "+f"((c)[1]), "+f"((c)[2]), "+f"((c)[3]) \
        : "r"((a)[0]), "r"((a)[1]), "r"((a)[2]), "r"((a)[3]), "r"((b)[0]), "r"((b)[1]))
#define CPASYNC16(sma, gp) \
    asm volatile("cp.async.cg.shared.global [%0], [%1], 16;" :: "r"(sma), "l"(gp) : "memory")
#define CPASYNC_COMMIT() asm volatile("cp.async.commit_group;" ::: "memory")
#define CPASYNC_WAIT(n)  asm volatile("cp.async.wait_group %0;" :: "n"(n) : "memory")

__device__ __forceinline__ float tanh_fast(float x) {
    float y;
    asm("tanh.approx.f32 %0, %1;" : "=f"(y) : "f"(x));
    return y;
}
__device__ __forceinline__ float exp_fast(float x) {
    float y;
    asm("ex2.approx.f32 %0, %1;" : "=f"(y) : "f"(x * 1.4426950408889634f));
    return y;
}
__device__ __forceinline__ float rcp_fast(float x) {
    float y;
    asm("rcp.approx.f32 %0, %1;" : "=f"(y) : "f"(x));
    return y;
}

#define SA 136    /* smem row stride (bf16 elems) for 128-col tiles */

// ---------------------------------------------------------------------------
// K0: weight prep
// ---------------------------------------------------------------------------
__global__ void k_prep(const float* __restrict__ Wg, const float* __restrict__ Wh,
                       const float* __restrict__ Wo, const float* __restrict__ W1,
                       const float* __restrict__ W2, const float* __restrict__ gk,
                       const float* __restrict__ hk) {
    int i = blockIdx.x * 256 + threadIdx.x;
    if (i < 16384) {
        int n = i >> 7, k = i & 127;
        g_WgT[i] = __float2bfloat16(Wg[k * 128 + n]);
        g_WhT[i] = __float2bfloat16(Wh[k * 128 + n]);
        g_WoT[i] = __float2bfloat16(Wo[k * 128 + n]);
    }
    if (i < 65536) {
        int n = i >> 7, k = i & 127;
        g_W1T[i] = __float2bfloat16(W1[k * 512 + n]);
        int n2 = i >> 9, k2 = i & 511;
        g_W2T[i] = __float2bfloat16(W2[k2 * 128 + n2]);
    }
    if (i < 2 * KTAPS * 128) {
        int which = i / (KTAPS * 128);
        int j = i - which * (KTAPS * 128);
        int tap = j >> 7, c = j & 127;
        const float* s = which ? hk : gk;
        g_kB[which][j] = __float2bfloat16(s[c * KTAPS + tap]);
    }
}

// ---------------------------------------------------------------------------
// K1: dual projection, 256 threads; Wg/Wh via cp.async overlapped with
// the fp32->bf16 x conversion.
// ---------------------------------------------------------------------------
#define PROJ_SMEM (3*128*SA*2 + 256*4)
__global__ void __launch_bounds__(256) k_proj(const float* __restrict__ x,
                                              const float* __restrict__ bg,
                                              const float* __restrict__ bh) {
    extern __shared__ __align__(16) char sm[];
    bf16* As = (bf16*)sm;
    bf16* Bs = As + 128 * SA;
    float* sbias = (float*)(Bs + 2 * 128 * SA);
    int tid = threadIdx.x, w = tid >> 5, l = tid & 31;
    size_t m0 = (size_t)blockIdx.x * 128;

    // issue Wg/Wh copies first (one group)
    {
        uint32_t bs = smem_u32(Bs);
        const uint4* wgp = (const uint4*)g_WgT;
        const uint4* whp = (const uint4*)g_WhT;
        #pragma unroll
        for (int j = 0; j < 8; j++) {
            int i = tid + 256 * j;
            int r = i >> 4, c = i & 15;
            CPASYNC16(bs + (r * SA + c * 8) * 2, wgp + i);
            CPASYNC16(bs + (128 * SA + r * SA + c * 8) * 2, whp + i);
        }
        CPASYNC_COMMIT();
    }

    if (tid < 128) sbias[tid] = bg[tid];
    else           sbias[tid] = bh[tid - 128];

    const float2* xs = (const float2*)(x + m0 * 128);
    for (int idx = tid; idx < 128 * 64; idx += 256) {
        int r = idx >> 6, cp = idx & 63;
        float2 v = xs[idx];
        *(bf162*)(As + r * SA + cp * 2) = __floats2bfloat162_rn(v.x, v.y);
    }
    CPASYNC_WAIT(0);
    __syncthreads();

    int which = w >> 2;
    int wn0 = (w & 3) * 32;
    uint32_t Abase = smem_u32(As) + ((l & 15) * SA + (l >> 4) * 8) * 2;
    uint32_t Bbase = smem_u32(Bs + which * 128 * SA) + ((l & 15) * SA + (l >> 4) * 8) * 2 + wn0 * SA * 2;
    bf16* outb = which ? g_hidP : g_gateP;
    float* bb = sbias + which * 128;
    int quad = l >> 2, t4 = l & 3;

    for (int mc = 0; mc < 4; mc++) {
        float acc[2][4][4];
        #pragma unroll
        for (int mf = 0; mf < 2; mf++)
            #pragma unroll
            for (int nf = 0; nf < 4; nf++)
                #pragma unroll
                for (int e = 0; e < 4; e++) acc[mf][nf][e] = 0.f;
        #pragma unroll
        for (int k = 0; k < 8; k++) {
            uint32_t a[2][4], b[4][2];
            #pragma unroll
            for (int mf = 0; mf < 2; mf++)
                LDSM4(a[mf][0], a[mf][1], a[mf][2], a[mf][3],
                      Abase + (mc * 32 + mf * 16) * SA * 2 + k * 32);
            #pragma unroll
            for (int nf2 = 0; nf2 < 2; nf2++) {
                uint32_t r0, r1, r2, r3;
                LDSM4(r0, r1, r2, r3, Bbase + nf2 * 16 * SA * 2 + k * 32);
                b[nf2 * 2][0] = r0; b[nf2 * 2][1] = r2;
                b[nf2 * 2 + 1][0] = r1; b[nf2 * 2 + 1][1] = r3;
            }
            #pragma unroll
            for (int mf = 0; mf < 2; mf++)
                #pragma unroll
                for (int nf = 0; nf < 4; nf++) MMA16816(acc[mf][nf], a[mf], b[nf]);
        }
        #pragma unroll
        for (int mf = 0; mf < 2; mf++)
            #pragma unroll
            for (int nf = 0; nf < 4; nf++) {
                int n = wn0 + nf * 8 + t4 * 2;
                int r0 = mc * 32 + mf * 16 + quad;
                *(bf162*)(outb + (m0 + r0) * 128 + n) =
                    __floats2bfloat162_rn(acc[mf][nf][0] + bb[n], acc[mf][nf][1] + bb[n + 1]);
                *(bf162*)(outb + (m0 + r0 + 8) * 128 + n) =
                    __floats2bfloat162_rn(acc[mf][nf][2] + bb[n], acc[mf][nf][3] + bb[n + 1]);
            }
    }
}

// ---------------------------------------------------------------------------
// K2: depthwise circular conv 5x7x7 with t-reuse (round-8 version)
// ---------------------------------------------------------------------------
__global__ void __launch_bounds__(256) k_conv(void) {
    int ct = threadIdx.x & 63;
    int tq = threadIdx.x >> 6;
    int which = blockIdx.z;
    const uint32_t* __restrict__ in = (const uint32_t*)(which ? g_hidP : g_gateP);
    uint32_t* __restrict__ outp = (uint32_t*)(which ? g_hidS : g_gateS);
    const uint32_t* __restrict__ kt = (const uint32_t*)g_kB[which];
    int w0 = blockIdx.x * 14;
    int by = blockIdx.y;
    int h = by % Hh;
    int b = by / Hh;
    int t0 = tq * 4;

    int offs[20];
    #pragma unroll
    for (int j = 0; j < 20; j++) {
        int wi = w0 - 3 + j;
        if (wi < 0)   wi += 56;
        if (wi >= 56) wi -= 56;
        offs[j] = wi * 64;
    }

    bf162 acc[4][14];
    bf162 z = __floats2bfloat162_rn(0.f, 0.f);
    #pragma unroll
    for (int tr = 0; tr < 4; tr++)
        #pragma unroll
        for (int i = 0; i < 14; i++) acc[tr][i] = z;

    for (int kh = 0; kh < 7; kh++) {
        int hin = h - kh + 3;
        if (hin < 0)   hin += 56;
        if (hin >= 56) hin -= 56;
        uint32_t kv[5][7];
        #pragma unroll
        for (int ktp = 0; ktp < 5; ktp++)
            #pragma unroll
            for (int kw = 0; kw < 7; kw++)
                kv[ktp][kw] = kt[(size_t)(ktp * 49 + kh * 7 + kw) * 64 + ct];

        #pragma unroll
        for (int j = 0; j < 8; j++) {
            int t_in = (t0 - 2 + j) & 15;
            const uint32_t* src = in + (size_t)((b * 16 + t_in) * Hh + hin) * (Ww * 64) + ct;
            uint32_t win[20];
            #pragma unroll
            for (int jj = 0; jj < 20; jj++) win[jj] = src[offs[jj]];
            #pragma unroll
            for (int ktp = 0; ktp < 5; ktp++) {
                int tr = j + ktp - 4;
                if (tr >= 0 && tr < 4) {
                    #pragma unroll
                    for (int i = 0; i < 14; i++) {
                        #pragma unroll
                        for (int kw = 0; kw < 7; kw++)
                            acc[tr][i] = __hfma2(*(bf162*)&kv[ktp][kw],
                                                 *(bf162*)&win[i + 6 - kw],
                                                 acc[tr][i]);
                    }
                }
            }
        }
    }
    #pragma unroll
    for (int tr = 0; tr < 4; tr++) {
        uint32_t* dst = outp + (size_t)(((b * 16 + t0 + tr) * Hh + h) * Ww + w0) * 64 + ct;
        #pragma unroll
        for (int i = 0; i < 14; i++)
            dst[(size_t)i * 64] = *(uint32_t*)&acc[tr][i];
    }
}

// ---------------------------------------------------------------------------
// K3: LINEAR-domain Heinsen scan, 4 channels/thread (uint2) for ILP
// ---------------------------------------------------------------------------
__global__ void k_scan(void) {
    int idx = blockIdx.x * 256 + threadIdx.x;
    int cq = idx & 31;
    int rest = idx >> 5;
    int w = rest % 56; rest /= 56;
    int h = rest % 56;
    int b = rest / 56;
    size_t base = (((size_t)(b * Tt) * Hh + h) * Ww + w) * 32 + cq;
    const uint2* gp = (const uint2*)g_gateS;
    const uint2* hp = (const uint2*)g_hidS;
    uint2* ep = (uint2*)g_E;
    float H0 = 0.f, H1 = 0.f, H2 = 0.f, H3 = 0.f;
    #pragma unroll
    for (int t = 0; t < Tt; t++) {
        size_t off = base + (size_t)t * (HWC / 4);
        uint2 gu = gp[off], hu = hp[off];
        float2 gA = __bfloat1622float2(*(bf162*)&gu.x);
        float2 gB = __bfloat1622float2(*(bf162*)&gu.y);
        float2 hA = __bfloat1622float2(*(bf162*)&hu.x);
        float2 hB = __bfloat1622float2(*(bf162*)&hu.y);
        float e0 = exp_fast(-fabsf(gA.x));
        float e1 = exp_fast(-fabsf(gA.y));
        float e2 = exp_fast(-fabsf(gB.x));
        float e3 = exp_fast(-fabsf(gB.y));
        float r0 = rcp_fast(1.f + e0);
        float r1 = rcp_fast(1.f + e1);
        float r2 = rcp_fast(1.f + e2);
        float r3 = rcp_fast(1.f + e3);
        float s0 = (gA.x >= 0.f) ? r0 : e0 * r0;
        float f0 = (gA.x >= 0.f) ? e0 * r0 : r0;
        float s1 = (gA.y >= 0.f) ? r1 : e1 * r1;
        float f1 = (gA.y >= 0.f) ? e1 * r1 : r1;
        float s2 = (gB.x >= 0.f) ? r2 : e2 * r2;
        float f2 = (gB.x >= 0.f) ? e2 * r2 : r2;
        float s3 = (gB.y >= 0.f) ? r3 : e3 * r3;
        float f3 = (gB.y >= 0.f) ? e3 * r3 : r3;
        H0 = fmaf(f0, H0, (hA.x * hA.x + 1e-6f) * s0);
        H1 = fmaf(f1, H1, (hA.y * hA.y + 1e-6f) * s1);
        H2 = fmaf(f2, H2, (hB.x * hB.x + 1e-6f) * s2);
        H3 = fmaf(f3, H3, (hB.y * hB.y + 1e-6f) * s3);
        bf162 oA = __floats2bfloat162_rn(H0, H1);
        bf162 oB = __floats2bfloat162_rn(H2, H3);
        uint2 o;
        o.x = *(uint32_t*)&oA;
        o.y = *(uint32_t*)&oB;
        ep[off] = o;
    }
}

// ---------------------------------------------------------------------------
// K4: womlp-v5: cp.async for E tile + weights, x-prefetch epilogue.
// ---------------------------------------------------------------------------
#define WM_SMEM ((64*SA + 64*SA + 128*SA + 128*SA)*2 + 1792*4)
__global__ void __launch_bounds__(256, 2) k_womlp(const float* __restrict__ x,
                                                  const float* __restrict__ bo,
                                                  const float* __restrict__ lns,
                                                  const float* __restrict__ lnb,
                                                  const float* __restrict__ b1,
                                                  const float* __restrict__ b2,
                                                  const float* __restrict__ gamma,
                                                  float* __restrict__ out) {
    extern __shared__ __align__(16) char sm[];
    bf16* As  = (bf16*)sm;                   // 64 x SA : E tile -> xn tile
    bf16* Cs  = As + 64 * SA;                // 64 x SA : gelu hidden chunk
    bf16* Bs0 = Cs + 64 * SA;                // 128 x SA : Wo / W2 chunks
    bf16* Bs1 = Bs0 + 128 * SA;              // 128 x SA : W1 chunks
    float* sbo  = (float*)(Bs1 + 128 * SA);
    float* slns = sbo + 128;
    float* slnb = slns + 128;
    float* sb1  = slnb + 128;
    float* sb2  = sb1 + 512;
    float* sgm  = sb2 + 128;
    float* rs   = sgm + 128;
    float* rq   = rs + 256;
    float2* stat = (float2*)(rq + 256);

    int tid = threadIdx.x, w = tid >> 5, l = tid & 31;
    int wm = w >> 2, wn = w & 3;
    int quad = l >> 2, t4 = l & 3;
    size_t m0 = (size_t)blockIdx.x * 64;

    const uint4* w1p = (const uint4*)g_W1T;
    const uint4* w2p = (const uint4*)g_W2T;
    uint32_t b0s = smem_u32(Bs0), b1s = smem_u32(Bs1), as_ = smem_u32(As);

    // group A: E tile + Wo ; group B: W1c0
    {
        const uint4* ep = (const uint4*)(g_E + m0 * 128);
        #pragma unroll
        for (int j = 0; j < 4; j++) {
            int i = tid + 256 * j;
            int r = i >> 4, c = i & 15;
            CPASYNC16(as_ + (r * SA + c * 8) * 2, ep + i);
        }
        const uint4* wop = (const uint4*)g_WoT;
        #pragma unroll
        for (int j = 0; j < 8; j++) {
            int i = tid + 256 * j;
            int r = i >> 4, c = i & 15;
            CPASYNC16(b0s + (r * SA + c * 8) * 2, wop + i);
        }
        CPASYNC_COMMIT();
        #pragma unroll
        for (int j = 0; j < 8; j++) {
            int i = tid + 256 * j;
            int r = i >> 4, c = i & 15;
            CPASYNC16(b1s + (r * SA + c * 8) * 2, w1p + i);
        }
        CPASYNC_COMMIT();
    }

    if (tid < 128) {
        sbo[tid] = bo[tid]; slns[tid] = lns[tid]; slnb[tid] = lnb[tid];
        sb2[tid] = b2[tid]; sgm[tid] = gamma[tid];
    }
    sb1[tid] = b1[tid]; sb1[256 + tid] = b1[256 + tid];

    CPASYNC_WAIT(1);      // E + Wo arrived (W1c0 may be in flight)
    __syncthreads();

    uint32_t Abase  = as_ + ((l & 15) * SA + (l >> 4) * 8) * 2 + (wm * 32) * SA * 2;
    uint32_t Cbase  = smem_u32(Cs) + ((l & 15) * SA + (l >> 4) * 8) * 2 + (wm * 32) * SA * 2;
    uint32_t B0base = b0s + ((l & 15) * SA + (l >> 4) * 8) * 2 + (wn * 32) * SA * 2;
    uint32_t B1base = b1s + ((l & 15) * SA + (l >> 4) * 8) * 2 + (wn * 32) * SA * 2;

    // ---------------- stage 0: wo GEMM (Bs0) ----------------
    float acc[2][4][4];
    #pragma unroll
    for (int mf = 0; mf < 2; mf++)
        #pragma unroll
        for (int nf = 0; nf < 4; nf++)
            #pragma unroll
            for (int e = 0; e < 4; e++) acc[mf][nf][e] = 0.f;
    #pragma unroll
    for (int k = 0; k < 8; k++) {
        uint32_t a[2][4], b[4][2];
        #pragma unroll
        for (int mf = 0; mf < 2; mf++)
            LDSM4(a[mf][0], a[mf][1], a[mf][2], a[mf][3],
                  Abase + mf * 16 * SA * 2 + k * 32);
        #pragma unroll
        for (int nf2 = 0; nf2 < 2; nf2++) {
            uint32_t r0, r1, r2, r3;
            LDSM4(r0, r1, r2, r3, B0base + nf2 * 16 * SA * 2 + k * 32);
            b[nf2 * 2][0] = r0; b[nf2 * 2][1] = r2;
            b[nf2 * 2 + 1][0] = r1; b[nf2 * 2 + 1][1] = r3;
        }
        #pragma unroll
        for (int mf = 0; mf < 2; mf++)
            #pragma unroll
            for (int nf = 0; nf < 4; nf++) MMA16816(acc[mf][nf], a[mf], b[nf]);
    }

    // bias + per-row partial sums
    #pragma unroll
    for (int mf = 0; mf < 2; mf++) {
        float s0 = 0.f, q0 = 0.f, s1 = 0.f, q1 = 0.f;
        #pragma unroll
        for (int nf = 0; nf < 4; nf++) {
            int n = wn * 32 + nf * 8 + t4 * 2;
            float v0 = acc[mf][nf][0] + sbo[n];
            float v1 = acc[mf][nf][1] + sbo[n + 1];
            float v2 = acc[mf][nf][2] + sbo[n];
            float v3 = acc[mf][nf][3] + sbo[n + 1];
            acc[mf][nf][0] = v0; acc[mf][nf][1] = v1;
            acc[mf][nf][2] = v2; acc[mf][nf][3] = v3;
            s0 += v0 + v1; q0 += v0 * v0 + v1 * v1;
            s1 += v2 + v3; q1 += v2 * v2 + v3 * v3;
        }
        #pragma unroll
        for (int o = 1; o < 4; o <<= 1) {
            s0 += __shfl_xor_sync(0xffffffffu, s0, o);
            q0 += __shfl_xor_sync(0xffffffffu, q0, o);
            s1 += __shfl_xor_sync(0xffffffffu, s1, o);
            q1 += __shfl_xor_sync(0xffffffffu, q1, o);
        }
        if (t4 == 0) {
            int rA = wm * 32 + mf * 16 + quad;
            rs[rA * 4 + wn] = s0; rq[rA * 4 + wn] = q0;
            rs[(rA + 8) * 4 + wn] = s1; rq[(rA + 8) * 4 + wn] = q1;
        }
    }
    __syncthreads();      // gemm0 Bs0 reads done + rs/rq visible

    // issue W2c0 -> Bs0 (group C)
    #pragma unroll
    for (int j = 0; j < 8; j++) {
        int i = tid + 256 * j;
        int r = i >> 4, c = i & 15;
        CPASYNC16(b0s + (r * SA + c * 8) * 2, w2p + (size_t)r * 64 + c);
    }
    CPASYNC_COMMIT();

    if (tid < 64) {
        float mean = (rs[tid * 4] + rs[tid * 4 + 1] + rs[tid * 4 + 2] + rs[tid * 4 + 3]) * (1.f / 128.f);
        float var = (rq[tid * 4] + rq[tid * 4 + 1] + rq[tid * 4 + 2] + rq[tid * 4 + 3]) * (1.f / 128.f) - mean * mean;
        stat[tid] = make_float2(mean, rsqrtf(var + 1e-6f));
    }
    __syncthreads();

    // write xn (bf16) into As
    #pragma unroll
    for (int mf = 0; mf < 2; mf++) {
        int rA = wm * 32 + mf * 16 + quad;
        float2 stA = stat[rA], stB = stat[rA + 8];
        #pragma unroll
        for (int nf = 0; nf < 4; nf++) {
            int n = wn * 32 + nf * 8 + t4 * 2;
            float x0 = (acc[mf][nf][0] - stA.x) * stA.y * slns[n] + slnb[n];
            float x1 = (acc[mf][nf][1] - stA.x) * stA.y * slns[n + 1] + slnb[n + 1];
            float x2 = (acc[mf][nf][2] - stB.x) * stB.y * slns[n] + slnb[n];
            float x3 = (acc[mf][nf][3] - stB.x) * stB.y * slns[n + 1] + slnb[n + 1];
            *(bf162*)(As + rA * SA + n) = __floats2bfloat162_rn(x0, x1);
            *(bf162*)(As + (rA + 8) * SA + n) = __floats2bfloat162_rn(x2, x3);
        }
    }
    __syncthreads();      // xn visible

    // ---------------- fused MLP: cp.async pipelined chunks ------------------
    float acc2[2][4][4];
    #pragma unroll
    for (int mf = 0; mf < 2; mf++)
        #pragma unroll
        for (int nf = 0; nf < 4; nf++)
            #pragma unroll
            for (int e = 0; e < 4; e++) acc2[mf][nf][e] = 0.f;

    for (int nc = 0; nc < 4; nc++) {
        // --- gemm1: xn @ W1c_nc (Bs1) ---
        CPASYNC_WAIT(1);
        __syncthreads();
        float a1[2][4][4];
        #pragma unroll
        for (int mf = 0; mf < 2; mf++)
            #pragma unroll
            for (int nf = 0; nf < 4; nf++)
                #pragma unroll
                for (int e = 0; e < 4; e++) a1[mf][nf][e] = 0.f;
        #pragma unroll
        for (int k = 0; k < 8; k++) {
            uint32_t a[2][4], b[4][2];
            #pragma unroll
            for (int mf = 0; mf < 2; mf++)
                LDSM4(a[mf][0], a[mf][1], a[mf][2], a[mf][3],
                      Abase + mf * 16 * SA * 2 + k * 32);
            #pragma unroll
            for (int nf2 = 0; nf2 < 2; nf2++) {
                uint32_t r0, r1, r2, r3;
                LDSM4(r0, r1, r2, r3, B1base + nf2 * 16 * SA * 2 + k * 32);
                b[nf2 * 2][0] = r0; b[nf2 * 2][1] = r2;
                b[nf2 * 2 + 1][0] = r1; b[nf2 * 2 + 1][1] = r3;
            }
            #pragma unroll
            for (int mf = 0; mf < 2; mf++)
                #pragma unroll
                for (int nf = 0; nf < 4; nf++) MMA16816(a1[mf][nf], a[mf], b[nf]);
        }
        // gelu -> Cs
        #pragma unroll
        for (int mf = 0; mf < 2; mf++)
            #pragma unroll
            for (int nf = 0; nf < 4; nf++) {
                int nl = wn * 32 + nf * 8 + t4 * 2;
                int ng = nc * 128 + nl;
                int r0 = wm * 32 + mf * 16 + quad;
                #pragma unroll
                for (int hrow = 0; hrow < 2; hrow++) {
                    float v0 = a1[mf][nf][hrow * 2] + sb1[ng];
                    float v1 = a1[mf][nf][hrow * 2 + 1] + sb1[ng + 1];
                    float t0 = tanh_fast(0.7978845608028654f * (v0 + 0.044715f * v0 * v0 * v0));
                    float t1 = tanh_fast(0.7978845608028654f * (v1 + 0.044715f * v1 * v1 * v1));
                    *(bf162*)(Cs + (r0 + hrow * 8) * SA + nl) =
                        __floats2bfloat162_rn(0.5f * v0 * (1.f + t0), 0.5f * v1 * (1.f + t1));
                }
            }
        __syncthreads();      // Bs1 reads done + Cs written
        if (nc < 3) {
            #pragma unroll
            for (int j = 0; j < 8; j++) {
                int i = tid + 256 * j;
                int r = i >> 4, c = i & 15;
                CPASYNC16(b1s + (r * SA + c * 8) * 2, w1p + (nc + 1) * 2048 + i);
            }
            CPASYNC_COMMIT();
        }

        // --- gemm2: Cs @ W2c_nc (Bs0), accumulate ---
        if (nc < 3) CPASYNC_WAIT(1);
        else        CPASYNC_WAIT(0);
        __syncthreads();
        #pragma unroll
        for (int k = 0; k < 8; k++) {
            uint32_t a[2][4], b[4][2];
            #pragma unroll
            for (int mf = 0; mf < 2; mf++)
                LDSM4(a[mf][0], a[mf][1], a[mf][2], a[mf][3],
                      Cbase + mf * 16 * SA * 2 + k * 32);
            #pragma unroll
            for (int nf2 = 0; nf2 < 2; nf2++) {
                uint32_t r0, r1, r2, r3;
                LDSM4(r0, r1, r2, r3, B0base + nf2 * 16 * SA * 2 + k * 32);
                b[nf2 * 2][0] = r0; b[nf2 * 2][1] = r2;
                b[nf2 * 2 + 1][0] = r1; b[nf2 * 2 + 1][1] = r3;
            }
            #pragma unroll
            for (int mf = 0; mf < 2; mf++)
                #pragma unroll
                for (int nf = 0; nf < 4; nf++) MMA16816(acc2[mf][nf], a[mf], b[nf]);
        }
        __syncthreads();      // Bs0 + Cs reads done
        if (nc < 3) {
            #pragma unroll
            for (int j = 0; j < 8; j++) {
                int i = tid + 256 * j;
                int r = i >> 4, c = i & 15;
                CPASYNC16(b0s + (r * SA + c * 8) * 2, w2p + (size_t)r * 64 + (nc + 1) * 16 + c);
            }
            CPASYNC_COMMIT();
        }
    }

    // ---------------- epilogue: stage y*gamma, prefetch x, coalesced store ---
    float* stg = (float*)sm;     // reuse As+Cs region (64 x 132 fp32)
    #pragma unroll
    for (int mf = 0; mf < 2; mf++)
        #pragma unroll
        for (int nf = 0; nf < 4; nf++) {
            int n = wn * 32 + nf * 8 + t4 * 2;
            int r0 = wm * 32 + mf * 16 + quad;
            #pragma unroll
            for (int hrow = 0; hrow < 2; hrow++) {
                int r = r0 + hrow * 8;
                stg[r * 132 + n]     = (acc2[mf][nf][hrow * 2]     + sb2[n])     * sgm[n];
                stg[r * 132 + n + 1] = (acc2[mf][nf][hrow * 2 + 1] + sb2[n + 1]) * sgm[n + 1];
            }
        }
    // prefetch residual x while staging drains (acc2 dead -> regs free)
    const float4* x4 = (const float4*)(x + m0 * 128);
    float4 xv[8];
    #pragma unroll
    for (int j = 0; j < 8; j++) xv[j] = x4[tid + 256 * j];
    __syncthreads();
    float4* o4 = (float4*)(out + m0 * 128);
    #pragma unroll
    for (int j = 0; j < 8; j++) {
        int i = tid + 256 * j;
        int r = i >> 5, c = i & 31;
        float4 ov;
        ov.x = stg[r * 132 + c * 4 + 0] + xv[j].x;
        ov.y = stg[r * 132 + c * 4 + 1] + xv[j].y;
        ov.z = stg[r * 132 + c * 4 + 2] + xv[j].z;
        ov.w = stg[r * 132 + c * 4 + 3] + xv[j].w;
        o4[i] = ov;
    }
}

// ---------------------------------------------------------------------------
extern "C" void kernel_launch(void* const* d_in, const int* in_sizes, int n_in,
                              void* d_out, int out_size) {
    const float* x     = (const float*)d_in[0];
    const float* Wg    = (const float*)d_in[1];
    const float* bg    = (const float*)d_in[2];
    const float* Wh    = (const float*)d_in[3];
    const float* bh    = (const float*)d_in[4];
    const float* gk    = (const float*)d_in[5];
    const float* hk    = (const float*)d_in[6];
    const float* Wo    = (const float*)d_in[7];
    const float* bo    = (const float*)d_in[8];
    const float* lns   = (const float*)d_in[9];
    const float* lnb   = (const float*)d_in[10];
    const float* W1    = (const float*)d_in[11];
    const float* b1    = (const float*)d_in[12];
    const float* W2    = (const float*)d_in[13];
    const float* b2    = (const float*)d_in[14];
    const float* gamma = (const float*)d_in[15];
    float* out = (float*)d_out;

    cudaFuncSetAttribute(k_proj,  cudaFuncAttributeMaxDynamicSharedMemorySize, PROJ_SMEM);
    cudaFuncSetAttribute(k_womlp, cudaFuncAttributeMaxDynamicSharedMemorySize, WM_SMEM);

    k_prep<<<256, 256>>>(Wg, Wh, Wo, W1, W2, gk, hk);
    k_proj<<<NTILES, 256, PROJ_SMEM>>>(x, bg, bh);
    k_conv<<<dim3(4, Bb * Hh, 2), 256>>>();
    k_scan<<<(Bb * Hh * Ww * 32) / 256, 256>>>();
    k_womlp<<<NPTS / 64, 256, WM_SMEM>>>(x, bo, lns, lnb, b1, b2, gamma, out);
}

// round 16
// speedup vs baseline: 1.1101x; 1.0393x over previous
#include <cuda_runtime.h>
#include <cuda_bf16.h>
#include <math.h>
#include <stdint.h>

#define Bb 2
#define Tt 16
#define Hh 56
#define Ww 56
#define Cc 128
#define NPTS (Bb*Tt*Hh*Ww)          /* 100352 */
#define TOT  (NPTS*Cc)              /* 12845056 */
#define HWC  (Hh*Ww*Cc)
#define KTAPS 245
#define NTILES (NPTS/128)           /* 784 */

typedef __nv_bfloat16 bf16;
typedef __nv_bfloat162 bf162;

// ---------------- device scratch (allocation-free) ----------------
__device__ __align__(16) bf16 g_gateP[TOT];
__device__ __align__(16) bf16 g_hidP[TOT];
__device__ __align__(16) bf16 g_E[TOT];
__device__ __align__(16) bf16 g_WgT[Cc*Cc];       // [n][k]
__device__ __align__(16) bf16 g_WhT[Cc*Cc];
__device__ __align__(16) bf16 g_WoT[Cc*Cc];
__device__ __align__(16) bf16 g_W1T[512*Cc];      // [n=512][k=128]
__device__ __align__(16) bf16 g_W2T[Cc*512];      // [n=128][k=512]
__device__ __align__(16) bf16 g_kB[2][KTAPS*Cc];  // [tap][c]

// ---------------- helpers ----------------
__device__ __forceinline__ uint32_t smem_u32(const void* p) {
    uint32_t a;
    asm("{ .reg .u64 t; cvta.to.shared.u64 t, %1; cvt.u32.u64 %0, t; }" : "=r"(a) : "l"(p));
    return a;
}
#define LDSM4(r0, r1, r2, r3, a) \
    asm volatile("ldmatrix.sync.aligned.m8n8.x4.shared.b16 {%0,%1,%2,%3}, [%4];" \
        : "=r"(r0), "=r"(r1), "=r"(r2), "=r"(r3) : "r"(a))
#define MMA16816(c, a, b) \
    asm volatile("mma.sync.aligned.m16n8k16.row.col.f32.bf16.bf16.f32 " \
        "{%0,%1,%2,%3},{%4,%5,%6,%7},{%8,%9},{%0,%1,%2,%3};" \
        : "+f"((c)[0]), "+f"((c)[1]), "+f"((c)[2]), "+f"((c)[3]) \
        : "r"((a)[0]), "r"((a)[1]), "r"((a)[2]), "r"((a)[3]), "r"((b)[0]), "r"((b)[1]))
#define CPASYNC16(sma, gp) \
    asm volatile("cp.async.cg.shared.global [%0], [%1], 16;" :: "r"(sma), "l"(gp) : "memory")
#define CPASYNC_COMMIT() asm volatile("cp.async.commit_group;" ::: "memory")
#define CPASYNC_WAIT(n)  asm volatile("cp.async.wait_group %0;" :: "n"(n) : "memory")

__device__ __forceinline__ float tanh_fast(float x) {
    float y;
    asm("tanh.approx.f32 %0, %1;" : "=f"(y) : "f"(x));
    return y;
}
__device__ __forceinline__ float exp_fast(float x) {
    float y;
    asm("ex2.approx.f32 %0, %1;" : "=f"(y) : "f"(x * 1.4426950408889634f));
    return y;
}
__device__ __forceinline__ float rcp_fast(float x) {
    float y;
    asm("rcp.approx.f32 %0, %1;" : "=f"(y) : "f"(x));
    return y;
}

#define SA 136    /* smem row stride (bf16 elems) for 128-col tiles */

// ---------------------------------------------------------------------------
// K0: weight prep
// ---------------------------------------------------------------------------
__global__ void k_prep(const float* __restrict__ Wg, const float* __restrict__ Wh,
                       const float* __restrict__ Wo, const float* __restrict__ W1,
                       const float* __restrict__ W2, const float* __restrict__ gk,
                       const float* __restrict__ hk) {
    int i = blockIdx.x * 256 + threadIdx.x;
    if (i < 16384) {
        int n = i >> 7, k = i & 127;
        g_WgT[i] = __float2bfloat16(Wg[k * 128 + n]);
        g_WhT[i] = __float2bfloat16(Wh[k * 128 + n]);
        g_WoT[i] = __float2bfloat16(Wo[k * 128 + n]);
    }
    if (i < 65536) {
        int n = i >> 7, k = i & 127;
        g_W1T[i] = __float2bfloat16(W1[k * 512 + n]);
        int n2 = i >> 9, k2 = i & 511;
        g_W2T[i] = __float2bfloat16(W2[k2 * 128 + n2]);
    }
    if (i < 2 * KTAPS * 128) {
        int which = i / (KTAPS * 128);
        int j = i - which * (KTAPS * 128);
        int tap = j >> 7, c = j & 127;
        const float* s = which ? hk : gk;
        g_kB[which][j] = __float2bfloat16(s[c * KTAPS + tap]);
    }
}

// ---------------------------------------------------------------------------
// K1: dual projection, 256 threads; Wg/Wh via cp.async
// ---------------------------------------------------------------------------
#define PROJ_SMEM (3*128*SA*2 + 256*4)
__global__ void __launch_bounds__(256) k_proj(const float* __restrict__ x,
                                              const float* __restrict__ bg,
                                              const float* __restrict__ bh) {
    extern __shared__ __align__(16) char sm[];
    bf16* As = (bf16*)sm;
    bf16* Bs = As + 128 * SA;
    float* sbias = (float*)(Bs + 2 * 128 * SA);
    int tid = threadIdx.x, w = tid >> 5, l = tid & 31;
    size_t m0 = (size_t)blockIdx.x * 128;

    {
        uint32_t bs = smem_u32(Bs);
        const uint4* wgp = (const uint4*)g_WgT;
        const uint4* whp = (const uint4*)g_WhT;
        #pragma unroll
        for (int j = 0; j < 8; j++) {
            int i = tid + 256 * j;
            int r = i >> 4, c = i & 15;
            CPASYNC16(bs + (r * SA + c * 8) * 2, wgp + i);
            CPASYNC16(bs + (128 * SA + r * SA + c * 8) * 2, whp + i);
        }
        CPASYNC_COMMIT();
    }

    if (tid < 128) sbias[tid] = bg[tid];
    else           sbias[tid] = bh[tid - 128];

    const float2* xs = (const float2*)(x + m0 * 128);
    for (int idx = tid; idx < 128 * 64; idx += 256) {
        int r = idx >> 6, cp = idx & 63;
        float2 v = xs[idx];
        *(bf162*)(As + r * SA + cp * 2) = __floats2bfloat162_rn(v.x, v.y);
    }
    CPASYNC_WAIT(0);
    __syncthreads();

    int which = w >> 2;
    int wn0 = (w & 3) * 32;
    uint32_t Abase = smem_u32(As) + ((l & 15) * SA + (l >> 4) * 8) * 2;
    uint32_t Bbase = smem_u32(Bs + which * 128 * SA) + ((l & 15) * SA + (l >> 4) * 8) * 2 + wn0 * SA * 2;
    bf16* outb = which ? g_hidP : g_gateP;
    float* bb = sbias + which * 128;
    int quad = l >> 2, t4 = l & 3;

    for (int mc = 0; mc < 4; mc++) {
        float acc[2][4][4];
        #pragma unroll
        for (int mf = 0; mf < 2; mf++)
            #pragma unroll
            for (int nf = 0; nf < 4; nf++)
                #pragma unroll
                for (int e = 0; e < 4; e++) acc[mf][nf][e] = 0.f;
        #pragma unroll
        for (int k = 0; k < 8; k++) {
            uint32_t a[2][4], b[4][2];
            #pragma unroll
            for (int mf = 0; mf < 2; mf++)
                LDSM4(a[mf][0], a[mf][1], a[mf][2], a[mf][3],
                      Abase + (mc * 32 + mf * 16) * SA * 2 + k * 32);
            #pragma unroll
            for (int nf2 = 0; nf2 < 2; nf2++) {
                uint32_t r0, r1, r2, r3;
                LDSM4(r0, r1, r2, r3, Bbase + nf2 * 16 * SA * 2 + k * 32);
                b[nf2 * 2][0] = r0; b[nf2 * 2][1] = r2;
                b[nf2 * 2 + 1][0] = r1; b[nf2 * 2 + 1][1] = r3;
            }
            #pragma unroll
            for (int mf = 0; mf < 2; mf++)
                #pragma unroll
                for (int nf = 0; nf < 4; nf++) MMA16816(acc[mf][nf], a[mf], b[nf]);
        }
        #pragma unroll
        for (int mf = 0; mf < 2; mf++)
            #pragma unroll
            for (int nf = 0; nf < 4; nf++) {
                int n = wn0 + nf * 8 + t4 * 2;
                int r0 = mc * 32 + mf * 16 + quad;
                *(bf162*)(outb + (m0 + r0) * 128 + n) =
                    __floats2bfloat162_rn(acc[mf][nf][0] + bb[n], acc[mf][nf][1] + bb[n + 1]);
                *(bf162*)(outb + (m0 + r0 + 8) * 128 + n) =
                    __floats2bfloat162_rn(acc[mf][nf][2] + bb[n], acc[mf][nf][3] + bb[n + 1]);
            }
    }
}

// ---------------------------------------------------------------------------
// K2: FUSED conv+scan v2, half-width (7w) tiles -> 57.3 KB smem, 2 CTAs/SM.
// Block: 256 threads = 64 cp x 4 tq; covers (b, h, 7-w slice), all 16 t,
// both tensors. Conv results staged in smem, in-block scan writes only g_E.
// ---------------------------------------------------------------------------
#define CS_SMEM (2 * 16 * 7 * 64 * 4)   /* 57344 B */
__global__ void __launch_bounds__(256, 2) k_convscan(void) {
    extern __shared__ uint32_t sgh[];
    uint32_t* sG = sgh;                 // [16t][7w][64cp]
    uint32_t* sH = sgh + 16 * 7 * 64;
    int ct = threadIdx.x & 63;
    int tq = threadIdx.x >> 6;
    int w0 = blockIdx.x * 7;
    int by = blockIdx.y;
    int h = by % Hh;
    int b = by / Hh;
    int t0 = tq * 4;

    int offs[13];
    #pragma unroll
    for (int j = 0; j < 13; j++) {
        int wi = w0 - 3 + j;
        if (wi < 0)   wi += 56;
        if (wi >= 56) wi -= 56;
        offs[j] = wi * 64;
    }

    #pragma unroll
    for (int which = 0; which < 2; which++) {
        const uint32_t* __restrict__ in = (const uint32_t*)(which ? g_hidP : g_gateP);
        const uint32_t* __restrict__ kt = (const uint32_t*)g_kB[which];
        uint32_t* stage = which ? sH : sG;

        bf162 acc[4][7];
        bf162 z = __floats2bfloat162_rn(0.f, 0.f);
        #pragma unroll
        for (int tr = 0; tr < 4; tr++)
            #pragma unroll
            for (int i = 0; i < 7; i++) acc[tr][i] = z;

        for (int kh = 0; kh < 7; kh++) {
            int hin = h - kh + 3;
            if (hin < 0)   hin += 56;
            if (hin >= 56) hin -= 56;
            uint32_t kv[5][7];
            #pragma unroll
            for (int ktp = 0; ktp < 5; ktp++)
                #pragma unroll
                for (int kw = 0; kw < 7; kw++)
                    kv[ktp][kw] = kt[(size_t)(ktp * 49 + kh * 7 + kw) * 64 + ct];

            #pragma unroll
            for (int j = 0; j < 8; j++) {
                int t_in = (t0 - 2 + j) & 15;
                const uint32_t* src = in + (size_t)((b * 16 + t_in) * Hh + hin) * (Ww * 64) + ct;
                uint32_t win[13];
                #pragma unroll
                for (int jj = 0; jj < 13; jj++) win[jj] = src[offs[jj]];
                #pragma unroll
                for (int ktp = 0; ktp < 5; ktp++) {
                    int tr = j + ktp - 4;
                    if (tr >= 0 && tr < 4) {
                        #pragma unroll
                        for (int i = 0; i < 7; i++) {
                            #pragma unroll
                            for (int kw = 0; kw < 7; kw++)
                                acc[tr][i] = __hfma2(*(bf162*)&kv[ktp][kw],
                                                     *(bf162*)&win[i + 6 - kw],
                                                     acc[tr][i]);
                        }
                    }
                }
            }
        }
        #pragma unroll
        for (int tr = 0; tr < 4; tr++)
            #pragma unroll
            for (int i = 0; i < 7; i++)
                stage[((t0 + tr) * 7 + i) * 64 + ct] = *(uint32_t*)&acc[tr][i];
    }
    __syncthreads();

    // ---- in-block scan over t (448 columns = 7 w x 64 cp) ----
    uint32_t* ep = (uint32_t*)g_E;
    for (int col = threadIdx.x; col < 448; col += 256) {
        int i = col >> 6;          // w offset 0..6
        int cp = col & 63;
        float H0 = 0.f, H1 = 0.f;
        size_t gout = ((size_t)(b * 16) * Hh + h) * Ww * 64 + (size_t)(w0 + i) * 64 + cp;
        #pragma unroll
        for (int t = 0; t < 16; t++) {
            uint32_t gu = sG[(t * 7 + i) * 64 + cp];
            uint32_t hu = sH[(t * 7 + i) * 64 + cp];
            float2 g2 = __bfloat1622float2(*(bf162*)&gu);
            float2 h2 = __bfloat1622float2(*(bf162*)&hu);
            float e0 = exp_fast(-fabsf(g2.x));
            float r0 = rcp_fast(1.f + e0);
            float s0 = (g2.x >= 0.f) ? r0 : e0 * r0;
            float f0 = (g2.x >= 0.f) ? e0 * r0 : r0;
            H0 = fmaf(f0, H0, (h2.x * h2.x + 1e-6f) * s0);
            float e1 = exp_fast(-fabsf(g2.y));
            float r1 = rcp_fast(1.f + e1);
            float s1 = (g2.y >= 0.f) ? r1 : e1 * r1;
            float f1 = (g2.y >= 0.f) ? e1 * r1 : r1;
            H1 = fmaf(f1, H1, (h2.y * h2.y + 1e-6f) * s1);
            bf162 o = __floats2bfloat162_rn(H0, H1);
            ep[gout + (size_t)t * (HWC / 2)] = *(uint32_t*)&o;
        }
    }
}

// ---------------------------------------------------------------------------
// K4: womlp-v5: cp.async for E tile + weights, x-prefetch epilogue.
// ---------------------------------------------------------------------------
#define WM_SMEM ((64*SA + 64*SA + 128*SA + 128*SA)*2 + 1792*4)
__global__ void __launch_bounds__(256, 2) k_womlp(const float* __restrict__ x,
                                                  const float* __restrict__ bo,
                                                  const float* __restrict__ lns,
                                                  const float* __restrict__ lnb,
                                                  const float* __restrict__ b1,
                                                  const float* __restrict__ b2,
                                                  const float* __restrict__ gamma,
                                                  float* __restrict__ out) {
    extern __shared__ __align__(16) char sm[];
    bf16* As  = (bf16*)sm;                   // 64 x SA : E tile -> xn tile
    bf16* Cs  = As + 64 * SA;                // 64 x SA : gelu hidden chunk
    bf16* Bs0 = Cs + 64 * SA;                // 128 x SA : Wo / W2 chunks
    bf16* Bs1 = Bs0 + 128 * SA;              // 128 x SA : W1 chunks
    float* sbo  = (float*)(Bs1 + 128 * SA);
    float* slns = sbo + 128;
    float* slnb = slns + 128;
    float* sb1  = slnb + 128;
    float* sb2  = sb1 + 512;
    float* sgm  = sb2 + 128;
    float* rs   = sgm + 128;
    float* rq   = rs + 256;
    float2* stat = (float2*)(rq + 256);

    int tid = threadIdx.x, w = tid >> 5, l = tid & 31;
    int wm = w >> 2, wn = w & 3;
    int quad = l >> 2, t4 = l & 3;
    size_t m0 = (size_t)blockIdx.x * 64;

    const uint4* w1p = (const uint4*)g_W1T;
    const uint4* w2p = (const uint4*)g_W2T;
    uint32_t b0s = smem_u32(Bs0), b1s = smem_u32(Bs1), as_ = smem_u32(As);

    // group A: E tile + Wo ; group B: W1c0
    {
        const uint4* ep = (const uint4*)(g_E + m0 * 128);
        #pragma unroll
        for (int j = 0; j < 4; j++) {
            int i = tid + 256 * j;
            int r = i >> 4, c = i & 15;
            CPASYNC16(as_ + (r * SA + c * 8) * 2, ep + i);
        }
        const uint4* wop = (const uint4*)g_WoT;
        #pragma unroll
        for (int j = 0; j < 8; j++) {
            int i = tid + 256 * j;
            int r = i >> 4, c = i & 15;
            CPASYNC16(b0s + (r * SA + c * 8) * 2, wop + i);
        }
        CPASYNC_COMMIT();
        #pragma unroll
        for (int j = 0; j < 8; j++) {
            int i = tid + 256 * j;
            int r = i >> 4, c = i & 15;
            CPASYNC16(b1s + (r * SA + c * 8) * 2, w1p + i);
        }
        CPASYNC_COMMIT();
    }

    if (tid < 128) {
        sbo[tid] = bo[tid]; slns[tid] = lns[tid]; slnb[tid] = lnb[tid];
        sb2[tid] = b2[tid]; sgm[tid] = gamma[tid];
    }
    sb1[tid] = b1[tid]; sb1[256 + tid] = b1[256 + tid];

    CPASYNC_WAIT(1);      // E + Wo arrived
    __syncthreads();

    uint32_t Abase  = as_ + ((l & 15) * SA + (l >> 4) * 8) * 2 + (wm * 32) * SA * 2;
    uint32_t Cbase  = smem_u32(Cs) + ((l & 15) * SA + (l >> 4) * 8) * 2 + (wm * 32) * SA * 2;
    uint32_t B0base = b0s + ((l & 15) * SA + (l >> 4) * 8) * 2 + (wn * 32) * SA * 2;
    uint32_t B1base = b1s + ((l & 15) * SA + (l >> 4) * 8) * 2 + (wn * 32) * SA * 2;

    // ---------------- stage 0: wo GEMM (Bs0) ----------------
    float acc[2][4][4];
    #pragma unroll
    for (int mf = 0; mf < 2; mf++)
        #pragma unroll
        for (int nf = 0; nf < 4; nf++)
            #pragma unroll
            for (int e = 0; e < 4; e++) acc[mf][nf][e] = 0.f;
    #pragma unroll
    for (int k = 0; k < 8; k++) {
        uint32_t a[2][4], b[4][2];
        #pragma unroll
        for (int mf = 0; mf < 2; mf++)
            LDSM4(a[mf][0], a[mf][1], a[mf][2], a[mf][3],
                  Abase + mf * 16 * SA * 2 + k * 32);
        #pragma unroll
        for (int nf2 = 0; nf2 < 2; nf2++) {
            uint32_t r0, r1, r2, r3;
            LDSM4(r0, r1, r2, r3, B0base + nf2 * 16 * SA * 2 + k * 32);
            b[nf2 * 2][0] = r0; b[nf2 * 2][1] = r2;
            b[nf2 * 2 + 1][0] = r1; b[nf2 * 2 + 1][1] = r3;
        }
        #pragma unroll
        for (int mf = 0; mf < 2; mf++)
            #pragma unroll
            for (int nf = 0; nf < 4; nf++) MMA16816(acc[mf][nf], a[mf], b[nf]);
    }

    // bias + per-row partial sums
    #pragma unroll
    for (int mf = 0; mf < 2; mf++) {
        float s0 = 0.f, q0 = 0.f, s1 = 0.f, q1 = 0.f;
        #pragma unroll
        for (int nf = 0; nf < 4; nf++) {
            int n = wn * 32 + nf * 8 + t4 * 2;
            float v0 = acc[mf][nf][0] + sbo[n];
            float v1 = acc[mf][nf][1] + sbo[n + 1];
            float v2 = acc[mf][nf][2] + sbo[n];
            float v3 = acc[mf][nf][3] + sbo[n + 1];
            acc[mf][nf][0] = v0; acc[mf][nf][1] = v1;
            acc[mf][nf][2] = v2; acc[mf][nf][3] = v3;
            s0 += v0 + v1; q0 += v0 * v0 + v1 * v1;
            s1 += v2 + v3; q1 += v2 * v2 + v3 * v3;
        }
        #pragma unroll
        for (int o = 1; o < 4; o <<= 1) {
            s0 += __shfl_xor_sync(0xffffffffu, s0, o);
            q0 += __shfl_xor_sync(0xffffffffu, q0, o);
            s1 += __shfl_xor_sync(0xffffffffu, s1, o);
            q1 += __shfl_xor_sync(0xffffffffu, q1, o);
        }
        if (t4 == 0) {
            int rA = wm * 32 + mf * 16 + quad;
            rs[rA * 4 + wn] = s0; rq[rA * 4 + wn] = q0;
            rs[(rA + 8) * 4 + wn] = s1; rq[(rA + 8) * 4 + wn] = q1;
        }
    }
    __syncthreads();

    // issue W2c0 -> Bs0 (group C)
    #pragma unroll
    for (int j = 0; j < 8; j++) {
        int i = tid + 256 * j;
        int r = i >> 4, c = i & 15;
        CPASYNC16(b0s + (r * SA + c * 8) * 2, w2p + (size_t)r * 64 + c);
    }
    CPASYNC_COMMIT();

    if (tid < 64) {
        float mean = (rs[tid * 4] + rs[tid * 4 + 1] + rs[tid * 4 + 2] + rs[tid * 4 + 3]) * (1.f / 128.f);
        float var = (rq[tid * 4] + rq[tid * 4 + 1] + rq[tid * 4 + 2] + rq[tid * 4 + 3]) * (1.f / 128.f) - mean * mean;
        stat[tid] = make_float2(mean, rsqrtf(var + 1e-6f));
    }
    __syncthreads();

    // write xn (bf16) into As
    #pragma unroll
    for (int mf = 0; mf < 2; mf++) {
        int rA = wm * 32 + mf * 16 + quad;
        float2 stA = stat[rA], stB = stat[rA + 8];
        #pragma unroll
        for (int nf = 0; nf < 4; nf++) {
            int n = wn * 32 + nf * 8 + t4 * 2;
            float x0 = (acc[mf][nf][0] - stA.x) * stA.y * slns[n] + slnb[n];
            float x1 = (acc[mf][nf][1] - stA.x) * stA.y * slns[n + 1] + slnb[n + 1];
            float x2 = (acc[mf][nf][2] - stB.x) * stB.y * slns[n] + slnb[n];
            float x3 = (acc[mf][nf][3] - stB.x) * stB.y * slns[n + 1] + slnb[n + 1];
            *(bf162*)(As + rA * SA + n) = __floats2bfloat162_rn(x0, x1);
            *(bf162*)(As + (rA + 8) * SA + n) = __floats2bfloat162_rn(x2, x3);
        }
    }
    __syncthreads();

    // ---------------- fused MLP: cp.async pipelined chunks ------------------
    float acc2[2][4][4];
    #pragma unroll
    for (int mf = 0; mf < 2; mf++)
        #pragma unroll
        for (int nf = 0; nf < 4; nf++)
            #pragma unroll
            for (int e = 0; e < 4; e++) acc2[mf][nf][e] = 0.f;

    for (int nc = 0; nc < 4; nc++) {
        CPASYNC_WAIT(1);
        __syncthreads();
        float a1[2][4][4];
        #pragma unroll
        for (int mf = 0; mf < 2; mf++)
            #pragma unroll
            for (int nf = 0; nf < 4; nf++)
                #pragma unroll
                for (int e = 0; e < 4; e++) a1[mf][nf][e] = 0.f;
        #pragma unroll
        for (int k = 0; k < 8; k++) {
            uint32_t a[2][4], b[4][2];
            #pragma unroll
            for (int mf = 0; mf < 2; mf++)
                LDSM4(a[mf][0], a[mf][1], a[mf][2], a[mf][3],
                      Abase + mf * 16 * SA * 2 + k * 32);
            #pragma unroll
            for (int nf2 = 0; nf2 < 2; nf2++) {
                uint32_t r0, r1, r2, r3;
                LDSM4(r0, r1, r2, r3, B1base + nf2 * 16 * SA * 2 + k * 32);
                b[nf2 * 2][0] = r0; b[nf2 * 2][1] = r2;
                b[nf2 * 2 + 1][0] = r1; b[nf2 * 2 + 1][1] = r3;
            }
            #pragma unroll
            for (int mf = 0; mf < 2; mf++)
                #pragma unroll
                for (int nf = 0; nf < 4; nf++) MMA16816(a1[mf][nf], a[mf], b[nf]);
        }
        // gelu -> Cs
        #pragma unroll
        for (int mf = 0; mf < 2; mf++)
            #pragma unroll
            for (int nf = 0; nf < 4; nf++) {
                int nl = wn * 32 + nf * 8 + t4 * 2;
                int ng = nc * 128 + nl;
                int r0 = wm * 32 + mf * 16 + quad;
                #pragma unroll
                for (int hrow = 0; hrow < 2; hrow++) {
                    float v0 = a1[mf][nf][hrow * 2] + sb1[ng];
                    float v1 = a1[mf][nf][hrow * 2 + 1] + sb1[ng + 1];
                    float t0 = tanh_fast(0.7978845608028654f * (v0 + 0.044715f * v0 * v0 * v0));
                    float t1 = tanh_fast(0.7978845608028654f * (v1 + 0.044715f * v1 * v1 * v1));
                    *(bf162*)(Cs + (r0 + hrow * 8) * SA + nl) =
                        __floats2bfloat162_rn(0.5f * v0 * (1.f + t0), 0.5f * v1 * (1.f + t1));
                }
            }
        __syncthreads();
        if (nc < 3) {
            #pragma unroll
            for (int j = 0; j < 8; j++) {
                int i = tid + 256 * j;
                int r = i >> 4, c = i & 15;
                CPASYNC16(b1s + (r * SA + c * 8) * 2, w1p + (nc + 1) * 2048 + i);
            }
            CPASYNC_COMMIT();
        }

        if (nc < 3) CPASYNC_WAIT(1);
        else        CPASYNC_WAIT(0);
        __syncthreads();
        #pragma unroll
        for (int k = 0; k < 8; k++) {
            uint32_t a[2][4], b[4][2];
            #pragma unroll
            for (int mf = 0; mf < 2; mf++)
                LDSM4(a[mf][0], a[mf][1], a[mf][2], a[mf][3],
                      Cbase + mf * 16 * SA * 2 + k * 32);
            #pragma unroll
            for (int nf2 = 0; nf2 < 2; nf2++) {
                uint32_t r0, r1, r2, r3;
                LDSM4(r0, r1, r2, r3, B0base + nf2 * 16 * SA * 2 + k * 32);
                b[nf2 * 2][0] = r0; b[nf2 * 2][1] = r2;
                b[nf2 * 2 + 1][0] = r1; b[nf2 * 2 + 1][1] = r3;
            }
            #pragma unroll
            for (int mf = 0; mf < 2; mf++)
                #pragma unroll
                for (int nf = 0; nf < 4; nf++) MMA16816(acc2[mf][nf], a[mf], b[nf]);
        }
        __syncthreads();
        if (nc < 3) {
            #pragma unroll
            for (int j = 0; j < 8; j++) {
                int i = tid + 256 * j;
                int r = i >> 4, c = i & 15;
                CPASYNC16(b0s + (r * SA + c * 8) * 2, w2p + (size_t)r * 64 + (nc + 1) * 16 + c);
            }
            CPASYNC_COMMIT();
        }
    }

    // ---------------- epilogue: stage y*gamma, prefetch x, coalesced store ---
    float* stg = (float*)sm;     // reuse As+Cs region (64 x 132 fp32)
    #pragma unroll
    for (int mf = 0; mf < 2; mf++)
        #pragma unroll
        for (int nf = 0; nf < 4; nf++) {
            int n = wn * 32 + nf * 8 + t4 * 2;
            int r0 = wm * 32 + mf * 16 + quad;
            #pragma unroll
            for (int hrow = 0; hrow < 2; hrow++) {
                int r = r0 + hrow * 8;
                stg[r * 132 + n]     = (acc2[mf][nf][hrow * 2]     + sb2[n])     * sgm[n];
                stg[r * 132 + n + 1] = (acc2[mf][nf][hrow * 2 + 1] + sb2[n + 1]) * sgm[n + 1];
            }
        }
    const float4* x4 = (const float4*)(x + m0 * 128);
    float4 xv[8];
    #pragma unroll
    for (int j = 0; j < 8; j++) xv[j] = x4[tid + 256 * j];
    __syncthreads();
    float4* o4 = (float4*)(out + m0 * 128);
    #pragma unroll
    for (int j = 0; j < 8; j++) {
        int i = tid + 256 * j;
        int r = i >> 5, c = i & 31;
        float4 ov;
        ov.x = stg[r * 132 + c * 4 + 0] + xv[j].x;
        ov.y = stg[r * 132 + c * 4 + 1] + xv[j].y;
        ov.z = stg[r * 132 + c * 4 + 2] + xv[j].z;
        ov.w = stg[r * 132 + c * 4 + 3] + xv[j].w;
        o4[i] = ov;
    }
}

// ---------------------------------------------------------------------------
extern "C" void kernel_launch(void* const* d_in, const int* in_sizes, int n_in,
                              void* d_out, int out_size) {
    const float* x     = (const float*)d_in[0];
    const float* Wg    = (const float*)d_in[1];
    const float* bg    = (const float*)d_in[2];
    const float* Wh    = (const float*)d_in[3];
    const float* bh    = (const float*)d_in[4];
    const float* gk    = (const float*)d_in[5];
    const float* hk    = (const float*)d_in[6];
    const float* Wo    = (const float*)d_in[7];
    const float* bo    = (const float*)d_in[8];
    const float* lns   = (const float*)d_in[9];
    const float* lnb   = (const float*)d_in[10];
    const float* W1    = (const float*)d_in[11];
    const float* b1    = (const float*)d_in[12];
    const float* W2    = (const float*)d_in[13];
    const float* b2    = (const float*)d_in[14];
    const float* gamma = (const float*)d_in[15];
    float* out = (float*)d_out;

    cudaFuncSetAttribute(k_proj,     cudaFuncAttributeMaxDynamicSharedMemorySize, PROJ_SMEM);
    cudaFuncSetAttribute(k_convscan, cudaFuncAttributeMaxDynamicSharedMemorySize, CS_SMEM);
    cudaFuncSetAttribute(k_womlp,    cudaFuncAttributeMaxDynamicSharedMemorySize, WM_SMEM);

    k_prep<<<256, 256>>>(Wg, Wh, Wo, W1, W2, gk, hk);
    k_proj<<<NTILES, 256, PROJ_SMEM>>>(x, bg, bh);
    k_convscan<<<dim3(8, Bb * Hh), 256, CS_SMEM>>>();
    k_womlp<<<NPTS / 64, 256, WM_SMEM>>>(x, bo, lns, lnb, b1, b2, gamma, out);
}

// round 17
// speedup vs baseline: 1.1214x; 1.0102x over previous
#include <cuda_runtime.h>
#include <cuda_bf16.h>
#include <math.h>
#include <stdint.h>

#define Bb 2
#define Tt 16
#define Hh 56
#define Ww 56
#define Cc 128
#define NPTS (Bb*Tt*Hh*Ww)          /* 100352 */
#define TOT  (NPTS*Cc)              /* 12845056 */
#define HWC  (Hh*Ww*Cc)
#define KTAPS 245
#define NTILES (NPTS/128)           /* 784 */

typedef __nv_bfloat16 bf16;
typedef __nv_bfloat162 bf162;

// ---------------- device scratch (allocation-free) ----------------
__device__ __align__(16) bf16 g_gateP[TOT];
__device__ __align__(16) bf16 g_hidP[TOT];
__device__ __align__(16) bf16 g_E[TOT];
__device__ __align__(16) bf16 g_WgT[Cc*Cc];       // [n][k]
__device__ __align__(16) bf16 g_WhT[Cc*Cc];
__device__ __align__(16) bf16 g_WoT[Cc*Cc];
__device__ __align__(16) bf16 g_W1T[512*Cc];      // [n=512][k=128]
__device__ __align__(16) bf16 g_W2T[Cc*512];      // [n=128][k=512]
__device__ __align__(16) bf16 g_kB[2][KTAPS*Cc];  // [tap][c]

// ---------------- helpers ----------------
__device__ __forceinline__ uint32_t smem_u32(const void* p) {
    uint32_t a;
    asm("{ .reg .u64 t; cvta.to.shared.u64 t, %1; cvt.u32.u64 %0, t; }" : "=r"(a) : "l"(p));
    return a;
}
#define LDSM4(r0, r1, r2, r3, a) \
    asm volatile("ldmatrix.sync.aligned.m8n8.x4.shared.b16 {%0,%1,%2,%3}, [%4];" \
        : "=r"(r0), "=r"(r1), "=r"(r2), "=r"(r3) : "r"(a))
#define MMA16816(c, a, b) \
    asm volatile("mma.sync.aligned.m16n8k16.row.col.f32.bf16.bf16.f32 " \
        "{%0,%1,%2,%3},{%4,%5,%6,%7},{%8,%9},{%0,%1,%2,%3};" \
        : "+f"((c)[0]), "+f"((c)[1]), "+f"((c)[2]), "+f"((c)[3]) \
        : "r"((a)[0]), "r"((a)[1]), "r"((a)[2]), "r"((a)[3]), "r"((b)[0]), "r"((b)[1]))
#define CPASYNC16(sma, gp) \
    asm volatile("cp.async.cg.shared.global [%0], [%1], 16;" :: "r"(sma), "l"(gp) : "memory")
#define CPASYNC_COMMIT() asm volatile("cp.async.commit_group;" ::: "memory")
#define CPASYNC_WAIT(n)  asm volatile("cp.async.wait_group %0;" :: "n"(n) : "memory")

__device__ __forceinline__ float tanh_fast(float x) {
    float y;
    asm("tanh.approx.f32 %0, %1;" : "=f"(y) : "f"(x));
    return y;
}
__device__ __forceinline__ float exp_fast(float x) {
    float y;
    asm("ex2.approx.f32 %0, %1;" : "=f"(y) : "f"(x * 1.4426950408889634f));
    return y;
}
__device__ __forceinline__ float rcp_fast(float x) {
    float y;
    asm("rcp.approx.f32 %0, %1;" : "=f"(y) : "f"(x));
    return y;
}

#define SA 136    /* smem row stride (bf16 elems) for 128-col tiles */

// ---------------------------------------------------------------------------
// K0: weight prep
// ---------------------------------------------------------------------------
__global__ void k_prep(const float* __restrict__ Wg, const float* __restrict__ Wh,
                       const float* __restrict__ Wo, const float* __restrict__ W1,
                       const float* __restrict__ W2, const float* __restrict__ gk,
                       const float* __restrict__ hk) {
    int i = blockIdx.x * 256 + threadIdx.x;
    if (i < 16384) {
        int n = i >> 7, k = i & 127;
        g_WgT[i] = __float2bfloat16(Wg[k * 128 + n]);
        g_WhT[i] = __float2bfloat16(Wh[k * 128 + n]);
        g_WoT[i] = __float2bfloat16(Wo[k * 128 + n]);
    }
    if (i < 65536) {
        int n = i >> 7, k = i & 127;
        g_W1T[i] = __float2bfloat16(W1[k * 512 + n]);
        int n2 = i >> 9, k2 = i & 511;
        g_W2T[i] = __float2bfloat16(W2[k2 * 128 + n2]);
    }
    if (i < 2 * KTAPS * 128) {
        int which = i / (KTAPS * 128);
        int j = i - which * (KTAPS * 128);
        int tap = j >> 7, c = j & 127;
        const float* s = which ? hk : gk;
        g_kB[which][j] = __float2bfloat16(s[c * KTAPS + tap]);
    }
}

// ---------------------------------------------------------------------------
// K1: dual projection, 256 threads; Wg/Wh via cp.async
// ---------------------------------------------------------------------------
#define PROJ_SMEM (3*128*SA*2 + 256*4)
__global__ void __launch_bounds__(256, 2) k_proj(const float* __restrict__ x,
                                                 const float* __restrict__ bg,
                                                 const float* __restrict__ bh) {
    extern __shared__ __align__(16) char sm[];
    bf16* As = (bf16*)sm;
    bf16* Bs = As + 128 * SA;
    float* sbias = (float*)(Bs + 2 * 128 * SA);
    int tid = threadIdx.x, w = tid >> 5, l = tid & 31;
    size_t m0 = (size_t)blockIdx.x * 128;

    {
        uint32_t bs = smem_u32(Bs);
        const uint4* wgp = (const uint4*)g_WgT;
        const uint4* whp = (const uint4*)g_WhT;
        #pragma unroll
        for (int j = 0; j < 8; j++) {
            int i = tid + 256 * j;
            int r = i >> 4, c = i & 15;
            CPASYNC16(bs + (r * SA + c * 8) * 2, wgp + i);
            CPASYNC16(bs + (128 * SA + r * SA + c * 8) * 2, whp + i);
        }
        CPASYNC_COMMIT();
    }

    if (tid < 128) sbias[tid] = bg[tid];
    else           sbias[tid] = bh[tid - 128];

    const float2* xs = (const float2*)(x + m0 * 128);
    for (int idx = tid; idx < 128 * 64; idx += 256) {
        int r = idx >> 6, cp = idx & 63;
        float2 v = xs[idx];
        *(bf162*)(As + r * SA + cp * 2) = __floats2bfloat162_rn(v.x, v.y);
    }
    CPASYNC_WAIT(0);
    __syncthreads();

    int which = w >> 2;
    int wn0 = (w & 3) * 32;
    uint32_t Abase = smem_u32(As) + ((l & 15) * SA + (l >> 4) * 8) * 2;
    uint32_t Bbase = smem_u32(Bs + which * 128 * SA) + ((l & 15) * SA + (l >> 4) * 8) * 2 + wn0 * SA * 2;
    bf16* outb = which ? g_hidP : g_gateP;
    float* bb = sbias + which * 128;
    int quad = l >> 2, t4 = l & 3;

    for (int mc = 0; mc < 4; mc++) {
        float acc[2][4][4];
        #pragma unroll
        for (int mf = 0; mf < 2; mf++)
            #pragma unroll
            for (int nf = 0; nf < 4; nf++)
                #pragma unroll
                for (int e = 0; e < 4; e++) acc[mf][nf][e] = 0.f;
        #pragma unroll
        for (int k = 0; k < 8; k++) {
            uint32_t a[2][4], b[4][2];
            #pragma unroll
            for (int mf = 0; mf < 2; mf++)
                LDSM4(a[mf][0], a[mf][1], a[mf][2], a[mf][3],
                      Abase + (mc * 32 + mf * 16) * SA * 2 + k * 32);
            #pragma unroll
            for (int nf2 = 0; nf2 < 2; nf2++) {
                uint32_t r0, r1, r2, r3;
                LDSM4(r0, r1, r2, r3, Bbase + nf2 * 16 * SA * 2 + k * 32);
                b[nf2 * 2][0] = r0; b[nf2 * 2][1] = r2;
                b[nf2 * 2 + 1][0] = r1; b[nf2 * 2 + 1][1] = r3;
            }
            #pragma unroll
            for (int mf = 0; mf < 2; mf++)
                #pragma unroll
                for (int nf = 0; nf < 4; nf++) MMA16816(acc[mf][nf], a[mf], b[nf]);
        }
        #pragma unroll
        for (int mf = 0; mf < 2; mf++)
            #pragma unroll
            for (int nf = 0; nf < 4; nf++) {
                int n = wn0 + nf * 8 + t4 * 2;
                int r0 = mc * 32 + mf * 16 + quad;
                *(bf162*)(outb + (m0 + r0) * 128 + n) =
                    __floats2bfloat162_rn(acc[mf][nf][0] + bb[n], acc[mf][nf][1] + bb[n + 1]);
                *(bf162*)(outb + (m0 + r0 + 8) * 128 + n) =
                    __floats2bfloat162_rn(acc[mf][nf][2] + bb[n], acc[mf][nf][3] + bb[n + 1]);
            }
    }
}

// ---------------------------------------------------------------------------
// K2: FUSED conv+scan v3: 512 threads, both tensors computed IN PARALLEL
// (which = tid>>8), halving block duration (~58us -> ~29us) to shrink the
// 8-block tail wave. smem unchanged (57.3 KB), 1 CTA/SM = 16 warps.
// ---------------------------------------------------------------------------
#define CS_SMEM (2 * 16 * 7 * 64 * 4)   /* 57344 B */
__global__ void __launch_bounds__(512, 1) k_convscan(void) {
    extern __shared__ uint32_t sgh[];
    uint32_t* sG = sgh;                 // [16t][7w][64cp]
    uint32_t* sH = sgh + 16 * 7 * 64;
    int ct = threadIdx.x & 63;
    int tq = (threadIdx.x >> 6) & 3;
    int which = threadIdx.x >> 8;       // 0: gate, 1: hidden
    int w0 = blockIdx.x * 7;
    int by = blockIdx.y;
    int h = by % Hh;
    int b = by / Hh;
    int t0 = tq * 4;

    int offs[13];
    #pragma unroll
    for (int j = 0; j < 13; j++) {
        int wi = w0 - 3 + j;
        if (wi < 0)   wi += 56;
        if (wi >= 56) wi -= 56;
        offs[j] = wi * 64;
    }

    {
        const uint32_t* __restrict__ in = (const uint32_t*)(which ? g_hidP : g_gateP);
        const uint32_t* __restrict__ kt = (const uint32_t*)g_kB[which];
        uint32_t* stage = which ? sH : sG;

        bf162 acc[4][7];
        bf162 z = __floats2bfloat162_rn(0.f, 0.f);
        #pragma unroll
        for (int tr = 0; tr < 4; tr++)
            #pragma unroll
            for (int i = 0; i < 7; i++) acc[tr][i] = z;

        for (int kh = 0; kh < 7; kh++) {
            int hin = h - kh + 3;
            if (hin < 0)   hin += 56;
            if (hin >= 56) hin -= 56;
            uint32_t kv[5][7];
            #pragma unroll
            for (int ktp = 0; ktp < 5; ktp++)
                #pragma unroll
                for (int kw = 0; kw < 7; kw++)
                    kv[ktp][kw] = kt[(size_t)(ktp * 49 + kh * 7 + kw) * 64 + ct];

            #pragma unroll
            for (int j = 0; j < 8; j++) {
                int t_in = (t0 - 2 + j) & 15;
                const uint32_t* src = in + (size_t)((b * 16 + t_in) * Hh + hin) * (Ww * 64) + ct;
                uint32_t win[13];
                #pragma unroll
                for (int jj = 0; jj < 13; jj++) win[jj] = src[offs[jj]];
                #pragma unroll
                for (int ktp = 0; ktp < 5; ktp++) {
                    int tr = j + ktp - 4;
                    if (tr >= 0 && tr < 4) {
                        #pragma unroll
                        for (int i = 0; i < 7; i++) {
                            #pragma unroll
                            for (int kw = 0; kw < 7; kw++)
                                acc[tr][i] = __hfma2(*(bf162*)&kv[ktp][kw],
                                                     *(bf162*)&win[i + 6 - kw],
                                                     acc[tr][i]);
                        }
                    }
                }
            }
        }
        #pragma unroll
        for (int tr = 0; tr < 4; tr++)
            #pragma unroll
            for (int i = 0; i < 7; i++)
                stage[((t0 + tr) * 7 + i) * 64 + ct] = *(uint32_t*)&acc[tr][i];
    }
    __syncthreads();

    // ---- in-block scan over t (448 columns, single pass over 512 threads) ----
    int col = threadIdx.x;
    if (col < 448) {
        int i = col >> 6;          // w offset 0..6
        int cp = col & 63;
        uint32_t* ep = (uint32_t*)g_E;
        float H0 = 0.f, H1 = 0.f;
        size_t gout = ((size_t)(b * 16) * Hh + h) * Ww * 64 + (size_t)(w0 + i) * 64 + cp;
        #pragma unroll
        for (int t = 0; t < 16; t++) {
            uint32_t gu = sG[(t * 7 + i) * 64 + cp];
            uint32_t hu = sH[(t * 7 + i) * 64 + cp];
            float2 g2 = __bfloat1622float2(*(bf162*)&gu);
            float2 h2 = __bfloat1622float2(*(bf162*)&hu);
            float e0 = exp_fast(-fabsf(g2.x));
            float r0 = rcp_fast(1.f + e0);
            float s0 = (g2.x >= 0.f) ? r0 : e0 * r0;
            float f0 = (g2.x >= 0.f) ? e0 * r0 : r0;
            H0 = fmaf(f0, H0, (h2.x * h2.x + 1e-6f) * s0);
            float e1 = exp_fast(-fabsf(g2.y));
            float r1 = rcp_fast(1.f + e1);
            float s1 = (g2.y >= 0.f) ? r1 : e1 * r1;
            float f1 = (g2.y >= 0.f) ? e1 * r1 : r1;
            H1 = fmaf(f1, H1, (h2.y * h2.y + 1e-6f) * s1);
            bf162 o = __floats2bfloat162_rn(H0, H1);
            ep[gout + (size_t)t * (HWC / 2)] = *(uint32_t*)&o;
        }
    }
}

// ---------------------------------------------------------------------------
// K4: womlp-v5: cp.async for E tile + weights, x-prefetch epilogue.
// ---------------------------------------------------------------------------
#define WM_SMEM ((64*SA + 64*SA + 128*SA + 128*SA)*2 + 1792*4)
__global__ void __launch_bounds__(256, 2) k_womlp(const float* __restrict__ x,
                                                  const float* __restrict__ bo,
                                                  const float* __restrict__ lns,
                                                  const float* __restrict__ lnb,
                                                  const float* __restrict__ b1,
                                                  const float* __restrict__ b2,
                                                  const float* __restrict__ gamma,
                                                  float* __restrict__ out) {
    extern __shared__ __align__(16) char sm[];
    bf16* As  = (bf16*)sm;                   // 64 x SA : E tile -> xn tile
    bf16* Cs  = As + 64 * SA;                // 64 x SA : gelu hidden chunk
    bf16* Bs0 = Cs + 64 * SA;                // 128 x SA : Wo / W2 chunks
    bf16* Bs1 = Bs0 + 128 * SA;              // 128 x SA : W1 chunks
    float* sbo  = (float*)(Bs1 + 128 * SA);
    float* slns = sbo + 128;
    float* slnb = slns + 128;
    float* sb1  = slnb + 128;
    float* sb2  = sb1 + 512;
    float* sgm  = sb2 + 128;
    float* rs   = sgm + 128;
    float* rq   = rs + 256;
    float2* stat = (float2*)(rq + 256);

    int tid = threadIdx.x, w = tid >> 5, l = tid & 31;
    int wm = w >> 2, wn = w & 3;
    int quad = l >> 2, t4 = l & 3;
    size_t m0 = (size_t)blockIdx.x * 64;

    const uint4* w1p = (const uint4*)g_W1T;
    const uint4* w2p = (const uint4*)g_W2T;
    uint32_t b0s = smem_u32(Bs0), b1s = smem_u32(Bs1), as_ = smem_u32(As);

    // group A: E tile + Wo ; group B: W1c0
    {
        const uint4* ep = (const uint4*)(g_E + m0 * 128);
        #pragma unroll
        for (int j = 0; j < 4; j++) {
            int i = tid + 256 * j;
            int r = i >> 4, c = i & 15;
            CPASYNC16(as_ + (r * SA + c * 8) * 2, ep + i);
        }
        const uint4* wop = (const uint4*)g_WoT;
        #pragma unroll
        for (int j = 0; j < 8; j++) {
            int i = tid + 256 * j;
            int r = i >> 4, c = i & 15;
            CPASYNC16(b0s + (r * SA + c * 8) * 2, wop + i);
        }
        CPASYNC_COMMIT();
        #pragma unroll
        for (int j = 0; j < 8; j++) {
            int i = tid + 256 * j;
            int r = i >> 4, c = i & 15;
            CPASYNC16(b1s + (r * SA + c * 8) * 2, w1p + i);
        }
        CPASYNC_COMMIT();
    }

    if (tid < 128) {
        sbo[tid] = bo[tid]; slns[tid] = lns[tid]; slnb[tid] = lnb[tid];
        sb2[tid] = b2[tid]; sgm[tid] = gamma[tid];
    }
    sb1[tid] = b1[tid]; sb1[256 + tid] = b1[256 + tid];

    CPASYNC_WAIT(1);      // E + Wo arrived
    __syncthreads();

    uint32_t Abase  = as_ + ((l & 15) * SA + (l >> 4) * 8) * 2 + (wm * 32) * SA * 2;
    uint32_t Cbase  = smem_u32(Cs) + ((l & 15) * SA + (l >> 4) * 8) * 2 + (wm * 32) * SA * 2;
    uint32_t B0base = b0s + ((l & 15) * SA + (l >> 4) * 8) * 2 + (wn * 32) * SA * 2;
    uint32_t B1base = b1s + ((l & 15) * SA + (l >> 4) * 8) * 2 + (wn * 32) * SA * 2;

    // ---------------- stage 0: wo GEMM (Bs0) ----------------
    float acc[2][4][4];
    #pragma unroll
    for (int mf = 0; mf < 2; mf++)
        #pragma unroll
        for (int nf = 0; nf < 4; nf++)
            #pragma unroll
            for (int e = 0; e < 4; e++) acc[mf][nf][e] = 0.f;
    #pragma unroll
    for (int k = 0; k < 8; k++) {
        uint32_t a[2][4], b[4][2];
        #pragma unroll
        for (int mf = 0; mf < 2; mf++)
            LDSM4(a[mf][0], a[mf][1], a[mf][2], a[mf][3],
                  Abase + mf * 16 * SA * 2 + k * 32);
        #pragma unroll
        for (int nf2 = 0; nf2 < 2; nf2++) {
            uint32_t r0, r1, r2, r3;
            LDSM4(r0, r1, r2, r3, B0base + nf2 * 16 * SA * 2 + k * 32);
            b[nf2 * 2][0] = r0; b[nf2 * 2][1] = r2;
            b[nf2 * 2 + 1][0] = r1; b[nf2 * 2 + 1][1] = r3;
        }
        #pragma unroll
        for (int mf = 0; mf < 2; mf++)
            #pragma unroll
            for (int nf = 0; nf < 4; nf++) MMA16816(acc[mf][nf], a[mf], b[nf]);
    }

    // bias + per-row partial sums
    #pragma unroll
    for (int mf = 0; mf < 2; mf++) {
        float s0 = 0.f, q0 = 0.f, s1 = 0.f, q1 = 0.f;
        #pragma unroll
        for (int nf = 0; nf < 4; nf++) {
            int n = wn * 32 + nf * 8 + t4 * 2;
            float v0 = acc[mf][nf][0] + sbo[n];
            float v1 = acc[mf][nf][1] + sbo[n + 1];
            float v2 = acc[mf][nf][2] + sbo[n];
            float v3 = acc[mf][nf][3] + sbo[n + 1];
            acc[mf][nf][0] = v0; acc[mf][nf][1] = v1;
            acc[mf][nf][2] = v2; acc[mf][nf][3] = v3;
            s0 += v0 + v1; q0 += v0 * v0 + v1 * v1;
            s1 += v2 + v3; q1 += v2 * v2 + v3 * v3;
        }
        #pragma unroll
        for (int o = 1; o < 4; o <<= 1) {
            s0 += __shfl_xor_sync(0xffffffffu, s0, o);
            q0 += __shfl_xor_sync(0xffffffffu, q0, o);
            s1 += __shfl_xor_sync(0xffffffffu, s1, o);
            q1 += __shfl_xor_sync(0xffffffffu, q1, o);
        }
        if (t4 == 0) {
            int rA = wm * 32 + mf * 16 + quad;
            rs[rA * 4 + wn] = s0; rq[rA * 4 + wn] = q0;
            rs[(rA + 8) * 4 + wn] = s1; rq[(rA + 8) * 4 + wn] = q1;
        }
    }
    __syncthreads();

    // issue W2c0 -> Bs0 (group C)
    #pragma unroll
    for (int j = 0; j < 8; j++) {
        int i = tid + 256 * j;
        int r = i >> 4, c = i & 15;
        CPASYNC16(b0s + (r * SA + c * 8) * 2, w2p + (size_t)r * 64 + c);
    }
    CPASYNC_COMMIT();

    if (tid < 64) {
        float mean = (rs[tid * 4] + rs[tid * 4 + 1] + rs[tid * 4 + 2] + rs[tid * 4 + 3]) * (1.f / 128.f);
        float var = (rq[tid * 4] + rq[tid * 4 + 1] + rq[tid * 4 + 2] + rq[tid * 4 + 3]) * (1.f / 128.f) - mean * mean;
        stat[tid] = make_float2(mean, rsqrtf(var + 1e-6f));
    }
    __syncthreads();

    // write xn (bf16) into As
    #pragma unroll
    for (int mf = 0; mf < 2; mf++) {
        int rA = wm * 32 + mf * 16 + quad;
        float2 stA = stat[rA], stB = stat[rA + 8];
        #pragma unroll
        for (int nf = 0; nf < 4; nf++) {
            int n = wn * 32 + nf * 8 + t4 * 2;
            float x0 = (acc[mf][nf][0] - stA.x) * stA.y * slns[n] + slnb[n];
            float x1 = (acc[mf][nf][1] - stA.x) * stA.y * slns[n + 1] + slnb[n + 1];
            float x2 = (acc[mf][nf][2] - stB.x) * stB.y * slns[n] + slnb[n];
            float x3 = (acc[mf][nf][3] - stB.x) * stB.y * slns[n + 1] + slnb[n + 1];
            *(bf162*)(As + rA * SA + n) = __floats2bfloat162_rn(x0, x1);
            *(bf162*)(As + (rA + 8) * SA + n) = __floats2bfloat162_rn(x2, x3);
        }
    }
    __syncthreads();

    // ---------------- fused MLP: cp.async pipelined chunks ------------------
    float acc2[2][4][4];
    #pragma unroll
    for (int mf = 0; mf < 2; mf++)
        #pragma unroll
        for (int nf = 0; nf < 4; nf++)
            #pragma unroll
            for (int e = 0; e < 4; e++) acc2[mf][nf][e] = 0.f;

    for (int nc = 0; nc < 4; nc++) {
        CPASYNC_WAIT(1);
        __syncthreads();
        float a1[2][4][4];
        #pragma unroll
        for (int mf = 0; mf < 2; mf++)
            #pragma unroll
            for (int nf = 0; nf < 4; nf++)
                #pragma unroll
                for (int e = 0; e < 4; e++) a1[mf][nf][e] = 0.f;
        #pragma unroll
        for (int k = 0; k < 8; k++) {
            uint32_t a[2][4], b[4][2];
            #pragma unroll
            for (int mf = 0; mf < 2; mf++)
                LDSM4(a[mf][0], a[mf][1], a[mf][2], a[mf][3],
                      Abase + mf * 16 * SA * 2 + k * 32);
            #pragma unroll
            for (int nf2 = 0; nf2 < 2; nf2++) {
                uint32_t r0, r1, r2, r3;
                LDSM4(r0, r1, r2, r3, B1base + nf2 * 16 * SA * 2 + k * 32);
                b[nf2 * 2][0] = r0; b[nf2 * 2][1] = r2;
                b[nf2 * 2 + 1][0] = r1; b[nf2 * 2 + 1][1] = r3;
            }
            #pragma unroll
            for (int mf = 0; mf < 2; mf++)
                #pragma unroll
                for (int nf = 0; nf < 4; nf++) MMA16816(a1[mf][nf], a[mf], b[nf]);
        }
        // gelu -> Cs
        #pragma unroll
        for (int mf = 0; mf < 2; mf++)
            #pragma unroll
            for (int nf = 0; nf < 4; nf++) {
                int nl = wn * 32 + nf * 8 + t4 * 2;
                int ng = nc * 128 + nl;
                int r0 = wm * 32 + mf * 16 + quad;
                #pragma unroll
                for (int hrow = 0; hrow < 2; hrow++) {
                    float v0 = a1[mf][nf][hrow * 2] + sb1[ng];
                    float v1 = a1[mf][nf][hrow * 2 + 1] + sb1[ng + 1];
                    float t0 = tanh_fast(0.7978845608028654f * (v0 + 0.044715f * v0 * v0 * v0));
                    float t1 = tanh_fast(0.7978845608028654f * (v1 + 0.044715f * v1 * v1 * v1));
                    *(bf162*)(Cs + (r0 + hrow * 8) * SA + nl) =
                        __floats2bfloat162_rn(0.5f * v0 * (1.f + t0), 0.5f * v1 * (1.f + t1));
                }
            }
        __syncthreads();
        if (nc < 3) {
            #pragma unroll
            for (int j = 0; j < 8; j++) {
                int i = tid + 256 * j;
                int r = i >> 4, c = i & 15;
                CPASYNC16(b1s + (r * SA + c * 8) * 2, w1p + (nc + 1) * 2048 + i);
            }
            CPASYNC_COMMIT();
        }

        if (nc < 3) CPASYNC_WAIT(1);
        else        CPASYNC_WAIT(0);
        __syncthreads();
        #pragma unroll
        for (int k = 0; k < 8; k++) {
            uint32_t a[2][4], b[4][2];
            #pragma unroll
            for (int mf = 0; mf < 2; mf++)
                LDSM4(a[mf][0], a[mf][1], a[mf][2], a[mf][3],
                      Cbase + mf * 16 * SA * 2 + k * 32);
            #pragma unroll
            for (int nf2 = 0; nf2 < 2; nf2++) {
                uint32_t r0, r1, r2, r3;
                LDSM4(r0, r1, r2, r3, B0base + nf2 * 16 * SA * 2 + k * 32);
                b[nf2 * 2][0] = r0; b[nf2 * 2][1] = r2;
                b[nf2 * 2 + 1][0] = r1; b[nf2 * 2 + 1][1] = r3;
            }
            #pragma unroll
            for (int mf = 0; mf < 2; mf++)
                #pragma unroll
                for (int nf = 0; nf < 4; nf++) MMA16816(acc2[mf][nf], a[mf], b[nf]);
        }
        __syncthreads();
        if (nc < 3) {
            #pragma unroll
            for (int j = 0; j < 8; j++) {
                int i = tid + 256 * j;
                int r = i >> 4, c = i & 15;
                CPASYNC16(b0s + (r * SA + c * 8) * 2, w2p + (size_t)r * 64 + (nc + 1) * 16 + c);
            }
            CPASYNC_COMMIT();
        }
    }

    // ---------------- epilogue: stage y*gamma, prefetch x, coalesced store ---
    float* stg = (float*)sm;     // reuse As+Cs region (64 x 132 fp32)
    #pragma unroll
    for (int mf = 0; mf < 2; mf++)
        #pragma unroll
        for (int nf = 0; nf < 4; nf++) {
            int n = wn * 32 + nf * 8 + t4 * 2;
            int r0 = wm * 32 + mf * 16 + quad;
            #pragma unroll
            for (int hrow = 0; hrow < 2; hrow++) {
                int r = r0 + hrow * 8;
                stg[r * 132 + n]     = (acc2[mf][nf][hrow * 2]     + sb2[n])     * sgm[n];
                stg[r * 132 + n + 1] = (acc2[mf][nf][hrow * 2 + 1] + sb2[n + 1]) * sgm[n + 1];
            }
        }
    const float4* x4 = (const float4*)(x + m0 * 128);
    float4 xv[8];
    #pragma unroll
    for (int j = 0; j < 8; j++) xv[j] = x4[tid + 256 * j];
    __syncthreads();
    float4* o4 = (float4*)(out + m0 * 128);
    #pragma unroll
    for (int j = 0; j < 8; j++) {
        int i = tid + 256 * j;
        int r = i >> 5, c = i & 31;
        float4 ov;
        ov.x = stg[r * 132 + c * 4 + 0] + xv[j].x;
        ov.y = stg[r * 132 + c * 4 + 1] + xv[j].y;
        ov.z = stg[r * 132 + c * 4 + 2] + xv[j].z;
        ov.w = stg[r * 132 + c * 4 + 3] + xv[j].w;
        o4[i] = ov;
    }
}

// ---------------------------------------------------------------------------
extern "C" void kernel_launch(void* const* d_in, const int* in_sizes, int n_in,
                              void* d_out, int out_size) {
    const float* x     = (const float*)d_in[0];
    const float* Wg    = (const float*)d_in[1];
    const float* bg    = (const float*)d_in[2];
    const float* Wh    = (const float*)d_in[3];
    const float* bh    = (const float*)d_in[4];
    const float* gk    = (const float*)d_in[5];
    const float* hk    = (const float*)d_in[6];
    const float* Wo    = (const float*)d_in[7];
    const float* bo    = (const float*)d_in[8];
    const float* lns   = (const float*)d_in[9];
    const float* lnb   = (const float*)d_in[10];
    const float* W1    = (const float*)d_in[11];
    const float* b1    = (const float*)d_in[12];
    const float* W2    = (const float*)d_in[13];
    const float* b2    = (const float*)d_in[14];
    const float* gamma = (const float*)d_in[15];
    float* out = (float*)d_out;

    cudaFuncSetAttribute(k_proj,     cudaFuncAttributeMaxDynamicSharedMemorySize, PROJ_SMEM);
    cudaFuncSetAttribute(k_convscan, cudaFuncAttributeMaxDynamicSharedMemorySize, CS_SMEM);
    cudaFuncSetAttribute(k_womlp,    cudaFuncAttributeMaxDynamicSharedMemorySize, WM_SMEM);

    k_prep<<<256, 256>>>(Wg, Wh, Wo, W1, W2, gk, hk);
    k_proj<<<NTILES, 256, PROJ_SMEM>>>(x, bg, bh);
    k_convscan<<<dim3(8, Bb * Hh), 512, CS_SMEM>>>();
    k_womlp<<<NPTS / 64, 256, WM_SMEM>>>(x, bo, lns, lnb, b1, b2, gamma, out);
}